// round 1
// baseline (speedup 1.0000x reference)
#include <cuda_runtime.h>
#include <cuda_bf16.h>
#include <math.h>

// Problem constants
#define BATCH 8
#define S_LEN 1024
#define DMODEL 1024
#define NHEAD 16
#define DHEAD 64
#define MAXK 4
// B*S
#define MROWS (BATCH * S_LEN)   // 8192

// Scratch (allocation-free rule -> device globals)
__device__ float g_Q[(size_t)MROWS * DMODEL];
__device__ float g_K[(size_t)MROWS * DMODEL];
__device__ float g_V[(size_t)MROWS * DMODEL];
__device__ float g_O[(size_t)MROWS * DMODEL];

// ---------------------------------------------------------------------------
// GEMM: C = alpha * (A @ W^T + bias)
// A: (M,K) row-major, W: (N,K) row-major, C: (M,N) row-major
// BM=BN=128, BK=16, 256 threads, 8x8 microtile
// ---------------------------------------------------------------------------
#define GBM 128
#define GBN 128
#define GBK 16

__global__ __launch_bounds__(256, 2)
void gemm_bias(const float* __restrict__ A, const float* __restrict__ W,
               const float* __restrict__ bias, float* __restrict__ C,
               int M, int N, int K, float alpha)
{
    __shared__ float As[GBK][GBM + 4];
    __shared__ float Ws[GBK][GBN + 4];

    const int tid = threadIdx.x;
    const int bm = blockIdx.y * GBM;
    const int bn = blockIdx.x * GBN;
    const int tx = tid & 15;        // 0..15 -> N
    const int ty = tid >> 4;        // 0..15 -> M

    float acc[8][8];
#pragma unroll
    for (int i = 0; i < 8; i++)
#pragma unroll
        for (int j = 0; j < 8; j++) acc[i][j] = 0.f;

    for (int k0 = 0; k0 < K; k0 += GBK) {
        // load A tile (128 x 16): 512 float4, 2 per thread
#pragma unroll
        for (int i = 0; i < 2; i++) {
            int fid = tid + i * 256;          // 0..511
            int r = fid >> 2;                 // row in tile
            int c4 = (fid & 3) << 2;          // col 0,4,8,12
            float4 v = *(const float4*)&A[(size_t)(bm + r) * K + k0 + c4];
            As[c4 + 0][r] = v.x; As[c4 + 1][r] = v.y;
            As[c4 + 2][r] = v.z; As[c4 + 3][r] = v.w;
        }
        // load W tile (128 x 16)
#pragma unroll
        for (int i = 0; i < 2; i++) {
            int fid = tid + i * 256;
            int r = fid >> 2;
            int c4 = (fid & 3) << 2;
            float4 v = *(const float4*)&W[(size_t)(bn + r) * K + k0 + c4];
            Ws[c4 + 0][r] = v.x; Ws[c4 + 1][r] = v.y;
            Ws[c4 + 2][r] = v.z; Ws[c4 + 3][r] = v.w;
        }
        __syncthreads();

#pragma unroll
        for (int kk = 0; kk < GBK; kk++) {
            float4 a0 = *(const float4*)&As[kk][ty * 8];
            float4 a1 = *(const float4*)&As[kk][ty * 8 + 4];
            float4 b0 = *(const float4*)&Ws[kk][tx * 8];
            float4 b1 = *(const float4*)&Ws[kk][tx * 8 + 4];
            float a[8] = {a0.x, a0.y, a0.z, a0.w, a1.x, a1.y, a1.z, a1.w};
            float b[8] = {b0.x, b0.y, b0.z, b0.w, b1.x, b1.y, b1.z, b1.w};
#pragma unroll
            for (int i = 0; i < 8; i++)
#pragma unroll
                for (int j = 0; j < 8; j++)
                    acc[i][j] += a[i] * b[j];
        }
        __syncthreads();
    }

#pragma unroll
    for (int i = 0; i < 8; i++) {
        int row = bm + ty * 8 + i;
#pragma unroll
        for (int j = 0; j < 8; j++) {
            int col = bn + tx * 8 + j;
            C[(size_t)row * N + col] = alpha * (acc[i][j] + bias[col]);
        }
    }
}

// ---------------------------------------------------------------------------
// Fused attention: per block = one (b, h, 32-row q tile).
// Q already scaled by 1/SCALE.
// scores = q@k^T + rbias(q, pe_k), mask, softmax, attn write,
// o = attn@V + w @ pe_v, where w = 9-bucket sums of attn row.
// ---------------------------------------------------------------------------
#define QT 32
#define KT 64

// shared memory layout (floats)
#define SC_OFF   0                      // 32*1024
#define QS_OFF   (SC_OFF + QT * S_LEN)  // 32*64
#define KT_OFF   (QS_OFF + QT * DHEAD)  // 64*65
#define PEK_OFF  (KT_OFF + 64 * 65)     // 9*64
#define PEV_OFF  (PEK_OFF + 9 * 64)     // 9*64
#define RB_OFF   (PEV_OFF + 9 * 64)     // 32*12
#define WS_OFF   (RB_OFF + QT * 12)     // 32*12
#define MSK_OFF  (WS_OFF + QT * 12)     // 1024 ints
#define SMEM_FLOATS (MSK_OFF + S_LEN)
#define SMEM_BYTES (SMEM_FLOATS * 4)

__global__ void attn_kernel(const float* __restrict__ Q, const float* __restrict__ K,
                            const float* __restrict__ V, const int* __restrict__ mask,
                            const float* __restrict__ pe_k, const float* __restrict__ pe_v,
                            float* __restrict__ attn_out, float* __restrict__ Obuf)
{
    extern __shared__ float sm[];
    float* sc  = sm + SC_OFF;
    float* qs  = sm + QS_OFF;
    float* kt  = sm + KT_OFF;
    float* pek = sm + PEK_OFF;
    float* pev = sm + PEV_OFF;
    float* rb  = sm + RB_OFF;
    float* ws  = sm + WS_OFF;
    int*   msk = (int*)(sm + MSK_OFF);

    const int b  = blockIdx.z;
    const int h  = blockIdx.y;
    const int qb = blockIdx.x * QT;
    const int tid = threadIdx.x;
    const int ty = tid >> 5;   // warp id 0..7
    const int tx = tid & 31;   // lane

    // load q tile (scaled by 1/8 already), pe tables, mask row
    for (int i = tid; i < QT * DHEAD; i += 256) {
        int qi = i >> 6, d = i & 63;
        qs[qi * DHEAD + d] = Q[(size_t)(b * S_LEN + qb + qi) * DMODEL + h * DHEAD + d];
    }
    for (int i = tid; i < 9 * 64; i += 256) {
        pek[i] = pe_k[i];
        pev[i] = pe_v[i];
    }
    for (int i = tid; i < S_LEN; i += 256) msk[i] = mask[b * S_LEN + i];
    __syncthreads();

    // relative-K bias table: rb[qi][j] = q_scaled . pe_k[j]
    for (int i = tid; i < QT * 9; i += 256) {
        int qi = i / 9, j = i % 9;
        float s = 0.f;
        const float* qr = qs + qi * DHEAD;
        const float* pr = pek + j * 64;
#pragma unroll 16
        for (int d = 0; d < 64; d++) s += qr[d] * pr[d];
        rb[qi * 12 + j] = s;
    }

    // ---- scores ----
    for (int kb = 0; kb < S_LEN / KT; kb++) {
        __syncthreads();  // protect kt reuse (also orders rb writes on kb==0)
        // load K tile transposed: kt[d*65 + kk]
        for (int i = tid; i < KT * DHEAD; i += 256) {
            int kk = i >> 6, d = i & 63;
            kt[d * 65 + kk] = K[(size_t)(b * S_LEN + kb * KT + kk) * DMODEL + h * DHEAD + d];
        }
        __syncthreads();

        float acc[4][2] = {{0.f, 0.f}, {0.f, 0.f}, {0.f, 0.f}, {0.f, 0.f}};
#pragma unroll 8
        for (int d = 0; d < 64; d++) {
            float k0 = kt[d * 65 + tx];
            float k1 = kt[d * 65 + tx + 32];
#pragma unroll
            for (int r = 0; r < 4; r++) {
                float qv = qs[(ty + r * 8) * DHEAD + d];
                acc[r][0] += qv * k0;
                acc[r][1] += qv * k1;
            }
        }
#pragma unroll
        for (int r = 0; r < 4; r++) {
            int qi = ty + r * 8;
            int qg = qb + qi;
#pragma unroll
            for (int c = 0; c < 2; c++) {
                int kg = kb * KT + tx + c * 32;
                int dlt = kg - qg;
                dlt = min(MAXK, max(-MAXK, dlt)) + MAXK;
                float v = acc[r][c] + rb[qi * 12 + dlt];
                sc[qi * S_LEN + kg] = msk[kg] ? v : -INFINITY;
            }
        }
    }
    __syncthreads();

    // ---- softmax (warp ty handles rows 4*ty .. 4*ty+3) + attn write + w buckets ----
    for (int r = 0; r < 4; r++) {
        int qi = ty * 4 + r;
        int qg = qb + qi;
        float* row = sc + qi * S_LEN;

        float m = -INFINITY;
        for (int k2 = tx; k2 < S_LEN; k2 += 32) m = fmaxf(m, row[k2]);
#pragma unroll
        for (int o = 16; o; o >>= 1) m = fmaxf(m, __shfl_xor_sync(0xFFFFFFFFu, m, o));

        float sum = 0.f;
        for (int k2 = tx; k2 < S_LEN; k2 += 32) {
            float e = __expf(row[k2] - m);
            row[k2] = e;
            sum += e;
        }
#pragma unroll
        for (int o = 16; o; o >>= 1) sum += __shfl_xor_sync(0xFFFFFFFFu, sum, o);
        float inv = 1.f / sum;

        float* ao = attn_out ? attn_out + ((size_t)(b * NHEAD + h) * S_LEN + qg) * S_LEN
                             : (float*)0;
        float w0 = 0.f, w8 = 0.f;
        for (int k2 = tx; k2 < S_LEN; k2 += 32) {
            float p = row[k2] * inv;
            row[k2] = p;
            if (ao) ao[k2] = p;
            if (k2 <= qg - MAXK) w0 += p;
            if (k2 >= qg + MAXK) w8 += p;
        }
#pragma unroll
        for (int o = 16; o; o >>= 1) {
            w0 += __shfl_xor_sync(0xFFFFFFFFu, w0, o);
            w8 += __shfl_xor_sync(0xFFFFFFFFu, w8, o);
        }
        __syncwarp();
        if (tx == 0) { ws[qi * 12 + 0] = w0; ws[qi * 12 + 8] = w8; }
        if (tx >= 1 && tx <= 7) {
            int k2 = qg + tx - MAXK;
            ws[qi * 12 + tx] = (k2 >= 0 && k2 < S_LEN) ? row[k2] : 0.f;
        }
    }
    __syncthreads();

    // ---- o = attn @ V (+ rel_v epilogue) ----
    float o[4][2] = {{0.f, 0.f}, {0.f, 0.f}, {0.f, 0.f}, {0.f, 0.f}};
    for (int vb = 0; vb < S_LEN / KT; vb++) {
        // load V tile: vt[kk*65 + d] (reuse kt buffer)
        for (int i = tid; i < KT * DHEAD; i += 256) {
            int kk = i >> 6, d = i & 63;
            kt[kk * 65 + d] = V[(size_t)(b * S_LEN + vb * KT + kk) * DMODEL + h * DHEAD + d];
        }
        __syncthreads();
#pragma unroll 4
        for (int kk = 0; kk < KT; kk++) {
            float v0 = kt[kk * 65 + tx];
            float v1 = kt[kk * 65 + tx + 32];
#pragma unroll
            for (int r = 0; r < 4; r++) {
                float p = sc[(ty + r * 8) * S_LEN + vb * KT + kk];
                o[r][0] += p * v0;
                o[r][1] += p * v1;
            }
        }
        __syncthreads();
    }

#pragma unroll
    for (int r = 0; r < 4; r++) {
        int qi = ty + r * 8;
        float a0 = o[r][0], a1 = o[r][1];
#pragma unroll
        for (int j = 0; j < 9; j++) {
            float wv = ws[qi * 12 + j];
            a0 += wv * pev[j * 64 + tx];
            a1 += wv * pev[j * 64 + tx + 32];
        }
        size_t base = (size_t)(b * S_LEN + qb + qi) * DMODEL + h * DHEAD;
        Obuf[base + tx] = a0;
        Obuf[base + tx + 32] = a1;
    }
}

// ---------------------------------------------------------------------------
extern "C" void kernel_launch(void* const* d_in, const int* in_sizes, int n_in,
                              void* d_out, int out_size)
{
    const float* query = (const float*)d_in[0];
    const float* key   = (const float*)d_in[1];
    const float* value = (const float*)d_in[2];
    const int*   mask  = (const int*)d_in[3];
    const float* Wq = (const float*)d_in[4];
    const float* bq = (const float*)d_in[5];
    const float* Wk = (const float*)d_in[6];
    const float* bk = (const float*)d_in[7];
    const float* Wv = (const float*)d_in[8];
    const float* bv = (const float*)d_in[9];
    const float* Wo = (const float*)d_in[10];
    const float* bo = (const float*)d_in[11];
    const float* pe_k = (const float*)d_in[12];
    const float* pe_v = (const float*)d_in[13];

    float* qbuf; float* kbuf; float* vbuf; float* obuf;
    cudaGetSymbolAddress((void**)&qbuf, g_Q);
    cudaGetSymbolAddress((void**)&kbuf, g_K);
    cudaGetSymbolAddress((void**)&vbuf, g_V);
    cudaGetSymbolAddress((void**)&obuf, g_O);

    const long long OUT_ELEMS = (long long)BATCH * S_LEN * DMODEL;     // 8388608
    float* out_ptr  = (float*)d_out;
    float* attn_ptr = ((long long)out_size > OUT_ELEMS) ? (float*)d_out + OUT_ELEMS
                                                        : (float*)0;

    cudaFuncSetAttribute(attn_kernel, cudaFuncAttributeMaxDynamicSharedMemorySize,
                         SMEM_BYTES);

    dim3 gg(DMODEL / GBN, MROWS / GBM);   // (8, 64)

    // projections; fold 1/SCALE (=1/8) into Q
    gemm_bias<<<gg, 256>>>(query, Wq, bq, qbuf, MROWS, DMODEL, DMODEL, 0.125f);
    gemm_bias<<<gg, 256>>>(key,   Wk, bk, kbuf, MROWS, DMODEL, DMODEL, 1.0f);
    gemm_bias<<<gg, 256>>>(value, Wv, bv, vbuf, MROWS, DMODEL, DMODEL, 1.0f);

    // fused attention
    dim3 ga(S_LEN / QT, NHEAD, BATCH);    // (32, 16, 8)
    attn_kernel<<<ga, 256, SMEM_BYTES>>>(qbuf, kbuf, vbuf, mask, pe_k, pe_v,
                                         attn_ptr, obuf);

    // output projection
    gemm_bias<<<gg, 256>>>(obuf, Wo, bo, out_ptr, MROWS, DMODEL, DMODEL, 1.0f);
}

// round 3
// speedup vs baseline: 1.4994x; 1.4994x over previous
#include <cuda_runtime.h>
#include <cuda_bf16.h>
#include <math.h>
#include <cstdint>

// Problem constants
#define BATCH 8
#define S_LEN 1024
#define DMODEL 1024
#define NHEAD 16
#define DHEAD 64
#define MAXK 4
#define MROWS (BATCH * S_LEN)   // 8192

// Scratch (allocation-free rule -> device globals)
__device__ float g_Q[(size_t)MROWS * DMODEL];
__device__ float g_K[(size_t)MROWS * DMODEL];
__device__ float g_V[(size_t)MROWS * DMODEL];
__device__ float g_O[(size_t)MROWS * DMODEL];
__device__ __nv_bfloat16 g_act_hi[(size_t)MROWS * DMODEL];
__device__ __nv_bfloat16 g_act_lo[(size_t)MROWS * DMODEL];
__device__ __nv_bfloat16 g_w_hi[(size_t)DMODEL * DMODEL];
__device__ __nv_bfloat16 g_w_lo[(size_t)DMODEL * DMODEL];

// ---------------------------------------------------------------------------
// fp32 -> (bf16 hi, bf16 lo) split
// ---------------------------------------------------------------------------
__global__ void split_bf16_kernel(const float* __restrict__ x,
                                  __nv_bfloat16* __restrict__ hi,
                                  __nv_bfloat16* __restrict__ lo, int n4)
{
    int i = blockIdx.x * blockDim.x + threadIdx.x;
    if (i >= n4) return;
    float4 v = ((const float4*)x)[i];
    __nv_bfloat16 h0 = __float2bfloat16(v.x);
    __nv_bfloat16 h1 = __float2bfloat16(v.y);
    __nv_bfloat16 h2 = __float2bfloat16(v.z);
    __nv_bfloat16 h3 = __float2bfloat16(v.w);
    __nv_bfloat16 l0 = __float2bfloat16(v.x - __bfloat162float(h0));
    __nv_bfloat16 l1 = __float2bfloat16(v.y - __bfloat162float(h1));
    __nv_bfloat16 l2 = __float2bfloat16(v.z - __bfloat162float(h2));
    __nv_bfloat16 l3 = __float2bfloat16(v.w - __bfloat162float(h3));
    __nv_bfloat162* h2p = (__nv_bfloat162*)hi;
    __nv_bfloat162* l2p = (__nv_bfloat162*)lo;
    h2p[i * 2 + 0] = __halves2bfloat162(h0, h1);
    h2p[i * 2 + 1] = __halves2bfloat162(h2, h3);
    l2p[i * 2 + 0] = __halves2bfloat162(l0, l1);
    l2p[i * 2 + 1] = __halves2bfloat162(l2, l3);
}

// ---------------------------------------------------------------------------
// Warp-MMA (HMMA bf16 m16n8k16) GEMM: C = alpha * (A @ W^T + bias)
// A: (M,1024) hi/lo bf16 row-major; W: (1024,1024) hi/lo bf16 row-major (n,k)
// CTA tile 128x128, 8 warps = 2(M) x 4(N), warp tile 64x32, BK=32.
// Split precision: D = Ahi*Whi + Ahi*Wlo + Alo*Whi.
// ---------------------------------------------------------------------------
#define LDT 40   // smem row stride in bf16 (32 data + 8 pad)

__device__ __forceinline__ void mma16816(float* c, const uint32_t* a, const uint32_t* b) {
    asm volatile(
        "mma.sync.aligned.m16n8k16.row.col.f32.bf16.bf16.f32 "
        "{%0,%1,%2,%3}, {%4,%5,%6,%7}, {%8,%9}, {%0,%1,%2,%3};"
        : "+f"(c[0]), "+f"(c[1]), "+f"(c[2]), "+f"(c[3])
        : "r"(a[0]), "r"(a[1]), "r"(a[2]), "r"(a[3]), "r"(b[0]), "r"(b[1]));
}

__global__ __launch_bounds__(256, 2)
void gemm_mma(const __nv_bfloat16* __restrict__ Ahi, const __nv_bfloat16* __restrict__ Alo,
              const __nv_bfloat16* __restrict__ Whi, const __nv_bfloat16* __restrict__ Wlo,
              const float* __restrict__ bias, float* __restrict__ C, float alpha)
{
    __shared__ __nv_bfloat16 sA[2][128 * LDT];
    __shared__ __nv_bfloat16 sW[2][128 * LDT];

    const int tid = threadIdx.x;
    const int wid = tid >> 5;
    const int lane = tid & 31;
    const int wm = wid >> 2;          // 0..1
    const int wn = wid & 3;           // 0..3
    const int m0 = blockIdx.y * 128;
    const int n0 = blockIdx.x * 128;

    float acc[4][4][4];
#pragma unroll
    for (int i = 0; i < 4; i++)
#pragma unroll
        for (int j = 0; j < 4; j++)
#pragma unroll
            for (int k = 0; k < 4; k++) acc[i][j][k] = 0.f;

    const int lr = lane >> 2;         // 0..7
    const int lc = lane & 3;          // 0..3

    for (int k0 = 0; k0 < DMODEL; k0 += 32) {
        // load 4 tiles: 128 rows x 32 bf16 each; 512 uint4 per tile
#pragma unroll
        for (int i = 0; i < 2; i++) {
            int idx = i * 256 + tid;
            int r = idx >> 2;
            int cg = idx & 3;                       // 16B group
            size_t gsrc = (size_t)r * DMODEL + k0 + cg * 8;
            int sdst = r * LDT + cg * 8;
            *(uint4*)&sA[0][sdst] = *(const uint4*)&Ahi[(size_t)m0 * DMODEL + gsrc];
            *(uint4*)&sA[1][sdst] = *(const uint4*)&Alo[(size_t)m0 * DMODEL + gsrc];
            *(uint4*)&sW[0][sdst] = *(const uint4*)&Whi[(size_t)n0 * DMODEL + gsrc];
            *(uint4*)&sW[1][sdst] = *(const uint4*)&Wlo[(size_t)n0 * DMODEL + gsrc];
        }
        __syncthreads();

#pragma unroll
        for (int ks = 0; ks < 2; ks++) {
            const int kb = ks * 16;
            const int kc = kb + lc * 2;

            uint32_t bh[4][2], bl[4][2];
#pragma unroll
            for (int ni = 0; ni < 4; ni++) {
                int nrow = wn * 32 + ni * 8 + lr;
                bh[ni][0] = *(const uint32_t*)&sW[0][nrow * LDT + kc];
                bh[ni][1] = *(const uint32_t*)&sW[0][nrow * LDT + kc + 8];
                bl[ni][0] = *(const uint32_t*)&sW[1][nrow * LDT + kc];
                bl[ni][1] = *(const uint32_t*)&sW[1][nrow * LDT + kc + 8];
            }

            uint32_t af[4][4];
            // hi-A pass: Ahi*Whi and Ahi*Wlo
#pragma unroll
            for (int mi = 0; mi < 4; mi++) {
                int mr = wm * 64 + mi * 16 + lr;
                af[mi][0] = *(const uint32_t*)&sA[0][mr * LDT + kc];
                af[mi][1] = *(const uint32_t*)&sA[0][(mr + 8) * LDT + kc];
                af[mi][2] = *(const uint32_t*)&sA[0][mr * LDT + kc + 8];
                af[mi][3] = *(const uint32_t*)&sA[0][(mr + 8) * LDT + kc + 8];
            }
#pragma unroll
            for (int mi = 0; mi < 4; mi++)
#pragma unroll
                for (int ni = 0; ni < 4; ni++) {
                    mma16816(acc[mi][ni], af[mi], bh[ni]);
                    mma16816(acc[mi][ni], af[mi], bl[ni]);
                }
            // lo-A pass: Alo*Whi
#pragma unroll
            for (int mi = 0; mi < 4; mi++) {
                int mr = wm * 64 + mi * 16 + lr;
                af[mi][0] = *(const uint32_t*)&sA[1][mr * LDT + kc];
                af[mi][1] = *(const uint32_t*)&sA[1][(mr + 8) * LDT + kc];
                af[mi][2] = *(const uint32_t*)&sA[1][mr * LDT + kc + 8];
                af[mi][3] = *(const uint32_t*)&sA[1][(mr + 8) * LDT + kc + 8];
            }
#pragma unroll
            for (int mi = 0; mi < 4; mi++)
#pragma unroll
                for (int ni = 0; ni < 4; ni++)
                    mma16816(acc[mi][ni], af[mi], bh[ni]);
        }
        __syncthreads();
    }

    // epilogue
#pragma unroll
    for (int mi = 0; mi < 4; mi++) {
        int row = m0 + wm * 64 + mi * 16 + lr;
#pragma unroll
        for (int ni = 0; ni < 4; ni++) {
            int col = n0 + wn * 32 + ni * 8 + lc * 2;
            float2 b2 = *(const float2*)&bias[col];
            float2 v0, v1;
            v0.x = alpha * (acc[mi][ni][0] + b2.x);
            v0.y = alpha * (acc[mi][ni][1] + b2.y);
            v1.x = alpha * (acc[mi][ni][2] + b2.x);
            v1.y = alpha * (acc[mi][ni][3] + b2.y);
            *(float2*)&C[(size_t)row * DMODEL + col] = v0;
            *(float2*)&C[(size_t)(row + 8) * DMODEL + col] = v1;
        }
    }
}

// ---------------------------------------------------------------------------
// Fused attention: per block = one (b, h, 32-row q tile). 512 threads.
// ---------------------------------------------------------------------------
#define QT 32
#define KT 64
#define ATH 512

#define SC_OFF   0
#define QS_OFF   (SC_OFF + QT * S_LEN)
#define KT_OFF   (QS_OFF + QT * DHEAD)
#define PEK_OFF  (KT_OFF + 64 * 65)
#define PEV_OFF  (PEK_OFF + 9 * 64)
#define RB_OFF   (PEV_OFF + 9 * 64)
#define WS_OFF   (RB_OFF + QT * 12)
#define MSK_OFF  (WS_OFF + QT * 12)
#define SMEM_FLOATS (MSK_OFF + S_LEN)
#define SMEM_BYTES (SMEM_FLOATS * 4)

__global__ __launch_bounds__(ATH)
void attn_kernel(const float* __restrict__ Q, const float* __restrict__ K,
                 const float* __restrict__ V, const int* __restrict__ mask,
                 const float* __restrict__ pe_k, const float* __restrict__ pe_v,
                 float* __restrict__ attn_out, float* __restrict__ Obuf)
{
    extern __shared__ float sm[];
    float* sc  = sm + SC_OFF;
    float* qs  = sm + QS_OFF;
    float* kt  = sm + KT_OFF;
    float* pek = sm + PEK_OFF;
    float* pev = sm + PEV_OFF;
    float* rb  = sm + RB_OFF;
    float* ws  = sm + WS_OFF;
    int*   msk = (int*)(sm + MSK_OFF);

    const int b  = blockIdx.z;
    const int h  = blockIdx.y;
    const int qb = blockIdx.x * QT;
    const int tid = threadIdx.x;
    const int ty = tid >> 5;   // warp id 0..15
    const int tx = tid & 31;

    for (int i = tid; i < QT * DHEAD; i += ATH) {
        int qi = i >> 6, d = i & 63;
        qs[qi * DHEAD + d] = Q[(size_t)(b * S_LEN + qb + qi) * DMODEL + h * DHEAD + d];
    }
    for (int i = tid; i < 9 * 64; i += ATH) {
        pek[i] = pe_k[i];
        pev[i] = pe_v[i];
    }
    for (int i = tid; i < S_LEN; i += ATH) msk[i] = mask[b * S_LEN + i];
    __syncthreads();

    for (int i = tid; i < QT * 9; i += ATH) {
        int qi = i / 9, j = i % 9;
        float s = 0.f;
        const float* qr = qs + qi * DHEAD;
        const float* pr = pek + j * 64;
#pragma unroll 16
        for (int d = 0; d < 64; d++) s += qr[d] * pr[d];
        rb[qi * 12 + j] = s;
    }

    // ---- scores ----
    for (int kb = 0; kb < S_LEN / KT; kb++) {
        __syncthreads();
        for (int i = tid; i < KT * DHEAD; i += ATH) {
            int kk = i >> 6, d = i & 63;
            kt[d * 65 + kk] = K[(size_t)(b * S_LEN + kb * KT + kk) * DMODEL + h * DHEAD + d];
        }
        __syncthreads();

        float acc[2][2] = {{0.f, 0.f}, {0.f, 0.f}};
#pragma unroll 8
        for (int d = 0; d < 64; d++) {
            float k0 = kt[d * 65 + tx];
            float k1 = kt[d * 65 + tx + 32];
#pragma unroll
            for (int r = 0; r < 2; r++) {
                float qv = qs[(ty + r * 16) * DHEAD + d];
                acc[r][0] += qv * k0;
                acc[r][1] += qv * k1;
            }
        }
#pragma unroll
        for (int r = 0; r < 2; r++) {
            int qi = ty + r * 16;
            int qg = qb + qi;
#pragma unroll
            for (int c = 0; c < 2; c++) {
                int kg = kb * KT + tx + c * 32;
                int dlt = kg - qg;
                dlt = min(MAXK, max(-MAXK, dlt)) + MAXK;
                float v = acc[r][c] + rb[qi * 12 + dlt];
                sc[qi * S_LEN + kg] = msk[kg] ? v : -INFINITY;
            }
        }
    }
    __syncthreads();

    // ---- softmax: warp ty handles rows 2*ty, 2*ty+1 ----
#pragma unroll
    for (int r = 0; r < 2; r++) {
        int qi = ty * 2 + r;
        int qg = qb + qi;
        float* row = sc + qi * S_LEN;

        float m = -INFINITY;
        for (int k2 = tx; k2 < S_LEN; k2 += 32) m = fmaxf(m, row[k2]);
#pragma unroll
        for (int o = 16; o; o >>= 1) m = fmaxf(m, __shfl_xor_sync(0xFFFFFFFFu, m, o));

        float sum = 0.f;
        for (int k2 = tx; k2 < S_LEN; k2 += 32) {
            float e = __expf(row[k2] - m);
            row[k2] = e;
            sum += e;
        }
#pragma unroll
        for (int o = 16; o; o >>= 1) sum += __shfl_xor_sync(0xFFFFFFFFu, sum, o);
        float inv = 1.f / sum;

        float* ao = attn_out ? attn_out + ((size_t)(b * NHEAD + h) * S_LEN + qg) * S_LEN
                             : (float*)0;
        float w0 = 0.f, w8 = 0.f;
        for (int k2 = tx; k2 < S_LEN; k2 += 32) {
            float p = row[k2] * inv;
            row[k2] = p;
            if (ao) ao[k2] = p;
            if (k2 <= qg - MAXK) w0 += p;
            if (k2 >= qg + MAXK) w8 += p;
        }
#pragma unroll
        for (int o = 16; o; o >>= 1) {
            w0 += __shfl_xor_sync(0xFFFFFFFFu, w0, o);
            w8 += __shfl_xor_sync(0xFFFFFFFFu, w8, o);
        }
        __syncwarp();
        if (tx == 0) { ws[qi * 12 + 0] = w0; ws[qi * 12 + 8] = w8; }
        if (tx >= 1 && tx <= 7) {
            int k2 = qg + tx - MAXK;
            ws[qi * 12 + tx] = (k2 >= 0 && k2 < S_LEN) ? row[k2] : 0.f;
        }
    }
    __syncthreads();

    // ---- o = attn @ V (+ rel_v epilogue) ----
    float o[2][2] = {{0.f, 0.f}, {0.f, 0.f}};
    for (int vb = 0; vb < S_LEN / KT; vb++) {
        for (int i = tid; i < KT * DHEAD; i += ATH) {
            int kk = i >> 6, d = i & 63;
            kt[kk * 65 + d] = V[(size_t)(b * S_LEN + vb * KT + kk) * DMODEL + h * DHEAD + d];
        }
        __syncthreads();
#pragma unroll 4
        for (int kk = 0; kk < KT; kk++) {
            float v0 = kt[kk * 65 + tx];
            float v1 = kt[kk * 65 + tx + 32];
#pragma unroll
            for (int r = 0; r < 2; r++) {
                float p = sc[(ty + r * 16) * S_LEN + vb * KT + kk];
                o[r][0] += p * v0;
                o[r][1] += p * v1;
            }
        }
        __syncthreads();
    }

#pragma unroll
    for (int r = 0; r < 2; r++) {
        int qi = ty + r * 16;
        float a0 = o[r][0], a1 = o[r][1];
#pragma unroll
        for (int j = 0; j < 9; j++) {
            float wv = ws[qi * 12 + j];
            a0 += wv * pev[j * 64 + tx];
            a1 += wv * pev[j * 64 + tx + 32];
        }
        size_t base = (size_t)(b * S_LEN + qb + qi) * DMODEL + h * DHEAD;
        Obuf[base + tx] = a0;
        Obuf[base + tx + 32] = a1;
    }
}

// ---------------------------------------------------------------------------
extern "C" void kernel_launch(void* const* d_in, const int* in_sizes, int n_in,
                              void* d_out, int out_size)
{
    const float* query = (const float*)d_in[0];
    const float* key   = (const float*)d_in[1];
    const float* value = (const float*)d_in[2];
    const int*   mask  = (const int*)d_in[3];
    const float* Wq = (const float*)d_in[4];
    const float* bq = (const float*)d_in[5];
    const float* Wk = (const float*)d_in[6];
    const float* bk = (const float*)d_in[7];
    const float* Wv = (const float*)d_in[8];
    const float* bv = (const float*)d_in[9];
    const float* Wo = (const float*)d_in[10];
    const float* bo = (const float*)d_in[11];
    const float* pe_k = (const float*)d_in[12];
    const float* pe_v = (const float*)d_in[13];

    float *qbuf, *kbuf, *vbuf, *obuf;
    __nv_bfloat16 *ahi, *alo, *whi, *wlo;
    cudaGetSymbolAddress((void**)&qbuf, g_Q);
    cudaGetSymbolAddress((void**)&kbuf, g_K);
    cudaGetSymbolAddress((void**)&vbuf, g_V);
    cudaGetSymbolAddress((void**)&obuf, g_O);
    cudaGetSymbolAddress((void**)&ahi, g_act_hi);
    cudaGetSymbolAddress((void**)&alo, g_act_lo);
    cudaGetSymbolAddress((void**)&whi, g_w_hi);
    cudaGetSymbolAddress((void**)&wlo, g_w_lo);

    const long long OUT_ELEMS = (long long)BATCH * S_LEN * DMODEL;
    float* out_ptr  = (float*)d_out;
    float* attn_ptr = ((long long)out_size > OUT_ELEMS) ? (float*)d_out + OUT_ELEMS
                                                        : (float*)0;

    cudaFuncSetAttribute(attn_kernel, cudaFuncAttributeMaxDynamicSharedMemorySize,
                         SMEM_BYTES);

    const int ACT4 = MROWS * DMODEL / 4;
    const int W4   = DMODEL * DMODEL / 4;
    dim3 gg(DMODEL / 128, MROWS / 128);    // (8, 64)

    // Q projection (fold 1/SCALE = 0.125)
    split_bf16_kernel<<<ACT4 / 256, 256>>>(query, ahi, alo, ACT4);
    split_bf16_kernel<<<W4 / 256, 256>>>(Wq, whi, wlo, W4);
    gemm_mma<<<gg, 256>>>(ahi, alo, whi, wlo, bq, qbuf, 0.125f);
    // K projection
    split_bf16_kernel<<<ACT4 / 256, 256>>>(key, ahi, alo, ACT4);
    split_bf16_kernel<<<W4 / 256, 256>>>(Wk, whi, wlo, W4);
    gemm_mma<<<gg, 256>>>(ahi, alo, whi, wlo, bk, kbuf, 1.0f);
    // V projection
    split_bf16_kernel<<<ACT4 / 256, 256>>>(value, ahi, alo, ACT4);
    split_bf16_kernel<<<W4 / 256, 256>>>(Wv, whi, wlo, W4);
    gemm_mma<<<gg, 256>>>(ahi, alo, whi, wlo, bv, vbuf, 1.0f);

    // fused attention
    dim3 ga(S_LEN / QT, NHEAD, BATCH);    // (32, 16, 8)
    attn_kernel<<<ga, ATH, SMEM_BYTES>>>(qbuf, kbuf, vbuf, mask, pe_k, pe_v,
                                         attn_ptr, obuf);

    // output projection
    split_bf16_kernel<<<ACT4 / 256, 256>>>(obuf, ahi, alo, ACT4);
    split_bf16_kernel<<<W4 / 256, 256>>>(Wo, whi, wlo, W4);
    gemm_mma<<<gg, 256>>>(ahi, alo, whi, wlo, bo, out_ptr, 1.0f);
}

// round 4
// speedup vs baseline: 1.7531x; 1.1692x over previous
#include <cuda_runtime.h>
#include <cuda_bf16.h>
#include <math.h>
#include <cstdint>

#define BATCH 8
#define S_LEN 1024
#define DMODEL 1024
#define NHEAD 16
#define DHEAD 64
#define MAXK 4
#define MROWS (BATCH * S_LEN)   // 8192

// Scratch (allocation-free rule -> device globals)
__device__ __nv_bfloat16 g_act_hi[(size_t)MROWS * DMODEL];
__device__ __nv_bfloat16 g_act_lo[(size_t)MROWS * DMODEL];
__device__ __nv_bfloat16 g_w_hi[(size_t)DMODEL * DMODEL];
__device__ __nv_bfloat16 g_w_lo[(size_t)DMODEL * DMODEL];
__device__ __nv_bfloat16 g_qh[(size_t)MROWS * DMODEL];
__device__ __nv_bfloat16 g_ql[(size_t)MROWS * DMODEL];
__device__ __nv_bfloat16 g_kh[(size_t)MROWS * DMODEL];
__device__ __nv_bfloat16 g_kl[(size_t)MROWS * DMODEL];
__device__ __nv_bfloat16 g_vh[(size_t)MROWS * DMODEL];
__device__ __nv_bfloat16 g_vl[(size_t)MROWS * DMODEL];
__device__ __nv_bfloat16 g_oh[(size_t)MROWS * DMODEL];
__device__ __nv_bfloat16 g_ol[(size_t)MROWS * DMODEL];

// ---------------------------------------------------------------------------
__device__ __forceinline__ void mma16816(float* c, const uint32_t* a, const uint32_t* b) {
    asm volatile(
        "mma.sync.aligned.m16n8k16.row.col.f32.bf16.bf16.f32 "
        "{%0,%1,%2,%3}, {%4,%5,%6,%7}, {%8,%9}, {%0,%1,%2,%3};"
        : "+f"(c[0]), "+f"(c[1]), "+f"(c[2]), "+f"(c[3])
        : "r"(a[0]), "r"(a[1]), "r"(a[2]), "r"(a[3]), "r"(b[0]), "r"(b[1]));
}
__device__ __forceinline__ uint32_t pack_bf16(float x, float y) {
    __nv_bfloat162 t = __halves2bfloat162(__float2bfloat16(x), __float2bfloat16(y));
    return *(uint32_t*)&t;
}

// ---------------------------------------------------------------------------
// fp32 -> (bf16 hi, bf16 lo) split
// ---------------------------------------------------------------------------
__global__ void split_bf16_kernel(const float* __restrict__ x,
                                  __nv_bfloat16* __restrict__ hi,
                                  __nv_bfloat16* __restrict__ lo, int n4)
{
    int i = blockIdx.x * blockDim.x + threadIdx.x;
    if (i >= n4) return;
    float4 v = ((const float4*)x)[i];
    __nv_bfloat16 h0 = __float2bfloat16(v.x);
    __nv_bfloat16 h1 = __float2bfloat16(v.y);
    __nv_bfloat16 h2 = __float2bfloat16(v.z);
    __nv_bfloat16 h3 = __float2bfloat16(v.w);
    __nv_bfloat16 l0 = __float2bfloat16(v.x - __bfloat162float(h0));
    __nv_bfloat16 l1 = __float2bfloat16(v.y - __bfloat162float(h1));
    __nv_bfloat16 l2 = __float2bfloat16(v.z - __bfloat162float(h2));
    __nv_bfloat16 l3 = __float2bfloat16(v.w - __bfloat162float(h3));
    __nv_bfloat162* h2p = (__nv_bfloat162*)hi;
    __nv_bfloat162* l2p = (__nv_bfloat162*)lo;
    h2p[i * 2 + 0] = __halves2bfloat162(h0, h1);
    h2p[i * 2 + 1] = __halves2bfloat162(h2, h3);
    l2p[i * 2 + 0] = __halves2bfloat162(l0, l1);
    l2p[i * 2 + 1] = __halves2bfloat162(l2, l3);
}

// ---------------------------------------------------------------------------
// HMMA GEMM: out = alpha * (A @ W^T + bias); writes fp32 C and/or bf16 hi/lo
// ---------------------------------------------------------------------------
#define LDT 40

__global__ __launch_bounds__(256, 2)
void gemm_mma(const __nv_bfloat16* __restrict__ Ahi, const __nv_bfloat16* __restrict__ Alo,
              const __nv_bfloat16* __restrict__ Whi, const __nv_bfloat16* __restrict__ Wlo,
              const float* __restrict__ bias, float* __restrict__ C,
              __nv_bfloat16* __restrict__ Chi, __nv_bfloat16* __restrict__ Clo,
              float alpha)
{
    __shared__ __nv_bfloat16 sA[2][128 * LDT];
    __shared__ __nv_bfloat16 sW[2][128 * LDT];

    const int tid = threadIdx.x;
    const int wid = tid >> 5;
    const int lane = tid & 31;
    const int wm = wid >> 2;
    const int wn = wid & 3;
    const int m0 = blockIdx.y * 128;
    const int n0 = blockIdx.x * 128;

    float acc[4][4][4];
#pragma unroll
    for (int i = 0; i < 4; i++)
#pragma unroll
        for (int j = 0; j < 4; j++)
#pragma unroll
            for (int k = 0; k < 4; k++) acc[i][j][k] = 0.f;

    const int lr = lane >> 2;
    const int lc = lane & 3;

    for (int k0 = 0; k0 < DMODEL; k0 += 32) {
#pragma unroll
        for (int i = 0; i < 2; i++) {
            int idx = i * 256 + tid;
            int r = idx >> 2;
            int cg = idx & 3;
            size_t gsrc = (size_t)r * DMODEL + k0 + cg * 8;
            int sdst = r * LDT + cg * 8;
            *(uint4*)&sA[0][sdst] = *(const uint4*)&Ahi[(size_t)m0 * DMODEL + gsrc];
            *(uint4*)&sA[1][sdst] = *(const uint4*)&Alo[(size_t)m0 * DMODEL + gsrc];
            *(uint4*)&sW[0][sdst] = *(const uint4*)&Whi[(size_t)n0 * DMODEL + gsrc];
            *(uint4*)&sW[1][sdst] = *(const uint4*)&Wlo[(size_t)n0 * DMODEL + gsrc];
        }
        __syncthreads();

#pragma unroll
        for (int ks = 0; ks < 2; ks++) {
            const int kc = ks * 16 + lc * 2;
            uint32_t bh[4][2], bl[4][2];
#pragma unroll
            for (int ni = 0; ni < 4; ni++) {
                int nrow = wn * 32 + ni * 8 + lr;
                bh[ni][0] = *(const uint32_t*)&sW[0][nrow * LDT + kc];
                bh[ni][1] = *(const uint32_t*)&sW[0][nrow * LDT + kc + 8];
                bl[ni][0] = *(const uint32_t*)&sW[1][nrow * LDT + kc];
                bl[ni][1] = *(const uint32_t*)&sW[1][nrow * LDT + kc + 8];
            }
            uint32_t af[4][4];
#pragma unroll
            for (int mi = 0; mi < 4; mi++) {
                int mr = wm * 64 + mi * 16 + lr;
                af[mi][0] = *(const uint32_t*)&sA[0][mr * LDT + kc];
                af[mi][1] = *(const uint32_t*)&sA[0][(mr + 8) * LDT + kc];
                af[mi][2] = *(const uint32_t*)&sA[0][mr * LDT + kc + 8];
                af[mi][3] = *(const uint32_t*)&sA[0][(mr + 8) * LDT + kc + 8];
            }
#pragma unroll
            for (int mi = 0; mi < 4; mi++)
#pragma unroll
                for (int ni = 0; ni < 4; ni++) {
                    mma16816(acc[mi][ni], af[mi], bh[ni]);
                    mma16816(acc[mi][ni], af[mi], bl[ni]);
                }
#pragma unroll
            for (int mi = 0; mi < 4; mi++) {
                int mr = wm * 64 + mi * 16 + lr;
                af[mi][0] = *(const uint32_t*)&sA[1][mr * LDT + kc];
                af[mi][1] = *(const uint32_t*)&sA[1][(mr + 8) * LDT + kc];
                af[mi][2] = *(const uint32_t*)&sA[1][mr * LDT + kc + 8];
                af[mi][3] = *(const uint32_t*)&sA[1][(mr + 8) * LDT + kc + 8];
            }
#pragma unroll
            for (int mi = 0; mi < 4; mi++)
#pragma unroll
                for (int ni = 0; ni < 4; ni++)
                    mma16816(acc[mi][ni], af[mi], bh[ni]);
        }
        __syncthreads();
    }

#pragma unroll
    for (int mi = 0; mi < 4; mi++) {
        int row = m0 + wm * 64 + mi * 16 + lr;
#pragma unroll
        for (int ni = 0; ni < 4; ni++) {
            int col = n0 + wn * 32 + ni * 8 + lc * 2;
            float2 b2 = *(const float2*)&bias[col];
            float v0x = alpha * (acc[mi][ni][0] + b2.x);
            float v0y = alpha * (acc[mi][ni][1] + b2.y);
            float v1x = alpha * (acc[mi][ni][2] + b2.x);
            float v1y = alpha * (acc[mi][ni][3] + b2.y);
            size_t p0 = (size_t)row * DMODEL + col;
            size_t p1 = (size_t)(row + 8) * DMODEL + col;
            if (C) {
                *(float2*)&C[p0] = make_float2(v0x, v0y);
                *(float2*)&C[p1] = make_float2(v1x, v1y);
            }
            if (Chi) {
                uint32_t h0 = pack_bf16(v0x, v0y);
                uint32_t h1 = pack_bf16(v1x, v1y);
                *(uint32_t*)&Chi[p0] = h0;
                *(uint32_t*)&Chi[p1] = h1;
                __nv_bfloat162 hh0 = *(__nv_bfloat162*)&h0;
                __nv_bfloat162 hh1 = *(__nv_bfloat162*)&h1;
                *(uint32_t*)&Clo[p0] = pack_bf16(v0x - __bfloat162float(hh0.x),
                                                 v0y - __bfloat162float(hh0.y));
                *(uint32_t*)&Clo[p1] = pack_bf16(v1x - __bfloat162float(hh1.x),
                                                 v1y - __bfloat162float(hh1.y));
            }
        }
    }
}

// ---------------------------------------------------------------------------
// Fused HMMA attention. Block = (b, h, 32-row q tile). 256 threads / 8 warps.
// Scores and PV both split-precision HMMA (3 passes).
// ---------------------------------------------------------------------------
#define QT 32
// smem byte offsets
#define O_SC   0                       // 32*1024 f32 = 131072 (later phi/plo)
#define O_QH   131072                  // 32*72 bf16 = 4608
#define O_QL   (O_QH + 4608)
#define O_KTH  140288                  // 64*72 bf16 = 9216
#define O_KTL  (O_KTH + 9216)
#define O_PEK  158720                  // 576 f32
#define O_PEV  (O_PEK + 2304)
#define O_RB   163328                  // 384 f32
#define O_WS   (O_RB + 1536)
#define O_MSK  166400                  // 1024 int
#define ATT_SMEM 170496

__global__ __launch_bounds__(256)
void attn_mma(const __nv_bfloat16* __restrict__ qh, const __nv_bfloat16* __restrict__ ql,
              const __nv_bfloat16* __restrict__ kh, const __nv_bfloat16* __restrict__ kl,
              const __nv_bfloat16* __restrict__ vh, const __nv_bfloat16* __restrict__ vl,
              const int* __restrict__ mask, const float* __restrict__ pe_k,
              const float* __restrict__ pe_v, float* __restrict__ attn_out,
              __nv_bfloat16* __restrict__ Oh, __nv_bfloat16* __restrict__ Ol)
{
    extern __shared__ char smem[];
    float* sc = (float*)(smem + O_SC);
    __nv_bfloat16* QH = (__nv_bfloat16*)(smem + O_QH);
    __nv_bfloat16* QL = (__nv_bfloat16*)(smem + O_QL);
    __nv_bfloat16* KTH = (__nv_bfloat16*)(smem + O_KTH);
    __nv_bfloat16* KTL = (__nv_bfloat16*)(smem + O_KTL);
    float* pek = (float*)(smem + O_PEK);
    float* pev = (float*)(smem + O_PEV);
    float* rb  = (float*)(smem + O_RB);
    float* ws  = (float*)(smem + O_WS);
    int*   msk = (int*)(smem + O_MSK);

    const int b  = blockIdx.z;
    const int h  = blockIdx.y;
    const int qb = blockIdx.x * QT;
    const int tid = threadIdx.x;
    const int w = tid >> 5;
    const int lane = tid & 31;
    const int lr = lane >> 2;
    const int lc = lane & 3;
    const int n0 = w * 8;

    // ---- load Q tile (hi/lo), pe tables, mask ----
    {
        int row = tid >> 3, dg = tid & 7;
        size_t g = (size_t)(b * S_LEN + qb + row) * DMODEL + h * DHEAD + dg * 8;
        *(uint4*)&QH[row * 72 + dg * 8] = *(const uint4*)&qh[g];
        *(uint4*)&QL[row * 72 + dg * 8] = *(const uint4*)&ql[g];
    }
    for (int i = tid; i < 576; i += 256) { pek[i] = pe_k[i]; pev[i] = pe_v[i]; }
    for (int i = tid; i < S_LEN; i += 256) msk[i] = mask[b * S_LEN + i];
    __syncthreads();

    // rb[qi][j] = q . pe_k[j]  (q reconstructed hi+lo)
    for (int i = tid; i < QT * 9; i += 256) {
        int qi = i / 9, j = i % 9;
        float s = 0.f;
        const __nv_bfloat16* qhr = QH + qi * 72;
        const __nv_bfloat16* qlr = QL + qi * 72;
        const float* pr = pek + j * 64;
#pragma unroll 16
        for (int d = 0; d < 64; d++)
            s += (__bfloat162float(qhr[d]) + __bfloat162float(qlr[d])) * pr[d];
        rb[qi * 12 + j] = s;
    }

    // hoist Q fragments into registers
    uint32_t qah[4][2][4], qal[4][2][4];
#pragma unroll
    for (int ks = 0; ks < 4; ks++)
#pragma unroll
        for (int mt = 0; mt < 2; mt++) {
            int r = mt * 16 + lr;
            int kc = ks * 16 + lc * 2;
            qah[ks][mt][0] = *(const uint32_t*)&QH[r * 72 + kc];
            qah[ks][mt][1] = *(const uint32_t*)&QH[(r + 8) * 72 + kc];
            qah[ks][mt][2] = *(const uint32_t*)&QH[r * 72 + kc + 8];
            qah[ks][mt][3] = *(const uint32_t*)&QH[(r + 8) * 72 + kc + 8];
            qal[ks][mt][0] = *(const uint32_t*)&QL[r * 72 + kc];
            qal[ks][mt][1] = *(const uint32_t*)&QL[(r + 8) * 72 + kc];
            qal[ks][mt][2] = *(const uint32_t*)&QL[r * 72 + kc + 8];
            qal[ks][mt][3] = *(const uint32_t*)&QL[(r + 8) * 72 + kc + 8];
        }

    // ---- scores ----
    for (int kb = 0; kb < 16; kb++) {
        __syncthreads();
#pragma unroll
        for (int i = 0; i < 2; i++) {
            int idx = tid + i * 256;
            int r = idx >> 3, dg = idx & 7;
            size_t g = (size_t)(b * S_LEN + kb * 64 + r) * DMODEL + h * DHEAD + dg * 8;
            *(uint4*)&KTH[r * 72 + dg * 8] = *(const uint4*)&kh[g];
            *(uint4*)&KTL[r * 72 + dg * 8] = *(const uint4*)&kl[g];
        }
        __syncthreads();

        float c[2][4] = {{0.f,0.f,0.f,0.f},{0.f,0.f,0.f,0.f}};
#pragma unroll
        for (int ks = 0; ks < 4; ks++) {
            int kc = ks * 16 + lc * 2;
            uint32_t bh[2], bl[2];
            bh[0] = *(const uint32_t*)&KTH[(n0 + lr) * 72 + kc];
            bh[1] = *(const uint32_t*)&KTH[(n0 + lr) * 72 + kc + 8];
            bl[0] = *(const uint32_t*)&KTL[(n0 + lr) * 72 + kc];
            bl[1] = *(const uint32_t*)&KTL[(n0 + lr) * 72 + kc + 8];
#pragma unroll
            for (int mt = 0; mt < 2; mt++) {
                mma16816(c[mt], qah[ks][mt], bh);
                mma16816(c[mt], qah[ks][mt], bl);
                mma16816(c[mt], qal[ks][mt], bh);
            }
        }
        // epilogue: rel bias + mask -> sc
#pragma unroll
        for (int mt = 0; mt < 2; mt++) {
#pragma unroll
            for (int half = 0; half < 2; half++) {
                int qi = mt * 16 + lr + half * 8;
                int qg = qb + qi;
                int kg = kb * 64 + n0 + lc * 2;
                float v0 = c[mt][half * 2 + 0];
                float v1 = c[mt][half * 2 + 1];
                int d0 = min(MAXK, max(-MAXK, kg - qg)) + MAXK;
                int d1 = min(MAXK, max(-MAXK, kg + 1 - qg)) + MAXK;
                v0 = msk[kg] ? v0 + rb[qi * 12 + d0] : -INFINITY;
                v1 = msk[kg + 1] ? v1 + rb[qi * 12 + d1] : -INFINITY;
                *(float2*)&sc[qi * S_LEN + kg] = make_float2(v0, v1);
            }
        }
    }
    __syncthreads();

    // ---- softmax: warp w handles rows w*4 .. w*4+3 ----
#pragma unroll
    for (int r = 0; r < 4; r++) {
        int qi = w * 4 + r;
        int qg = qb + qi;
        float* row = sc + qi * S_LEN;

        float m = -INFINITY;
        for (int k2 = lane; k2 < S_LEN; k2 += 32) m = fmaxf(m, row[k2]);
#pragma unroll
        for (int o = 16; o; o >>= 1) m = fmaxf(m, __shfl_xor_sync(0xFFFFFFFFu, m, o));

        float sum = 0.f;
        for (int k2 = lane; k2 < S_LEN; k2 += 32) {
            float e = __expf(row[k2] - m);
            row[k2] = e;
            sum += e;
        }
#pragma unroll
        for (int o = 16; o; o >>= 1) sum += __shfl_xor_sync(0xFFFFFFFFu, sum, o);
        float inv = 1.f / sum;

        float* ao = attn_out ? attn_out + ((size_t)(b * NHEAD + h) * S_LEN + qg) * S_LEN
                             : (float*)0;
        float w0 = 0.f, w8 = 0.f;
        for (int k2 = lane; k2 < S_LEN; k2 += 32) {
            float p = row[k2] * inv;
            row[k2] = p;
            if (ao) ao[k2] = p;
            if (k2 <= qg - MAXK) w0 += p;
            if (k2 >= qg + MAXK) w8 += p;
        }
#pragma unroll
        for (int o = 16; o; o >>= 1) {
            w0 += __shfl_xor_sync(0xFFFFFFFFu, w0, o);
            w8 += __shfl_xor_sync(0xFFFFFFFFu, w8, o);
        }
        __syncwarp();
        if (lane == 0) { ws[qi * 12 + 0] = w0; ws[qi * 12 + 8] = w8; }
        if (lane >= 1 && lane <= 7) {
            int k2 = qg + lane - MAXK;
            ws[qi * 12 + lane] = (k2 >= 0 && k2 < S_LEN) ? row[k2] : 0.f;
        }
        __syncwarp();

        // ---- in-place convert this row to phi/plo (swizzled) ----
        float x[32];
        const float4* src = (const float4*)(row + lane * 32);
#pragma unroll
        for (int t = 0; t < 8; t++) {
            float4 v = src[t];
            x[t * 4 + 0] = v.x; x[t * 4 + 1] = v.y;
            x[t * 4 + 2] = v.z; x[t * 4 + 3] = v.w;
        }
        __syncwarp();
        uint32_t swz = (uint32_t)((qi & 7) << 4);
        char* rowb = smem + qi * 4096;
#pragma unroll
        for (int jj = 0; jj < 16; jj++) {
            int j = lane * 16 + jj;
            float a = x[jj * 2], bb = x[jj * 2 + 1];
            uint32_t hi = pack_bf16(a, bb);
            __nv_bfloat162 h2 = *(__nv_bfloat162*)&hi;
            uint32_t lo = pack_bf16(a - __bfloat162float(h2.x),
                                    bb - __bfloat162float(h2.y));
            *(uint32_t*)(rowb + (((uint32_t)(4 * j)) ^ swz)) = hi;
            *(uint32_t*)(rowb + 2048 + (((uint32_t)(4 * j)) ^ swz)) = lo;
        }
    }
    __syncthreads();

    // ---- PV: o = P @ V (split-precision HMMA) ----
    float o[2][4] = {{0.f,0.f,0.f,0.f},{0.f,0.f,0.f,0.f}};
    for (int vb = 0; vb < 16; vb++) {
        __syncthreads();
        // load V tile transposed: vt[d][s], reuse KTH/KTL
#pragma unroll
        for (int i = 0; i < 2; i++) {
            int idx = tid + i * 256;
            int s = idx & 63, dg = idx >> 6;
            size_t g = (size_t)(b * S_LEN + vb * 64 + s) * DMODEL + h * DHEAD + dg * 8;
            uint4 vh4 = *(const uint4*)&vh[g];
            uint4 vl4 = *(const uint4*)&vl[g];
            const __nv_bfloat16* eh = (const __nv_bfloat16*)&vh4;
            const __nv_bfloat16* el = (const __nv_bfloat16*)&vl4;
#pragma unroll
            for (int t = 0; t < 8; t++) {
                KTH[(dg * 8 + t) * 72 + s] = eh[t];
                KTL[(dg * 8 + t) * 72 + s] = el[t];
            }
        }
        __syncthreads();

#pragma unroll
        for (int ks = 0; ks < 4; ks++) {
            int kc = ks * 16 + lc * 2;
            uint32_t bh[2], bl[2];
            bh[0] = *(const uint32_t*)&KTH[(n0 + lr) * 72 + kc];
            bh[1] = *(const uint32_t*)&KTH[(n0 + lr) * 72 + kc + 8];
            bl[0] = *(const uint32_t*)&KTL[(n0 + lr) * 72 + kc];
            bl[1] = *(const uint32_t*)&KTL[(n0 + lr) * 72 + kc + 8];
            int jb = vb * 32 + ks * 8 + lc;   // pair index
#pragma unroll
            for (int mt = 0; mt < 2; mt++) {
                int r0 = mt * 16 + lr;
                int r1 = r0 + 8;
                uint32_t s0 = (uint32_t)((r0 & 7) << 4);
                uint32_t s1 = (uint32_t)((r1 & 7) << 4);
                char* rb0 = smem + r0 * 4096;
                char* rb1 = smem + r1 * 4096;
                uint32_t ah[4], al[4];
                ah[0] = *(uint32_t*)(rb0 + (((uint32_t)(4 * jb)) ^ s0));
                ah[1] = *(uint32_t*)(rb1 + (((uint32_t)(4 * jb)) ^ s1));
                ah[2] = *(uint32_t*)(rb0 + (((uint32_t)(4 * (jb + 4))) ^ s0));
                ah[3] = *(uint32_t*)(rb1 + (((uint32_t)(4 * (jb + 4))) ^ s1));
                al[0] = *(uint32_t*)(rb0 + 2048 + (((uint32_t)(4 * jb)) ^ s0));
                al[1] = *(uint32_t*)(rb1 + 2048 + (((uint32_t)(4 * jb)) ^ s1));
                al[2] = *(uint32_t*)(rb0 + 2048 + (((uint32_t)(4 * (jb + 4))) ^ s0));
                al[3] = *(uint32_t*)(rb1 + 2048 + (((uint32_t)(4 * (jb + 4))) ^ s1));
                mma16816(o[mt], ah, bh);
                mma16816(o[mt], ah, bl);
                mma16816(o[mt], al, bh);
            }
        }
    }

    // ---- epilogue: rel_v + write O (bf16 hi/lo) ----
#pragma unroll
    for (int mt = 0; mt < 2; mt++) {
#pragma unroll
        for (int half = 0; half < 2; half++) {
            int qi = mt * 16 + lr + half * 8;
            int d0 = n0 + lc * 2;
            float a0 = o[mt][half * 2 + 0];
            float a1 = o[mt][half * 2 + 1];
#pragma unroll
            for (int j = 0; j < 9; j++) {
                float wv = ws[qi * 12 + j];
                a0 += wv * pev[j * 64 + d0];
                a1 += wv * pev[j * 64 + d0 + 1];
            }
            size_t base = (size_t)(b * S_LEN + qb + qi) * DMODEL + h * DHEAD + d0;
            uint32_t hi = pack_bf16(a0, a1);
            __nv_bfloat162 h2 = *(__nv_bfloat162*)&hi;
            uint32_t lo = pack_bf16(a0 - __bfloat162float(h2.x),
                                    a1 - __bfloat162float(h2.y));
            *(uint32_t*)&Oh[base] = hi;
            *(uint32_t*)&Ol[base] = lo;
        }
    }
}

// ---------------------------------------------------------------------------
extern "C" void kernel_launch(void* const* d_in, const int* in_sizes, int n_in,
                              void* d_out, int out_size)
{
    const float* query = (const float*)d_in[0];
    const float* key   = (const float*)d_in[1];
    const float* value = (const float*)d_in[2];
    const int*   mask  = (const int*)d_in[3];
    const float* Wq = (const float*)d_in[4];
    const float* bq = (const float*)d_in[5];
    const float* Wk = (const float*)d_in[6];
    const float* bk = (const float*)d_in[7];
    const float* Wv = (const float*)d_in[8];
    const float* bv = (const float*)d_in[9];
    const float* Wo = (const float*)d_in[10];
    const float* bo = (const float*)d_in[11];
    const float* pe_k = (const float*)d_in[12];
    const float* pe_v = (const float*)d_in[13];

    __nv_bfloat16 *ahi, *alo, *whi, *wlo, *qh, *ql, *kh, *kl, *vh, *vl, *oh, *ol;
    cudaGetSymbolAddress((void**)&ahi, g_act_hi);
    cudaGetSymbolAddress((void**)&alo, g_act_lo);
    cudaGetSymbolAddress((void**)&whi, g_w_hi);
    cudaGetSymbolAddress((void**)&wlo, g_w_lo);
    cudaGetSymbolAddress((void**)&qh, g_qh);
    cudaGetSymbolAddress((void**)&ql, g_ql);
    cudaGetSymbolAddress((void**)&kh, g_kh);
    cudaGetSymbolAddress((void**)&kl, g_kl);
    cudaGetSymbolAddress((void**)&vh, g_vh);
    cudaGetSymbolAddress((void**)&vl, g_vl);
    cudaGetSymbolAddress((void**)&oh, g_oh);
    cudaGetSymbolAddress((void**)&ol, g_ol);

    const long long OUT_ELEMS = (long long)BATCH * S_LEN * DMODEL;
    float* out_ptr  = (float*)d_out;
    float* attn_ptr = ((long long)out_size > OUT_ELEMS) ? (float*)d_out + OUT_ELEMS
                                                        : (float*)0;

    cudaFuncSetAttribute(attn_mma, cudaFuncAttributeMaxDynamicSharedMemorySize,
                         ATT_SMEM);

    const int ACT4 = MROWS * DMODEL / 4;
    const int W4   = DMODEL * DMODEL / 4;
    dim3 gg(DMODEL / 128, MROWS / 128);

    // Q projection (fold 1/SCALE = 0.125), bf16 hi/lo output only
    split_bf16_kernel<<<ACT4 / 256, 256>>>(query, ahi, alo, ACT4);
    split_bf16_kernel<<<W4 / 256, 256>>>(Wq, whi, wlo, W4);
    gemm_mma<<<gg, 256>>>(ahi, alo, whi, wlo, bq, (float*)0, qh, ql, 0.125f);
    // K projection
    split_bf16_kernel<<<ACT4 / 256, 256>>>(key, ahi, alo, ACT4);
    split_bf16_kernel<<<W4 / 256, 256>>>(Wk, whi, wlo, W4);
    gemm_mma<<<gg, 256>>>(ahi, alo, whi, wlo, bk, (float*)0, kh, kl, 1.0f);
    // V projection
    split_bf16_kernel<<<ACT4 / 256, 256>>>(value, ahi, alo, ACT4);
    split_bf16_kernel<<<W4 / 256, 256>>>(Wv, whi, wlo, W4);
    gemm_mma<<<gg, 256>>>(ahi, alo, whi, wlo, bv, (float*)0, vh, vl, 1.0f);

    // fused attention (writes O as bf16 hi/lo directly)
    dim3 ga(S_LEN / QT, NHEAD, BATCH);
    attn_mma<<<ga, 256, ATT_SMEM>>>(qh, ql, kh, kl, vh, vl, mask, pe_k, pe_v,
                                    attn_ptr, oh, ol);

    // output projection (fp32 out)
    split_bf16_kernel<<<W4 / 256, 256>>>(Wo, whi, wlo, W4);
    gemm_mma<<<gg, 256>>>(oh, ol, whi, wlo, bo, out_ptr,
                          (__nv_bfloat16*)0, (__nv_bfloat16*)0, 1.0f);
}

// round 6
// speedup vs baseline: 1.8315x; 1.0447x over previous
#include <cuda_runtime.h>
#include <cuda_bf16.h>
#include <math.h>
#include <cstdint>

#define BATCH 8
#define S_LEN 1024
#define DMODEL 1024
#define NHEAD 16
#define DHEAD 64
#define MAXK 4
#define MROWS (BATCH * S_LEN)   // 8192

// Scratch (allocation-free rule -> device globals)
__device__ __nv_bfloat16 g_act_hi[(size_t)MROWS * DMODEL];
__device__ __nv_bfloat16 g_act_lo[(size_t)MROWS * DMODEL];
__device__ __nv_bfloat16 g_w_hi[(size_t)DMODEL * DMODEL];
__device__ __nv_bfloat16 g_w_lo[(size_t)DMODEL * DMODEL];
__device__ __nv_bfloat16 g_qh[(size_t)MROWS * DMODEL];
__device__ __nv_bfloat16 g_ql[(size_t)MROWS * DMODEL];
__device__ __nv_bfloat16 g_kh[(size_t)MROWS * DMODEL];
__device__ __nv_bfloat16 g_kl[(size_t)MROWS * DMODEL];
__device__ __nv_bfloat16 g_vh[(size_t)MROWS * DMODEL];
__device__ __nv_bfloat16 g_vl[(size_t)MROWS * DMODEL];
__device__ __nv_bfloat16 g_oh[(size_t)MROWS * DMODEL];
__device__ __nv_bfloat16 g_ol[(size_t)MROWS * DMODEL];

// ---------------------------------------------------------------------------
__device__ __forceinline__ void mma16816(float* c, const uint32_t* a, const uint32_t* b) {
    asm volatile(
        "mma.sync.aligned.m16n8k16.row.col.f32.bf16.bf16.f32 "
        "{%0,%1,%2,%3}, {%4,%5,%6,%7}, {%8,%9}, {%0,%1,%2,%3};"
        : "+f"(c[0]), "+f"(c[1]), "+f"(c[2]), "+f"(c[3])
        : "r"(a[0]), "r"(a[1]), "r"(a[2]), "r"(a[3]), "r"(b[0]), "r"(b[1]));
}
__device__ __forceinline__ uint32_t pack_bf16(float x, float y) {
    __nv_bfloat162 t = __halves2bfloat162(__float2bfloat16(x), __float2bfloat16(y));
    return *(uint32_t*)&t;
}
__device__ __forceinline__ uint32_t smem_u32(const void* p) {
    uint32_t a;
    asm("{ .reg .u64 t; cvta.to.shared.u64 t, %1; cvt.u32.u64 %0, t; }"
        : "=r"(a) : "l"(p));
    return a;
}
__device__ __forceinline__ void ldmx4(uint32_t* r, uint32_t addr) {
    asm volatile("ldmatrix.sync.aligned.m8n8.x4.shared.b16 {%0,%1,%2,%3}, [%4];"
        : "=r"(r[0]), "=r"(r[1]), "=r"(r[2]), "=r"(r[3]) : "r"(addr));
}
__device__ __forceinline__ void cp_async16(uint32_t d, const void* s) {
    asm volatile("cp.async.cg.shared.global [%0], [%1], 16;" :: "r"(d), "l"(s));
}
#define CP_COMMIT asm volatile("cp.async.commit_group;" ::: "memory")
#define CP_WAIT1  asm volatile("cp.async.wait_group 1;" ::: "memory")

// ---------------------------------------------------------------------------
// fp32 -> (bf16 hi, bf16 lo) split
// ---------------------------------------------------------------------------
__global__ void split_bf16_kernel(const float* __restrict__ x,
                                  __nv_bfloat16* __restrict__ hi,
                                  __nv_bfloat16* __restrict__ lo, int n4)
{
    int i = blockIdx.x * blockDim.x + threadIdx.x;
    if (i >= n4) return;
    float4 v = ((const float4*)x)[i];
    __nv_bfloat16 h0 = __float2bfloat16(v.x);
    __nv_bfloat16 h1 = __float2bfloat16(v.y);
    __nv_bfloat16 h2 = __float2bfloat16(v.z);
    __nv_bfloat16 h3 = __float2bfloat16(v.w);
    __nv_bfloat16 l0 = __float2bfloat16(v.x - __bfloat162float(h0));
    __nv_bfloat16 l1 = __float2bfloat16(v.y - __bfloat162float(h1));
    __nv_bfloat16 l2 = __float2bfloat16(v.z - __bfloat162float(h2));
    __nv_bfloat16 l3 = __float2bfloat16(v.w - __bfloat162float(h3));
    __nv_bfloat162* h2p = (__nv_bfloat162*)hi;
    __nv_bfloat162* l2p = (__nv_bfloat162*)lo;
    h2p[i * 2 + 0] = __halves2bfloat162(h0, h1);
    h2p[i * 2 + 1] = __halves2bfloat162(h2, h3);
    l2p[i * 2 + 0] = __halves2bfloat162(l0, l1);
    l2p[i * 2 + 1] = __halves2bfloat162(l2, l3);
}

// ---------------------------------------------------------------------------
// Pipelined HMMA GEMM: out = alpha * (A @ W^T + bias)
// cp.async 2-stage double buffer + non-trans ldmatrix fragments (both A and W
// are stored outer-major with contiguous k).
// Tile 128x128, BK=32, 8 warps (2M x 4N). 3-pass split precision.
// ---------------------------------------------------------------------------
#define LDT 40                       // bf16 elems per row (32 data + 8 pad)
#define TILE_B (128 * LDT * 2)       // 10240 bytes per tile
#define STAGE_B (4 * TILE_B)         // 40960 bytes per stage
#define GEMM_SMEM (2 * STAGE_B)      // 81920

__global__ __launch_bounds__(256, 2)
void gemm_mma(const __nv_bfloat16* __restrict__ Ahi, const __nv_bfloat16* __restrict__ Alo,
              const __nv_bfloat16* __restrict__ Whi, const __nv_bfloat16* __restrict__ Wlo,
              const float* __restrict__ bias, float* __restrict__ C,
              __nv_bfloat16* __restrict__ Chi, __nv_bfloat16* __restrict__ Clo,
              float alpha)
{
    extern __shared__ char smem[];
    const uint32_t sb = smem_u32(smem);

    const int tid = threadIdx.x;
    const int wid = tid >> 5;
    const int lane = tid & 31;
    const int wm = wid >> 2;
    const int wn = wid & 3;
    const int m0 = blockIdx.y * 128;
    const int n0 = blockIdx.x * 128;

    float acc[4][4][4];
#pragma unroll
    for (int i = 0; i < 4; i++)
#pragma unroll
        for (int j = 0; j < 4; j++)
#pragma unroll
            for (int k = 0; k < 4; k++) acc[i][j][k] = 0.f;

    const int lr = lane >> 2;
    const int lc = lane & 3;

    const int r0i = tid >> 2, c0i = tid & 3;
    const int r1i = (tid + 256) >> 2, c1i = tid & 3;

    // ldmatrix per-thread address parts (non-trans quads)
    // A x4: m0=(rows 0-7,k0-7) m1=(rows 8-15,k0-7) m2=(rows 0-7,k8-15) m3=(rows 8-15,k8-15)
    const int aRow = wm * 64 + (lane & 15);                       // + mi*16
    const int aColB = ((lane >> 4) << 3) * 2;                     // + ks*32 bytes
    // W x4: m0=(n 0-7,k0-7) m1=(n 0-7,k8-15) m2=(n 8-15,k0-7) m3=(n 8-15,k8-15)
    const int bRow = wn * 32 + ((lane >> 4) << 3) + (lane & 7);   // + nip*16
    const int bColB = (((lane >> 3) & 1) << 3) * 2;               // + ks*32 bytes

#define ISSUE(K0, ST) do {                                                     \
    uint32_t sd = sb + (ST) * STAGE_B;                                         \
    size_t g0 = (size_t)(m0 + r0i) * DMODEL + (K0) + c0i * 8;                  \
    size_t g1 = (size_t)(m0 + r1i) * DMODEL + (K0) + c1i * 8;                  \
    size_t h0 = (size_t)(n0 + r0i) * DMODEL + (K0) + c0i * 8;                  \
    size_t h1 = (size_t)(n0 + r1i) * DMODEL + (K0) + c1i * 8;                  \
    uint32_t d0 = r0i * (LDT * 2) + c0i * 16;                                  \
    uint32_t d1 = r1i * (LDT * 2) + c1i * 16;                                  \
    cp_async16(sd + 0 * TILE_B + d0, Ahi + g0);                                \
    cp_async16(sd + 0 * TILE_B + d1, Ahi + g1);                                \
    cp_async16(sd + 1 * TILE_B + d0, Alo + g0);                                \
    cp_async16(sd + 1 * TILE_B + d1, Alo + g1);                                \
    cp_async16(sd + 2 * TILE_B + d0, Whi + h0);                                \
    cp_async16(sd + 2 * TILE_B + d1, Whi + h1);                                \
    cp_async16(sd + 3 * TILE_B + d0, Wlo + h0);                                \
    cp_async16(sd + 3 * TILE_B + d1, Wlo + h1);                                \
} while (0)

    ISSUE(0, 0);
    CP_COMMIT;

    for (int it = 0; it < DMODEL / 32; it++) {
        if (it + 1 < DMODEL / 32) ISSUE((it + 1) * 32, (it + 1) & 1);
        CP_COMMIT;
        CP_WAIT1;
        __syncthreads();

        const uint32_t st = sb + (it & 1) * STAGE_B;
        const uint32_t aHiB = st + 0 * TILE_B;
        const uint32_t aLoB = st + 1 * TILE_B;
        const uint32_t wHiB = st + 2 * TILE_B;
        const uint32_t wLoB = st + 3 * TILE_B;

#pragma unroll
        for (int ks = 0; ks < 2; ks++) {
            const uint32_t acol = ks * 32 + aColB;
            const uint32_t bcol = ks * 32 + bColB;

            uint32_t bh[2][4], bl[2][4];
#pragma unroll
            for (int nip = 0; nip < 2; nip++) {
                uint32_t boff = (uint32_t)(bRow + nip * 16) * (LDT * 2) + bcol;
                ldmx4(bh[nip], wHiB + boff);
                ldmx4(bl[nip], wLoB + boff);
            }
#pragma unroll
            for (int mi = 0; mi < 4; mi++) {
                uint32_t aoff = (uint32_t)(aRow + mi * 16) * (LDT * 2) + acol;
                uint32_t a[4];
                ldmx4(a, aHiB + aoff);
#pragma unroll
                for (int nip = 0; nip < 2; nip++) {
                    mma16816(acc[mi][2 * nip + 0], a, &bh[nip][0]);
                    mma16816(acc[mi][2 * nip + 1], a, &bh[nip][2]);
                    mma16816(acc[mi][2 * nip + 0], a, &bl[nip][0]);
                    mma16816(acc[mi][2 * nip + 1], a, &bl[nip][2]);
                }
                ldmx4(a, aLoB + aoff);
#pragma unroll
                for (int nip = 0; nip < 2; nip++) {
                    mma16816(acc[mi][2 * nip + 0], a, &bh[nip][0]);
                    mma16816(acc[mi][2 * nip + 1], a, &bh[nip][2]);
                }
            }
        }
        __syncthreads();
    }
#undef ISSUE

    // epilogue
#pragma unroll
    for (int mi = 0; mi < 4; mi++) {
        int row = m0 + wm * 64 + mi * 16 + lr;
#pragma unroll
        for (int ni = 0; ni < 4; ni++) {
            int col = n0 + wn * 32 + ni * 8 + lc * 2;
            float2 b2 = *(const float2*)&bias[col];
            float v0x = alpha * (acc[mi][ni][0] + b2.x);
            float v0y = alpha * (acc[mi][ni][1] + b2.y);
            float v1x = alpha * (acc[mi][ni][2] + b2.x);
            float v1y = alpha * (acc[mi][ni][3] + b2.y);
            size_t p0 = (size_t)row * DMODEL + col;
            size_t p1 = (size_t)(row + 8) * DMODEL + col;
            if (C) {
                *(float2*)&C[p0] = make_float2(v0x, v0y);
                *(float2*)&C[p1] = make_float2(v1x, v1y);
            }
            if (Chi) {
                uint32_t h0 = pack_bf16(v0x, v0y);
                uint32_t h1 = pack_bf16(v1x, v1y);
                *(uint32_t*)&Chi[p0] = h0;
                *(uint32_t*)&Chi[p1] = h1;
                __nv_bfloat162 hh0 = *(__nv_bfloat162*)&h0;
                __nv_bfloat162 hh1 = *(__nv_bfloat162*)&h1;
                *(uint32_t*)&Clo[p0] = pack_bf16(v0x - __bfloat162float(hh0.x),
                                                 v0y - __bfloat162float(hh0.y));
                *(uint32_t*)&Clo[p1] = pack_bf16(v1x - __bfloat162float(hh1.x),
                                                 v1y - __bfloat162float(hh1.y));
            }
        }
    }
}

// ---------------------------------------------------------------------------
// Fused HMMA attention (unchanged from R4). Block = (b, h, 32-row q tile).
// ---------------------------------------------------------------------------
#define QT 32
#define O_SC   0
#define O_QH   131072
#define O_QL   (O_QH + 4608)
#define O_KTH  140288
#define O_KTL  (O_KTH + 9216)
#define O_PEK  158720
#define O_PEV  (O_PEK + 2304)
#define O_RB   163328
#define O_WS   (O_RB + 1536)
#define O_MSK  166400
#define ATT_SMEM 170496

__global__ __launch_bounds__(256)
void attn_mma(const __nv_bfloat16* __restrict__ qh, const __nv_bfloat16* __restrict__ ql,
              const __nv_bfloat16* __restrict__ kh, const __nv_bfloat16* __restrict__ kl,
              const __nv_bfloat16* __restrict__ vh, const __nv_bfloat16* __restrict__ vl,
              const int* __restrict__ mask, const float* __restrict__ pe_k,
              const float* __restrict__ pe_v, float* __restrict__ attn_out,
              __nv_bfloat16* __restrict__ Oh, __nv_bfloat16* __restrict__ Ol)
{
    extern __shared__ char smem[];
    float* sc = (float*)(smem + O_SC);
    __nv_bfloat16* QH = (__nv_bfloat16*)(smem + O_QH);
    __nv_bfloat16* QL = (__nv_bfloat16*)(smem + O_QL);
    __nv_bfloat16* KTH = (__nv_bfloat16*)(smem + O_KTH);
    __nv_bfloat16* KTL = (__nv_bfloat16*)(smem + O_KTL);
    float* pek = (float*)(smem + O_PEK);
    float* pev = (float*)(smem + O_PEV);
    float* rb  = (float*)(smem + O_RB);
    float* ws  = (float*)(smem + O_WS);
    int*   msk = (int*)(smem + O_MSK);

    const int b  = blockIdx.z;
    const int h  = blockIdx.y;
    const int qb = blockIdx.x * QT;
    const int tid = threadIdx.x;
    const int w = tid >> 5;
    const int lane = tid & 31;
    const int lr = lane >> 2;
    const int lc = lane & 3;
    const int n0 = w * 8;

    {
        int row = tid >> 3, dg = tid & 7;
        size_t g = (size_t)(b * S_LEN + qb + row) * DMODEL + h * DHEAD + dg * 8;
        *(uint4*)&QH[row * 72 + dg * 8] = *(const uint4*)&qh[g];
        *(uint4*)&QL[row * 72 + dg * 8] = *(const uint4*)&ql[g];
    }
    for (int i = tid; i < 576; i += 256) { pek[i] = pe_k[i]; pev[i] = pe_v[i]; }
    for (int i = tid; i < S_LEN; i += 256) msk[i] = mask[b * S_LEN + i];
    __syncthreads();

    for (int i = tid; i < QT * 9; i += 256) {
        int qi = i / 9, j = i % 9;
        float s = 0.f;
        const __nv_bfloat16* qhr = QH + qi * 72;
        const __nv_bfloat16* qlr = QL + qi * 72;
        const float* pr = pek + j * 64;
#pragma unroll 16
        for (int d = 0; d < 64; d++)
            s += (__bfloat162float(qhr[d]) + __bfloat162float(qlr[d])) * pr[d];
        rb[qi * 12 + j] = s;
    }

    uint32_t qah[4][2][4], qal[4][2][4];
#pragma unroll
    for (int ks = 0; ks < 4; ks++)
#pragma unroll
        for (int mt = 0; mt < 2; mt++) {
            int r = mt * 16 + lr;
            int kc = ks * 16 + lc * 2;
            qah[ks][mt][0] = *(const uint32_t*)&QH[r * 72 + kc];
            qah[ks][mt][1] = *(const uint32_t*)&QH[(r + 8) * 72 + kc];
            qah[ks][mt][2] = *(const uint32_t*)&QH[r * 72 + kc + 8];
            qah[ks][mt][3] = *(const uint32_t*)&QH[(r + 8) * 72 + kc + 8];
            qal[ks][mt][0] = *(const uint32_t*)&QL[r * 72 + kc];
            qal[ks][mt][1] = *(const uint32_t*)&QL[(r + 8) * 72 + kc];
            qal[ks][mt][2] = *(const uint32_t*)&QL[r * 72 + kc + 8];
            qal[ks][mt][3] = *(const uint32_t*)&QL[(r + 8) * 72 + kc + 8];
        }

    for (int kb = 0; kb < 16; kb++) {
        __syncthreads();
#pragma unroll
        for (int i = 0; i < 2; i++) {
            int idx = tid + i * 256;
            int r = idx >> 3, dg = idx & 7;
            size_t g = (size_t)(b * S_LEN + kb * 64 + r) * DMODEL + h * DHEAD + dg * 8;
            *(uint4*)&KTH[r * 72 + dg * 8] = *(const uint4*)&kh[g];
            *(uint4*)&KTL[r * 72 + dg * 8] = *(const uint4*)&kl[g];
        }
        __syncthreads();

        float c[2][4] = {{0.f,0.f,0.f,0.f},{0.f,0.f,0.f,0.f}};
#pragma unroll
        for (int ks = 0; ks < 4; ks++) {
            int kc = ks * 16 + lc * 2;
            uint32_t bh[2], bl[2];
            bh[0] = *(const uint32_t*)&KTH[(n0 + lr) * 72 + kc];
            bh[1] = *(const uint32_t*)&KTH[(n0 + lr) * 72 + kc + 8];
            bl[0] = *(const uint32_t*)&KTL[(n0 + lr) * 72 + kc];
            bl[1] = *(const uint32_t*)&KTL[(n0 + lr) * 72 + kc + 8];
#pragma unroll
            for (int mt = 0; mt < 2; mt++) {
                mma16816(c[mt], qah[ks][mt], bh);
                mma16816(c[mt], qah[ks][mt], bl);
                mma16816(c[mt], qal[ks][mt], bh);
            }
        }
#pragma unroll
        for (int mt = 0; mt < 2; mt++) {
#pragma unroll
            for (int half = 0; half < 2; half++) {
                int qi = mt * 16 + lr + half * 8;
                int qg = qb + qi;
                int kg = kb * 64 + n0 + lc * 2;
                float v0 = c[mt][half * 2 + 0];
                float v1 = c[mt][half * 2 + 1];
                int d0 = min(MAXK, max(-MAXK, kg - qg)) + MAXK;
                int d1 = min(MAXK, max(-MAXK, kg + 1 - qg)) + MAXK;
                v0 = msk[kg] ? v0 + rb[qi * 12 + d0] : -INFINITY;
                v1 = msk[kg + 1] ? v1 + rb[qi * 12 + d1] : -INFINITY;
                *(float2*)&sc[qi * S_LEN + kg] = make_float2(v0, v1);
            }
        }
    }
    __syncthreads();

#pragma unroll
    for (int r = 0; r < 4; r++) {
        int qi = w * 4 + r;
        int qg = qb + qi;
        float* row = sc + qi * S_LEN;

        float m = -INFINITY;
        for (int k2 = lane; k2 < S_LEN; k2 += 32) m = fmaxf(m, row[k2]);
#pragma unroll
        for (int o = 16; o; o >>= 1) m = fmaxf(m, __shfl_xor_sync(0xFFFFFFFFu, m, o));

        float sum = 0.f;
        for (int k2 = lane; k2 < S_LEN; k2 += 32) {
            float e = __expf(row[k2] - m);
            row[k2] = e;
            sum += e;
        }
#pragma unroll
        for (int o = 16; o; o >>= 1) sum += __shfl_xor_sync(0xFFFFFFFFu, sum, o);
        float inv = 1.f / sum;

        float* ao = attn_out ? attn_out + ((size_t)(b * NHEAD + h) * S_LEN + qg) * S_LEN
                             : (float*)0;
        float w0 = 0.f, w8 = 0.f;
        for (int k2 = lane; k2 < S_LEN; k2 += 32) {
            float p = row[k2] * inv;
            row[k2] = p;
            if (ao) ao[k2] = p;
            if (k2 <= qg - MAXK) w0 += p;
            if (k2 >= qg + MAXK) w8 += p;
        }
#pragma unroll
        for (int o = 16; o; o >>= 1) {
            w0 += __shfl_xor_sync(0xFFFFFFFFu, w0, o);
            w8 += __shfl_xor_sync(0xFFFFFFFFu, w8, o);
        }
        __syncwarp();
        if (lane == 0) { ws[qi * 12 + 0] = w0; ws[qi * 12 + 8] = w8; }
        if (lane >= 1 && lane <= 7) {
            int k2 = qg + lane - MAXK;
            ws[qi * 12 + lane] = (k2 >= 0 && k2 < S_LEN) ? row[k2] : 0.f;
        }
        __syncwarp();

        float x[32];
        const float4* src = (const float4*)(row + lane * 32);
#pragma unroll
        for (int t = 0; t < 8; t++) {
            float4 v = src[t];
            x[t * 4 + 0] = v.x; x[t * 4 + 1] = v.y;
            x[t * 4 + 2] = v.z; x[t * 4 + 3] = v.w;
        }
        __syncwarp();
        uint32_t swz = (uint32_t)((qi & 7) << 4);
        char* rowb = smem + qi * 4096;
#pragma unroll
        for (int jj = 0; jj < 16; jj++) {
            int j = lane * 16 + jj;
            float a = x[jj * 2], bb = x[jj * 2 + 1];
            uint32_t hi = pack_bf16(a, bb);
            __nv_bfloat162 h2 = *(__nv_bfloat162*)&hi;
            uint32_t lo = pack_bf16(a - __bfloat162float(h2.x),
                                    bb - __bfloat162float(h2.y));
            *(uint32_t*)(rowb + (((uint32_t)(4 * j)) ^ swz)) = hi;
            *(uint32_t*)(rowb + 2048 + (((uint32_t)(4 * j)) ^ swz)) = lo;
        }
    }
    __syncthreads();

    float o[2][4] = {{0.f,0.f,0.f,0.f},{0.f,0.f,0.f,0.f}};
    for (int vb = 0; vb < 16; vb++) {
        __syncthreads();
#pragma unroll
        for (int i = 0; i < 2; i++) {
            int idx = tid + i * 256;
            int s = idx & 63, dg = idx >> 6;
            size_t g = (size_t)(b * S_LEN + vb * 64 + s) * DMODEL + h * DHEAD + dg * 8;
            uint4 vh4 = *(const uint4*)&vh[g];
            uint4 vl4 = *(const uint4*)&vl[g];
            const __nv_bfloat16* eh = (const __nv_bfloat16*)&vh4;
            const __nv_bfloat16* el = (const __nv_bfloat16*)&vl4;
#pragma unroll
            for (int t = 0; t < 8; t++) {
                KTH[(dg * 8 + t) * 72 + s] = eh[t];
                KTL[(dg * 8 + t) * 72 + s] = el[t];
            }
        }
        __syncthreads();

#pragma unroll
        for (int ks = 0; ks < 4; ks++) {
            int kc = ks * 16 + lc * 2;
            uint32_t bh[2], bl[2];
            bh[0] = *(const uint32_t*)&KTH[(n0 + lr) * 72 + kc];
            bh[1] = *(const uint32_t*)&KTH[(n0 + lr) * 72 + kc + 8];
            bl[0] = *(const uint32_t*)&KTL[(n0 + lr) * 72 + kc];
            bl[1] = *(const uint32_t*)&KTL[(n0 + lr) * 72 + kc + 8];
            int jb = vb * 32 + ks * 8 + lc;
#pragma unroll
            for (int mt = 0; mt < 2; mt++) {
                int r0 = mt * 16 + lr;
                int r1 = r0 + 8;
                uint32_t s0 = (uint32_t)((r0 & 7) << 4);
                uint32_t s1 = (uint32_t)((r1 & 7) << 4);
                char* rb0 = smem + r0 * 4096;
                char* rb1 = smem + r1 * 4096;
                uint32_t ah[4], al[4];
                ah[0] = *(uint32_t*)(rb0 + (((uint32_t)(4 * jb)) ^ s0));
                ah[1] = *(uint32_t*)(rb1 + (((uint32_t)(4 * jb)) ^ s1));
                ah[2] = *(uint32_t*)(rb0 + (((uint32_t)(4 * (jb + 4))) ^ s0));
                ah[3] = *(uint32_t*)(rb1 + (((uint32_t)(4 * (jb + 4))) ^ s1));
                al[0] = *(uint32_t*)(rb0 + 2048 + (((uint32_t)(4 * jb)) ^ s0));
                al[1] = *(uint32_t*)(rb1 + 2048 + (((uint32_t)(4 * jb)) ^ s1));
                al[2] = *(uint32_t*)(rb0 + 2048 + (((uint32_t)(4 * (jb + 4))) ^ s0));
                al[3] = *(uint32_t*)(rb1 + 2048 + (((uint32_t)(4 * (jb + 4))) ^ s1));
                mma16816(o[mt], ah, bh);
                mma16816(o[mt], ah, bl);
                mma16816(o[mt], al, bh);
            }
        }
    }

#pragma unroll
    for (int mt = 0; mt < 2; mt++) {
#pragma unroll
        for (int half = 0; half < 2; half++) {
            int qi = mt * 16 + lr + half * 8;
            int d0 = n0 + lc * 2;
            float a0 = o[mt][half * 2 + 0];
            float a1 = o[mt][half * 2 + 1];
#pragma unroll
            for (int j = 0; j < 9; j++) {
                float wv = ws[qi * 12 + j];
                a0 += wv * pev[j * 64 + d0];
                a1 += wv * pev[j * 64 + d0 + 1];
            }
            size_t base = (size_t)(b * S_LEN + qb + qi) * DMODEL + h * DHEAD + d0;
            uint32_t hi = pack_bf16(a0, a1);
            __nv_bfloat162 h2 = *(__nv_bfloat162*)&hi;
            uint32_t lo = pack_bf16(a0 - __bfloat162float(h2.x),
                                    a1 - __bfloat162float(h2.y));
            *(uint32_t*)&Oh[base] = hi;
            *(uint32_t*)&Ol[base] = lo;
        }
    }
}

// ---------------------------------------------------------------------------
extern "C" void kernel_launch(void* const* d_in, const int* in_sizes, int n_in,
                              void* d_out, int out_size)
{
    const float* query = (const float*)d_in[0];
    const float* key   = (const float*)d_in[1];
    const float* value = (const float*)d_in[2];
    const int*   mask  = (const int*)d_in[3];
    const float* Wq = (const float*)d_in[4];
    const float* bq = (const float*)d_in[5];
    const float* Wk = (const float*)d_in[6];
    const float* bk = (const float*)d_in[7];
    const float* Wv = (const float*)d_in[8];
    const float* bv = (const float*)d_in[9];
    const float* Wo = (const float*)d_in[10];
    const float* bo = (const float*)d_in[11];
    const float* pe_k = (const float*)d_in[12];
    const float* pe_v = (const float*)d_in[13];

    __nv_bfloat16 *ahi, *alo, *whi, *wlo, *qh, *ql, *kh, *kl, *vh, *vl, *oh, *ol;
    cudaGetSymbolAddress((void**)&ahi, g_act_hi);
    cudaGetSymbolAddress((void**)&alo, g_act_lo);
    cudaGetSymbolAddress((void**)&whi, g_w_hi);
    cudaGetSymbolAddress((void**)&wlo, g_w_lo);
    cudaGetSymbolAddress((void**)&qh, g_qh);
    cudaGetSymbolAddress((void**)&ql, g_ql);
    cudaGetSymbolAddress((void**)&kh, g_kh);
    cudaGetSymbolAddress((void**)&kl, g_kl);
    cudaGetSymbolAddress((void**)&vh, g_vh);
    cudaGetSymbolAddress((void**)&vl, g_vl);
    cudaGetSymbolAddress((void**)&oh, g_oh);
    cudaGetSymbolAddress((void**)&ol, g_ol);

    const long long OUT_ELEMS = (long long)BATCH * S_LEN * DMODEL;
    float* out_ptr  = (float*)d_out;
    float* attn_ptr = ((long long)out_size > OUT_ELEMS) ? (float*)d_out + OUT_ELEMS
                                                        : (float*)0;

    cudaFuncSetAttribute(attn_mma, cudaFuncAttributeMaxDynamicSharedMemorySize,
                         ATT_SMEM);
    cudaFuncSetAttribute(gemm_mma, cudaFuncAttributeMaxDynamicSharedMemorySize,
                         GEMM_SMEM);

    const int ACT4 = MROWS * DMODEL / 4;
    const int W4   = DMODEL * DMODEL / 4;
    dim3 gg(DMODEL / 128, MROWS / 128);

    split_bf16_kernel<<<ACT4 / 256, 256>>>(query, ahi, alo, ACT4);
    split_bf16_kernel<<<W4 / 256, 256>>>(Wq, whi, wlo, W4);
    gemm_mma<<<gg, 256, GEMM_SMEM>>>(ahi, alo, whi, wlo, bq, (float*)0, qh, ql, 0.125f);
    split_bf16_kernel<<<ACT4 / 256, 256>>>(key, ahi, alo, ACT4);
    split_bf16_kernel<<<W4 / 256, 256>>>(Wk, whi, wlo, W4);
    gemm_mma<<<gg, 256, GEMM_SMEM>>>(ahi, alo, whi, wlo, bk, (float*)0, kh, kl, 1.0f);
    split_bf16_kernel<<<ACT4 / 256, 256>>>(value, ahi, alo, ACT4);
    split_bf16_kernel<<<W4 / 256, 256>>>(Wv, whi, wlo, W4);
    gemm_mma<<<gg, 256, GEMM_SMEM>>>(ahi, alo, whi, wlo, bv, (float*)0, vh, vl, 1.0f);

    dim3 ga(S_LEN / QT, NHEAD, BATCH);
    attn_mma<<<ga, 256, ATT_SMEM>>>(qh, ql, kh, kl, vh, vl, mask, pe_k, pe_v,
                                    attn_ptr, oh, ol);

    split_bf16_kernel<<<W4 / 256, 256>>>(Wo, whi, wlo, W4);
    gemm_mma<<<gg, 256, GEMM_SMEM>>>(oh, ol, whi, wlo, bo, out_ptr,
                                     (__nv_bfloat16*)0, (__nv_bfloat16*)0, 1.0f);
}

// round 7
// speedup vs baseline: 2.6594x; 1.4520x over previous
#include <cuda_runtime.h>
#include <cuda_bf16.h>
#include <math.h>
#include <cstdint>

#define BATCH 8
#define S_LEN 1024
#define DMODEL 1024
#define NHEAD 16
#define DHEAD 64
#define MAXK 4
#define MROWS (BATCH * S_LEN)   // 8192

// Scratch (allocation-free rule -> device globals)
__device__ __nv_bfloat16 g_act_hi[(size_t)MROWS * DMODEL];
__device__ __nv_bfloat16 g_act_lo[(size_t)MROWS * DMODEL];
__device__ __nv_bfloat16 g_w_hi[(size_t)DMODEL * DMODEL];
__device__ __nv_bfloat16 g_w_lo[(size_t)DMODEL * DMODEL];
__device__ __nv_bfloat16 g_qh[(size_t)MROWS * DMODEL];
__device__ __nv_bfloat16 g_ql[(size_t)MROWS * DMODEL];
__device__ __nv_bfloat16 g_kh[(size_t)MROWS * DMODEL];
__device__ __nv_bfloat16 g_kl[(size_t)MROWS * DMODEL];
__device__ __nv_bfloat16 g_vh[(size_t)MROWS * DMODEL];
__device__ __nv_bfloat16 g_vl[(size_t)MROWS * DMODEL];
__device__ __nv_bfloat16 g_oh[(size_t)MROWS * DMODEL];
__device__ __nv_bfloat16 g_ol[(size_t)MROWS * DMODEL];

// ---------------------------------------------------------------------------
__device__ __forceinline__ void mma16816(float* c, const uint32_t* a, const uint32_t* b) {
    asm volatile(
        "mma.sync.aligned.m16n8k16.row.col.f32.bf16.bf16.f32 "
        "{%0,%1,%2,%3}, {%4,%5,%6,%7}, {%8,%9}, {%0,%1,%2,%3};"
        : "+f"(c[0]), "+f"(c[1]), "+f"(c[2]), "+f"(c[3])
        : "r"(a[0]), "r"(a[1]), "r"(a[2]), "r"(a[3]), "r"(b[0]), "r"(b[1]));
}
__device__ __forceinline__ uint32_t pack_bf16(float x, float y) {
    __nv_bfloat162 t = __halves2bfloat162(__float2bfloat16(x), __float2bfloat16(y));
    return *(uint32_t*)&t;
}
__device__ __forceinline__ uint32_t smem_u32(const void* p) {
    uint32_t a;
    asm("{ .reg .u64 t; cvta.to.shared.u64 t, %1; cvt.u32.u64 %0, t; }"
        : "=r"(a) : "l"(p));
    return a;
}
__device__ __forceinline__ void ldmx4(uint32_t* r, uint32_t addr) {
    asm volatile("ldmatrix.sync.aligned.m8n8.x4.shared.b16 {%0,%1,%2,%3}, [%4];"
        : "=r"(r[0]), "=r"(r[1]), "=r"(r[2]), "=r"(r[3]) : "r"(addr));
}
__device__ __forceinline__ void ldmx4t(uint32_t* r, uint32_t addr) {
    asm volatile("ldmatrix.sync.aligned.m8n8.x4.trans.shared.b16 {%0,%1,%2,%3}, [%4];"
        : "=r"(r[0]), "=r"(r[1]), "=r"(r[2]), "=r"(r[3]) : "r"(addr));
}
__device__ __forceinline__ void cp_async16(uint32_t d, const void* s) {
    asm volatile("cp.async.cg.shared.global [%0], [%1], 16;" :: "r"(d), "l"(s));
}
#define CP_COMMIT asm volatile("cp.async.commit_group;" ::: "memory")
#define CP_WAIT1  asm volatile("cp.async.wait_group 1;" ::: "memory")

// ---------------------------------------------------------------------------
// fp32 -> (bf16 hi, bf16 lo) split
// ---------------------------------------------------------------------------
__global__ void split_bf16_kernel(const float* __restrict__ x,
                                  __nv_bfloat16* __restrict__ hi,
                                  __nv_bfloat16* __restrict__ lo, int n4)
{
    int i = blockIdx.x * blockDim.x + threadIdx.x;
    if (i >= n4) return;
    float4 v = ((const float4*)x)[i];
    __nv_bfloat16 h0 = __float2bfloat16(v.x);
    __nv_bfloat16 h1 = __float2bfloat16(v.y);
    __nv_bfloat16 h2 = __float2bfloat16(v.z);
    __nv_bfloat16 h3 = __float2bfloat16(v.w);
    __nv_bfloat16 l0 = __float2bfloat16(v.x - __bfloat162float(h0));
    __nv_bfloat16 l1 = __float2bfloat16(v.y - __bfloat162float(h1));
    __nv_bfloat16 l2 = __float2bfloat16(v.z - __bfloat162float(h2));
    __nv_bfloat16 l3 = __float2bfloat16(v.w - __bfloat162float(h3));
    __nv_bfloat162* h2p = (__nv_bfloat162*)hi;
    __nv_bfloat162* l2p = (__nv_bfloat162*)lo;
    h2p[i * 2 + 0] = __halves2bfloat162(h0, h1);
    h2p[i * 2 + 1] = __halves2bfloat162(h2, h3);
    l2p[i * 2 + 0] = __halves2bfloat162(l0, l1);
    l2p[i * 2 + 1] = __halves2bfloat162(l2, l3);
}

// ---------------------------------------------------------------------------
// Pipelined HMMA GEMM (unchanged from R6, passing)
// ---------------------------------------------------------------------------
#define LDT 40
#define TILE_B (128 * LDT * 2)
#define STAGE_B (4 * TILE_B)
#define GEMM_SMEM (2 * STAGE_B)

__global__ __launch_bounds__(256, 2)
void gemm_mma(const __nv_bfloat16* __restrict__ Ahi, const __nv_bfloat16* __restrict__ Alo,
              const __nv_bfloat16* __restrict__ Whi, const __nv_bfloat16* __restrict__ Wlo,
              const float* __restrict__ bias, float* __restrict__ C,
              __nv_bfloat16* __restrict__ Chi, __nv_bfloat16* __restrict__ Clo,
              float alpha)
{
    extern __shared__ char smem[];
    const uint32_t sb = smem_u32(smem);

    const int tid = threadIdx.x;
    const int wid = tid >> 5;
    const int lane = tid & 31;
    const int wm = wid >> 2;
    const int wn = wid & 3;
    const int m0 = blockIdx.y * 128;
    const int n0 = blockIdx.x * 128;

    float acc[4][4][4];
#pragma unroll
    for (int i = 0; i < 4; i++)
#pragma unroll
        for (int j = 0; j < 4; j++)
#pragma unroll
            for (int k = 0; k < 4; k++) acc[i][j][k] = 0.f;

    const int lr = lane >> 2;
    const int lc = lane & 3;

    const int r0i = tid >> 2, c0i = tid & 3;
    const int r1i = (tid + 256) >> 2, c1i = tid & 3;

    const int aRow = wm * 64 + (lane & 15);
    const int aColB = ((lane >> 4) << 3) * 2;
    const int bRow = wn * 32 + ((lane >> 4) << 3) + (lane & 7);
    const int bColB = (((lane >> 3) & 1) << 3) * 2;

#define ISSUE(K0, ST) do {                                                     \
    uint32_t sd = sb + (ST) * STAGE_B;                                         \
    size_t g0 = (size_t)(m0 + r0i) * DMODEL + (K0) + c0i * 8;                  \
    size_t g1 = (size_t)(m0 + r1i) * DMODEL + (K0) + c1i * 8;                  \
    size_t h0 = (size_t)(n0 + r0i) * DMODEL + (K0) + c0i * 8;                  \
    size_t h1 = (size_t)(n0 + r1i) * DMODEL + (K0) + c1i * 8;                  \
    uint32_t d0 = r0i * (LDT * 2) + c0i * 16;                                  \
    uint32_t d1 = r1i * (LDT * 2) + c1i * 16;                                  \
    cp_async16(sd + 0 * TILE_B + d0, Ahi + g0);                                \
    cp_async16(sd + 0 * TILE_B + d1, Ahi + g1);                                \
    cp_async16(sd + 1 * TILE_B + d0, Alo + g0);                                \
    cp_async16(sd + 1 * TILE_B + d1, Alo + g1);                                \
    cp_async16(sd + 2 * TILE_B + d0, Whi + h0);                                \
    cp_async16(sd + 2 * TILE_B + d1, Whi + h1);                                \
    cp_async16(sd + 3 * TILE_B + d0, Wlo + h0);                                \
    cp_async16(sd + 3 * TILE_B + d1, Wlo + h1);                                \
} while (0)

    ISSUE(0, 0);
    CP_COMMIT;

    for (int it = 0; it < DMODEL / 32; it++) {
        if (it + 1 < DMODEL / 32) ISSUE((it + 1) * 32, (it + 1) & 1);
        CP_COMMIT;
        CP_WAIT1;
        __syncthreads();

        const uint32_t st = sb + (it & 1) * STAGE_B;
        const uint32_t aHiB = st + 0 * TILE_B;
        const uint32_t aLoB = st + 1 * TILE_B;
        const uint32_t wHiB = st + 2 * TILE_B;
        const uint32_t wLoB = st + 3 * TILE_B;

#pragma unroll
        for (int ks = 0; ks < 2; ks++) {
            const uint32_t acol = ks * 32 + aColB;
            const uint32_t bcol = ks * 32 + bColB;

            uint32_t bh[2][4], bl[2][4];
#pragma unroll
            for (int nip = 0; nip < 2; nip++) {
                uint32_t boff = (uint32_t)(bRow + nip * 16) * (LDT * 2) + bcol;
                ldmx4(bh[nip], wHiB + boff);
                ldmx4(bl[nip], wLoB + boff);
            }
#pragma unroll
            for (int mi = 0; mi < 4; mi++) {
                uint32_t aoff = (uint32_t)(aRow + mi * 16) * (LDT * 2) + acol;
                uint32_t a[4];
                ldmx4(a, aHiB + aoff);
#pragma unroll
                for (int nip = 0; nip < 2; nip++) {
                    mma16816(acc[mi][2 * nip + 0], a, &bh[nip][0]);
                    mma16816(acc[mi][2 * nip + 1], a, &bh[nip][2]);
                    mma16816(acc[mi][2 * nip + 0], a, &bl[nip][0]);
                    mma16816(acc[mi][2 * nip + 1], a, &bl[nip][2]);
                }
                ldmx4(a, aLoB + aoff);
#pragma unroll
                for (int nip = 0; nip < 2; nip++) {
                    mma16816(acc[mi][2 * nip + 0], a, &bh[nip][0]);
                    mma16816(acc[mi][2 * nip + 1], a, &bh[nip][2]);
                }
            }
        }
        __syncthreads();
    }
#undef ISSUE

#pragma unroll
    for (int mi = 0; mi < 4; mi++) {
        int row = m0 + wm * 64 + mi * 16 + lr;
#pragma unroll
        for (int ni = 0; ni < 4; ni++) {
            int col = n0 + wn * 32 + ni * 8 + lc * 2;
            float2 b2 = *(const float2*)&bias[col];
            float v0x = alpha * (acc[mi][ni][0] + b2.x);
            float v0y = alpha * (acc[mi][ni][1] + b2.y);
            float v1x = alpha * (acc[mi][ni][2] + b2.x);
            float v1y = alpha * (acc[mi][ni][3] + b2.y);
            size_t p0 = (size_t)row * DMODEL + col;
            size_t p1 = (size_t)(row + 8) * DMODEL + col;
            if (C) {
                *(float2*)&C[p0] = make_float2(v0x, v0y);
                *(float2*)&C[p1] = make_float2(v1x, v1y);
            }
            if (Chi) {
                uint32_t h0 = pack_bf16(v0x, v0y);
                uint32_t h1 = pack_bf16(v1x, v1y);
                *(uint32_t*)&Chi[p0] = h0;
                *(uint32_t*)&Chi[p1] = h1;
                __nv_bfloat162 hh0 = *(__nv_bfloat162*)&h0;
                __nv_bfloat162 hh1 = *(__nv_bfloat162*)&h1;
                *(uint32_t*)&Clo[p0] = pack_bf16(v0x - __bfloat162float(hh0.x),
                                                 v0y - __bfloat162float(hh0.y));
                *(uint32_t*)&Clo[p1] = pack_bf16(v1x - __bfloat162float(hh1.x),
                                                 v1y - __bfloat162float(hh1.y));
            }
        }
    }
}

// ---------------------------------------------------------------------------
// Fused HMMA attention v2: 512 threads / 16 warps, ldmatrix fragments,
// natural-layout V tiles (ldmatrix.trans), two vb-parity groups for PV.
// ---------------------------------------------------------------------------
#define QT 32
#define O_SC   0                         // 32 rows x 4096 B (fp32 -> phi/plo)
#define O_QH   131072                    // 32*72 bf16 = 4608
#define O_QL   (O_QH + 4608)             // 135680
#define O_KT   140288                    // K: KTH 18432 + KTL 18432 (V aliases)
#define O_PEK  177152
#define O_PEV  (O_PEK + 2304)
#define O_RB   181760
#define O_WS   (O_RB + 1536)
#define O_MSK  184832
#define ATT_SMEM 188928

__global__ __launch_bounds__(512)
void attn_mma(const __nv_bfloat16* __restrict__ qh, const __nv_bfloat16* __restrict__ ql,
              const __nv_bfloat16* __restrict__ kh, const __nv_bfloat16* __restrict__ kl,
              const __nv_bfloat16* __restrict__ vh, const __nv_bfloat16* __restrict__ vl,
              const int* __restrict__ mask, const float* __restrict__ pe_k,
              const float* __restrict__ pe_v, float* __restrict__ attn_out,
              __nv_bfloat16* __restrict__ Oh, __nv_bfloat16* __restrict__ Ol)
{
    extern __shared__ char smem[];
    const uint32_t sb = smem_u32(smem);
    float* sc = (float*)smem;
    __nv_bfloat16* QH = (__nv_bfloat16*)(smem + O_QH);
    __nv_bfloat16* QL = (__nv_bfloat16*)(smem + O_QL);
    float* pek = (float*)(smem + O_PEK);
    float* pev = (float*)(smem + O_PEV);
    float* rb  = (float*)(smem + O_RB);
    float* ws  = (float*)(smem + O_WS);
    int*   msk = (int*)(smem + O_MSK);

    const int b  = blockIdx.z;
    const int h  = blockIdx.y;
    const int qb = blockIdx.x * QT;
    const int tid = threadIdx.x;
    const int w = tid >> 5;
    const int lane = tid & 31;
    const int lr = lane >> 2;
    const int lc = lane & 3;

    // ---- load Q tile, pe tables, mask ----
    if (tid < 256) {
        int row = tid >> 3, dg = tid & 7;
        size_t g = (size_t)(b * S_LEN + qb + row) * DMODEL + h * DHEAD + dg * 8;
        *(uint4*)&QH[row * 72 + dg * 8] = *(const uint4*)&qh[g];
        *(uint4*)&QL[row * 72 + dg * 8] = *(const uint4*)&ql[g];
    }
    for (int i = tid; i < 576; i += 512) { pek[i] = pe_k[i]; pev[i] = pe_v[i]; }
    for (int i = tid; i < S_LEN; i += 512) msk[i] = mask[b * S_LEN + i];
    __syncthreads();

    for (int i = tid; i < QT * 9; i += 512) {
        int qi = i / 9, j = i % 9;
        float s = 0.f;
        const __nv_bfloat16* qhr = QH + qi * 72;
        const __nv_bfloat16* qlr = QL + qi * 72;
        const float* pr = pek + j * 64;
#pragma unroll 16
        for (int d = 0; d < 64; d++)
            s += (__bfloat162float(qhr[d]) + __bfloat162float(qlr[d])) * pr[d];
        rb[qi * 12 + j] = s;
    }

    // hoist Q fragments
    uint32_t qah[4][2][4], qal[4][2][4];
#pragma unroll
    for (int ks = 0; ks < 4; ks++)
#pragma unroll
        for (int mt = 0; mt < 2; mt++) {
            int r = mt * 16 + lr;
            int kc = ks * 16 + lc * 2;
            qah[ks][mt][0] = *(const uint32_t*)&QH[r * 72 + kc];
            qah[ks][mt][1] = *(const uint32_t*)&QH[(r + 8) * 72 + kc];
            qah[ks][mt][2] = *(const uint32_t*)&QH[r * 72 + kc + 8];
            qah[ks][mt][3] = *(const uint32_t*)&QH[(r + 8) * 72 + kc + 8];
            qal[ks][mt][0] = *(const uint32_t*)&QL[r * 72 + kc];
            qal[ks][mt][1] = *(const uint32_t*)&QL[(r + 8) * 72 + kc];
            qal[ks][mt][2] = *(const uint32_t*)&QL[r * 72 + kc + 8];
            qal[ks][mt][3] = *(const uint32_t*)&QL[(r + 8) * 72 + kc + 8];
        }

    // ---- scores: 8 tiles of 128 k-columns; warp w covers n0 = w*8 ----
    const int n0 = w * 8;
    for (int kb = 0; kb < 8; kb++) {
        __syncthreads();
#pragma unroll
        for (int i = 0; i < 2; i++) {
            int idx = tid + i * 512;
            int r = idx >> 3, dg = idx & 7;
            size_t g = (size_t)(b * S_LEN + kb * 128 + r) * DMODEL + h * DHEAD + dg * 8;
            *(uint4*)(smem + O_KT + (r * 72 + dg * 8) * 2) = *(const uint4*)&kh[g];
            *(uint4*)(smem + O_KT + 18432 + (r * 72 + dg * 8) * 2) = *(const uint4*)&kl[g];
        }
        __syncthreads();

        uint32_t bh2[2][4], bl2[2][4];
#pragma unroll
        for (int j = 0; j < 2; j++) {
            uint32_t addr = sb + O_KT + (uint32_t)(n0 + (lane & 7)) * 144
                          + j * 64 + (lane >> 3) * 16;
            ldmx4(bh2[j], addr);
            ldmx4(bl2[j], addr + 18432);
        }

        float c[2][4] = {{0.f,0.f,0.f,0.f},{0.f,0.f,0.f,0.f}};
#pragma unroll
        for (int ks = 0; ks < 4; ks++) {
            uint32_t* bh = &bh2[ks >> 1][(ks & 1) * 2];
            uint32_t* bl = &bl2[ks >> 1][(ks & 1) * 2];
#pragma unroll
            for (int mt = 0; mt < 2; mt++) {
                mma16816(c[mt], qah[ks][mt], bh);
                mma16816(c[mt], qah[ks][mt], bl);
                mma16816(c[mt], qal[ks][mt], bh);
            }
        }
#pragma unroll
        for (int mt = 0; mt < 2; mt++) {
#pragma unroll
            for (int half = 0; half < 2; half++) {
                int qi = mt * 16 + lr + half * 8;
                int qg = qb + qi;
                int kg = kb * 128 + n0 + lc * 2;
                float v0 = c[mt][half * 2 + 0];
                float v1 = c[mt][half * 2 + 1];
                int d0 = min(MAXK, max(-MAXK, kg - qg)) + MAXK;
                int d1 = min(MAXK, max(-MAXK, kg + 1 - qg)) + MAXK;
                v0 = msk[kg] ? v0 + rb[qi * 12 + d0] : -INFINITY;
                v1 = msk[kg + 1] ? v1 + rb[qi * 12 + d1] : -INFINITY;
                *(float2*)&sc[qi * S_LEN + kg] = make_float2(v0, v1);
            }
        }
    }
    __syncthreads();

    // ---- softmax: warp w -> rows 2w, 2w+1 ----
#pragma unroll
    for (int r = 0; r < 2; r++) {
        int qi = w * 2 + r;
        int qg = qb + qi;
        float* row = sc + qi * S_LEN;

        float m = -INFINITY;
        for (int k2 = lane; k2 < S_LEN; k2 += 32) m = fmaxf(m, row[k2]);
#pragma unroll
        for (int o = 16; o; o >>= 1) m = fmaxf(m, __shfl_xor_sync(0xFFFFFFFFu, m, o));

        float sum = 0.f;
        for (int k2 = lane; k2 < S_LEN; k2 += 32) {
            float e = __expf(row[k2] - m);
            row[k2] = e;
            sum += e;
        }
#pragma unroll
        for (int o = 16; o; o >>= 1) sum += __shfl_xor_sync(0xFFFFFFFFu, sum, o);
        float inv = 1.f / sum;

        float* ao = attn_out ? attn_out + ((size_t)(b * NHEAD + h) * S_LEN + qg) * S_LEN
                             : (float*)0;
        float w0 = 0.f, w8 = 0.f;
        for (int k2 = lane; k2 < S_LEN; k2 += 32) {
            float p = row[k2] * inv;
            row[k2] = p;
            if (ao) ao[k2] = p;
            if (k2 <= qg - MAXK) w0 += p;
            if (k2 >= qg + MAXK) w8 += p;
        }
#pragma unroll
        for (int o = 16; o; o >>= 1) {
            w0 += __shfl_xor_sync(0xFFFFFFFFu, w0, o);
            w8 += __shfl_xor_sync(0xFFFFFFFFu, w8, o);
        }
        __syncwarp();
        if (lane == 0) { ws[qi * 12 + 0] = w0; ws[qi * 12 + 8] = w8; }
        if (lane >= 1 && lane <= 7) {
            int k2 = qg + lane - MAXK;
            ws[qi * 12 + lane] = (k2 >= 0 && k2 < S_LEN) ? row[k2] : 0.f;
        }
        __syncwarp();

        // convert row to phi/plo in place (XOR swizzled)
        float x[32];
        const float4* src = (const float4*)(row + lane * 32);
#pragma unroll
        for (int t = 0; t < 8; t++) {
            float4 v = src[t];
            x[t * 4 + 0] = v.x; x[t * 4 + 1] = v.y;
            x[t * 4 + 2] = v.z; x[t * 4 + 3] = v.w;
        }
        __syncwarp();
        uint32_t swz = (uint32_t)((qi & 7) << 4);
        char* rowb = smem + qi * 4096;
#pragma unroll
        for (int jj = 0; jj < 16; jj++) {
            int j = lane * 16 + jj;
            float a = x[jj * 2], bb = x[jj * 2 + 1];
            uint32_t hi = pack_bf16(a, bb);
            __nv_bfloat162 h2 = *(__nv_bfloat162*)&hi;
            uint32_t lo = pack_bf16(a - __bfloat162float(h2.x),
                                    bb - __bfloat162float(h2.y));
            *(uint32_t*)(rowb + (((uint32_t)(4 * j)) ^ swz)) = hi;
            *(uint32_t*)(rowb + 2048 + (((uint32_t)(4 * j)) ^ swz)) = lo;
        }
    }
    __syncthreads();

    // ---- PV: two vb-parity groups, warp (g, wn) covers d-cols wn*8..+7 ----
    const int g = w >> 3;
    const int wn = w & 7;
    float o[2][4] = {{0.f,0.f,0.f,0.f},{0.f,0.f,0.f,0.f}};

    for (int vbi = 0; vbi < 8; vbi++) {
        __syncthreads();
        // load two V tiles (natural [seq][d] layout, hi+lo)
#pragma unroll
        for (int i = 0; i < 2; i++) {
            int idx = tid + i * 512;            // 0..1023
            int tg = idx >> 9;                  // group tile 0/1
            int r = (idx >> 3) & 63, dg = idx & 7;
            size_t ga = (size_t)(b * S_LEN + vbi * 128 + tg * 64 + r) * DMODEL
                      + h * DHEAD + dg * 8;
            uint32_t off = O_KT + tg * 18432 + (r * 72 + dg * 8) * 2;
            *(uint4*)(smem + off) = *(const uint4*)&vh[ga];
            *(uint4*)(smem + off + 9216) = *(const uint4*)&vl[ga];
        }
        __syncthreads();

        const int vb = vbi * 2 + g;
        const uint32_t vtile = sb + O_KT + g * 18432;

        uint32_t bh2[2][4], bl2[2][4];
#pragma unroll
        for (int j = 0; j < 2; j++) {
            uint32_t addr = vtile + (uint32_t)(j * 32 + lane) * 144 + wn * 16;
            ldmx4t(bh2[j], addr);
            ldmx4t(bl2[j], addr + 9216);
        }

#pragma unroll
        for (int ks = 0; ks < 4; ks++) {
            uint32_t* bh = &bh2[ks >> 1][(ks & 1) * 2];
            uint32_t* bl = &bl2[ks >> 1][(ks & 1) * 2];
            uint32_t kby = (uint32_t)(vb * 128 + ks * 32 + (lane >> 4) * 16);
#pragma unroll
            for (int mt = 0; mt < 2; mt++) {
                int prow = mt * 16 + (lane & 7) + ((lane >> 3) & 1) * 8;
                uint32_t cby = kby ^ ((uint32_t)(prow & 7) << 4);
                uint32_t pa = sb + (uint32_t)prow * 4096 + cby;
                uint32_t ah[4], al[4];
                ldmx4(ah, pa);
                ldmx4(al, pa + 2048);
                mma16816(o[mt], ah, bh);
                mma16816(o[mt], ah, bl);
                mma16816(o[mt], al, bh);
            }
        }
    }

    // ---- cross-group reduce + epilogue (group 0 writes) ----
    __syncthreads();
    float* red = (float*)(smem + O_QH);   // 8 KB, Q no longer needed
    if (g == 1) {
        int widx = wn * 32 + lane;
#pragma unroll
        for (int mt = 0; mt < 2; mt++)
#pragma unroll
            for (int j = 0; j < 4; j++)
                red[widx * 8 + mt * 4 + j] = o[mt][j];
    }
    __syncthreads();
    if (g == 0) {
        int widx = wn * 32 + lane;
#pragma unroll
        for (int mt = 0; mt < 2; mt++)
#pragma unroll
            for (int j = 0; j < 4; j++)
                o[mt][j] += red[widx * 8 + mt * 4 + j];

#pragma unroll
        for (int mt = 0; mt < 2; mt++) {
#pragma unroll
            for (int half = 0; half < 2; half++) {
                int qi = mt * 16 + lr + half * 8;
                int d0 = wn * 8 + lc * 2;
                float a0 = o[mt][half * 2 + 0];
                float a1 = o[mt][half * 2 + 1];
#pragma unroll
                for (int j = 0; j < 9; j++) {
                    float wv = ws[qi * 12 + j];
                    a0 += wv * pev[j * 64 + d0];
                    a1 += wv * pev[j * 64 + d0 + 1];
                }
                size_t base = (size_t)(b * S_LEN + qb + qi) * DMODEL + h * DHEAD + d0;
                uint32_t hi = pack_bf16(a0, a1);
                __nv_bfloat162 h2 = *(__nv_bfloat162*)&hi;
                uint32_t lo = pack_bf16(a0 - __bfloat162float(h2.x),
                                        a1 - __bfloat162float(h2.y));
                *(uint32_t*)&Oh[base] = hi;
                *(uint32_t*)&Ol[base] = lo;
            }
        }
    }
}

// ---------------------------------------------------------------------------
extern "C" void kernel_launch(void* const* d_in, const int* in_sizes, int n_in,
                              void* d_out, int out_size)
{
    const float* query = (const float*)d_in[0];
    const float* key   = (const float*)d_in[1];
    const float* value = (const float*)d_in[2];
    const int*   mask  = (const int*)d_in[3];
    const float* Wq = (const float*)d_in[4];
    const float* bq = (const float*)d_in[5];
    const float* Wk = (const float*)d_in[6];
    const float* bk = (const float*)d_in[7];
    const float* Wv = (const float*)d_in[8];
    const float* bv = (const float*)d_in[9];
    const float* Wo = (const float*)d_in[10];
    const float* bo = (const float*)d_in[11];
    const float* pe_k = (const float*)d_in[12];
    const float* pe_v = (const float*)d_in[13];

    __nv_bfloat16 *ahi, *alo, *whi, *wlo, *qh, *ql, *kh, *kl, *vh, *vl, *oh, *ol;
    cudaGetSymbolAddress((void**)&ahi, g_act_hi);
    cudaGetSymbolAddress((void**)&alo, g_act_lo);
    cudaGetSymbolAddress((void**)&whi, g_w_hi);
    cudaGetSymbolAddress((void**)&wlo, g_w_lo);
    cudaGetSymbolAddress((void**)&qh, g_qh);
    cudaGetSymbolAddress((void**)&ql, g_ql);
    cudaGetSymbolAddress((void**)&kh, g_kh);
    cudaGetSymbolAddress((void**)&kl, g_kl);
    cudaGetSymbolAddress((void**)&vh, g_vh);
    cudaGetSymbolAddress((void**)&vl, g_vl);
    cudaGetSymbolAddress((void**)&oh, g_oh);
    cudaGetSymbolAddress((void**)&ol, g_ol);

    const long long OUT_ELEMS = (long long)BATCH * S_LEN * DMODEL;
    float* out_ptr  = (float*)d_out;
    float* attn_ptr = ((long long)out_size > OUT_ELEMS) ? (float*)d_out + OUT_ELEMS
                                                        : (float*)0;

    cudaFuncSetAttribute(attn_mma, cudaFuncAttributeMaxDynamicSharedMemorySize,
                         ATT_SMEM);
    cudaFuncSetAttribute(gemm_mma, cudaFuncAttributeMaxDynamicSharedMemorySize,
                         GEMM_SMEM);

    const int ACT4 = MROWS * DMODEL / 4;
    const int W4   = DMODEL * DMODEL / 4;
    dim3 gg(DMODEL / 128, MROWS / 128);

    split_bf16_kernel<<<ACT4 / 256, 256>>>(query, ahi, alo, ACT4);
    split_bf16_kernel<<<W4 / 256, 256>>>(Wq, whi, wlo, W4);
    gemm_mma<<<gg, 256, GEMM_SMEM>>>(ahi, alo, whi, wlo, bq, (float*)0, qh, ql, 0.125f);
    split_bf16_kernel<<<ACT4 / 256, 256>>>(key, ahi, alo, ACT4);
    split_bf16_kernel<<<W4 / 256, 256>>>(Wk, whi, wlo, W4);
    gemm_mma<<<gg, 256, GEMM_SMEM>>>(ahi, alo, whi, wlo, bk, (float*)0, kh, kl, 1.0f);
    split_bf16_kernel<<<ACT4 / 256, 256>>>(value, ahi, alo, ACT4);
    split_bf16_kernel<<<W4 / 256, 256>>>(Wv, whi, wlo, W4);
    gemm_mma<<<gg, 256, GEMM_SMEM>>>(ahi, alo, whi, wlo, bv, (float*)0, vh, vl, 1.0f);

    dim3 ga(S_LEN / QT, NHEAD, BATCH);
    attn_mma<<<ga, 512, ATT_SMEM>>>(qh, ql, kh, kl, vh, vl, mask, pe_k, pe_v,
                                    attn_ptr, oh, ol);

    split_bf16_kernel<<<W4 / 256, 256>>>(Wo, whi, wlo, W4);
    gemm_mma<<<gg, 256, GEMM_SMEM>>>(oh, ol, whi, wlo, bo, out_ptr,
                                     (__nv_bfloat16*)0, (__nv_bfloat16*)0, 1.0f);
}

// round 8
// speedup vs baseline: 2.8817x; 1.0836x over previous
#include <cuda_runtime.h>
#include <cuda_bf16.h>
#include <math.h>
#include <cstdint>

#define BATCH 8
#define S_LEN 1024
#define DMODEL 1024
#define NHEAD 16
#define DHEAD 64
#define MAXK 4
#define MROWS (BATCH * S_LEN)   // 8192

// Scratch (allocation-free rule -> device globals)
__device__ __nv_bfloat16 g_act_hi[(size_t)MROWS * DMODEL];
__device__ __nv_bfloat16 g_act_lo[(size_t)MROWS * DMODEL];
__device__ __nv_bfloat16 g_w_hi[(size_t)DMODEL * DMODEL];
__device__ __nv_bfloat16 g_w_lo[(size_t)DMODEL * DMODEL];
__device__ __nv_bfloat16 g_qh[(size_t)MROWS * DMODEL];
__device__ __nv_bfloat16 g_ql[(size_t)MROWS * DMODEL];
__device__ __nv_bfloat16 g_kh[(size_t)MROWS * DMODEL];
__device__ __nv_bfloat16 g_kl[(size_t)MROWS * DMODEL];
__device__ __nv_bfloat16 g_vh[(size_t)MROWS * DMODEL];
__device__ __nv_bfloat16 g_vl[(size_t)MROWS * DMODEL];
__device__ __nv_bfloat16 g_oh[(size_t)MROWS * DMODEL];
__device__ __nv_bfloat16 g_ol[(size_t)MROWS * DMODEL];

// ---------------------------------------------------------------------------
__device__ __forceinline__ void mma16816(float* c, const uint32_t* a, const uint32_t* b) {
    asm volatile(
        "mma.sync.aligned.m16n8k16.row.col.f32.bf16.bf16.f32 "
        "{%0,%1,%2,%3}, {%4,%5,%6,%7}, {%8,%9}, {%0,%1,%2,%3};"
        : "+f"(c[0]), "+f"(c[1]), "+f"(c[2]), "+f"(c[3])
        : "r"(a[0]), "r"(a[1]), "r"(a[2]), "r"(a[3]), "r"(b[0]), "r"(b[1]));
}
__device__ __forceinline__ uint32_t pack_bf16(float x, float y) {
    __nv_bfloat162 t = __halves2bfloat162(__float2bfloat16(x), __float2bfloat16(y));
    return *(uint32_t*)&t;
}
__device__ __forceinline__ uint32_t smem_u32(const void* p) {
    uint32_t a;
    asm("{ .reg .u64 t; cvta.to.shared.u64 t, %1; cvt.u32.u64 %0, t; }"
        : "=r"(a) : "l"(p));
    return a;
}
__device__ __forceinline__ void ldmx4(uint32_t* r, uint32_t addr) {
    asm volatile("ldmatrix.sync.aligned.m8n8.x4.shared.b16 {%0,%1,%2,%3}, [%4];"
        : "=r"(r[0]), "=r"(r[1]), "=r"(r[2]), "=r"(r[3]) : "r"(addr));
}
__device__ __forceinline__ void ldmx4t(uint32_t* r, uint32_t addr) {
    asm volatile("ldmatrix.sync.aligned.m8n8.x4.trans.shared.b16 {%0,%1,%2,%3}, [%4];"
        : "=r"(r[0]), "=r"(r[1]), "=r"(r[2]), "=r"(r[3]) : "r"(addr));
}
__device__ __forceinline__ void cp_async16(uint32_t d, const void* s) {
    asm volatile("cp.async.cg.shared.global [%0], [%1], 16;" :: "r"(d), "l"(s));
}
#define CP_COMMIT asm volatile("cp.async.commit_group;" ::: "memory")
#define CP_WAIT1  asm volatile("cp.async.wait_group 1;" ::: "memory")

// ---------------------------------------------------------------------------
// fp32 -> (bf16 hi, bf16 lo) split
// ---------------------------------------------------------------------------
__global__ void split_bf16_kernel(const float* __restrict__ x,
                                  __nv_bfloat16* __restrict__ hi,
                                  __nv_bfloat16* __restrict__ lo, int n4)
{
    int i = blockIdx.x * blockDim.x + threadIdx.x;
    if (i >= n4) return;
    float4 v = ((const float4*)x)[i];
    __nv_bfloat16 h0 = __float2bfloat16(v.x);
    __nv_bfloat16 h1 = __float2bfloat16(v.y);
    __nv_bfloat16 h2 = __float2bfloat16(v.z);
    __nv_bfloat16 h3 = __float2bfloat16(v.w);
    __nv_bfloat16 l0 = __float2bfloat16(v.x - __bfloat162float(h0));
    __nv_bfloat16 l1 = __float2bfloat16(v.y - __bfloat162float(h1));
    __nv_bfloat16 l2 = __float2bfloat16(v.z - __bfloat162float(h2));
    __nv_bfloat16 l3 = __float2bfloat16(v.w - __bfloat162float(h3));
    __nv_bfloat162* h2p = (__nv_bfloat162*)hi;
    __nv_bfloat162* l2p = (__nv_bfloat162*)lo;
    h2p[i * 2 + 0] = __halves2bfloat162(h0, h1);
    h2p[i * 2 + 1] = __halves2bfloat162(h2, h3);
    l2p[i * 2 + 0] = __halves2bfloat162(l0, l1);
    l2p[i * 2 + 1] = __halves2bfloat162(l2, l3);
}

// ---------------------------------------------------------------------------
// Pipelined HMMA GEMM (unchanged from R6, passing)
// ---------------------------------------------------------------------------
#define LDT 40
#define TILE_B (128 * LDT * 2)
#define STAGE_B (4 * TILE_B)
#define GEMM_SMEM (2 * STAGE_B)

__global__ __launch_bounds__(256, 2)
void gemm_mma(const __nv_bfloat16* __restrict__ Ahi, const __nv_bfloat16* __restrict__ Alo,
              const __nv_bfloat16* __restrict__ Whi, const __nv_bfloat16* __restrict__ Wlo,
              const float* __restrict__ bias, float* __restrict__ C,
              __nv_bfloat16* __restrict__ Chi, __nv_bfloat16* __restrict__ Clo,
              float alpha)
{
    extern __shared__ char smem[];
    const uint32_t sb = smem_u32(smem);

    const int tid = threadIdx.x;
    const int wid = tid >> 5;
    const int lane = tid & 31;
    const int wm = wid >> 2;
    const int wn = wid & 3;
    const int m0 = blockIdx.y * 128;
    const int n0 = blockIdx.x * 128;

    float acc[4][4][4];
#pragma unroll
    for (int i = 0; i < 4; i++)
#pragma unroll
        for (int j = 0; j < 4; j++)
#pragma unroll
            for (int k = 0; k < 4; k++) acc[i][j][k] = 0.f;

    const int lr = lane >> 2;
    const int lc = lane & 3;

    const int r0i = tid >> 2, c0i = tid & 3;
    const int r1i = (tid + 256) >> 2, c1i = tid & 3;

    const int aRow = wm * 64 + (lane & 15);
    const int aColB = ((lane >> 4) << 3) * 2;
    const int bRow = wn * 32 + ((lane >> 4) << 3) + (lane & 7);
    const int bColB = (((lane >> 3) & 1) << 3) * 2;

#define ISSUE(K0, ST) do {                                                     \
    uint32_t sd = sb + (ST) * STAGE_B;                                         \
    size_t g0 = (size_t)(m0 + r0i) * DMODEL + (K0) + c0i * 8;                  \
    size_t g1 = (size_t)(m0 + r1i) * DMODEL + (K0) + c1i * 8;                  \
    size_t h0 = (size_t)(n0 + r0i) * DMODEL + (K0) + c0i * 8;                  \
    size_t h1 = (size_t)(n0 + r1i) * DMODEL + (K0) + c1i * 8;                  \
    uint32_t d0 = r0i * (LDT * 2) + c0i * 16;                                  \
    uint32_t d1 = r1i * (LDT * 2) + c1i * 16;                                  \
    cp_async16(sd + 0 * TILE_B + d0, Ahi + g0);                                \
    cp_async16(sd + 0 * TILE_B + d1, Ahi + g1);                                \
    cp_async16(sd + 1 * TILE_B + d0, Alo + g0);                                \
    cp_async16(sd + 1 * TILE_B + d1, Alo + g1);                                \
    cp_async16(sd + 2 * TILE_B + d0, Whi + h0);                                \
    cp_async16(sd + 2 * TILE_B + d1, Whi + h1);                                \
    cp_async16(sd + 3 * TILE_B + d0, Wlo + h0);                                \
    cp_async16(sd + 3 * TILE_B + d1, Wlo + h1);                                \
} while (0)

    ISSUE(0, 0);
    CP_COMMIT;

    for (int it = 0; it < DMODEL / 32; it++) {
        if (it + 1 < DMODEL / 32) ISSUE((it + 1) * 32, (it + 1) & 1);
        CP_COMMIT;
        CP_WAIT1;
        __syncthreads();

        const uint32_t st = sb + (it & 1) * STAGE_B;
        const uint32_t aHiB = st + 0 * TILE_B;
        const uint32_t aLoB = st + 1 * TILE_B;
        const uint32_t wHiB = st + 2 * TILE_B;
        const uint32_t wLoB = st + 3 * TILE_B;

#pragma unroll
        for (int ks = 0; ks < 2; ks++) {
            const uint32_t acol = ks * 32 + aColB;
            const uint32_t bcol = ks * 32 + bColB;

            uint32_t bh[2][4], bl[2][4];
#pragma unroll
            for (int nip = 0; nip < 2; nip++) {
                uint32_t boff = (uint32_t)(bRow + nip * 16) * (LDT * 2) + bcol;
                ldmx4(bh[nip], wHiB + boff);
                ldmx4(bl[nip], wLoB + boff);
            }
#pragma unroll
            for (int mi = 0; mi < 4; mi++) {
                uint32_t aoff = (uint32_t)(aRow + mi * 16) * (LDT * 2) + acol;
                uint32_t a[4];
                ldmx4(a, aHiB + aoff);
#pragma unroll
                for (int nip = 0; nip < 2; nip++) {
                    mma16816(acc[mi][2 * nip + 0], a, &bh[nip][0]);
                    mma16816(acc[mi][2 * nip + 1], a, &bh[nip][2]);
                    mma16816(acc[mi][2 * nip + 0], a, &bl[nip][0]);
                    mma16816(acc[mi][2 * nip + 1], a, &bl[nip][2]);
                }
                ldmx4(a, aLoB + aoff);
#pragma unroll
                for (int nip = 0; nip < 2; nip++) {
                    mma16816(acc[mi][2 * nip + 0], a, &bh[nip][0]);
                    mma16816(acc[mi][2 * nip + 1], a, &bh[nip][2]);
                }
            }
        }
        __syncthreads();
    }
#undef ISSUE

#pragma unroll
    for (int mi = 0; mi < 4; mi++) {
        int row = m0 + wm * 64 + mi * 16 + lr;
#pragma unroll
        for (int ni = 0; ni < 4; ni++) {
            int col = n0 + wn * 32 + ni * 8 + lc * 2;
            float2 b2 = *(const float2*)&bias[col];
            float v0x = alpha * (acc[mi][ni][0] + b2.x);
            float v0y = alpha * (acc[mi][ni][1] + b2.y);
            float v1x = alpha * (acc[mi][ni][2] + b2.x);
            float v1y = alpha * (acc[mi][ni][3] + b2.y);
            size_t p0 = (size_t)row * DMODEL + col;
            size_t p1 = (size_t)(row + 8) * DMODEL + col;
            if (C) {
                *(float2*)&C[p0] = make_float2(v0x, v0y);
                *(float2*)&C[p1] = make_float2(v1x, v1y);
            }
            if (Chi) {
                uint32_t h0 = pack_bf16(v0x, v0y);
                uint32_t h1 = pack_bf16(v1x, v1y);
                *(uint32_t*)&Chi[p0] = h0;
                *(uint32_t*)&Chi[p1] = h1;
                __nv_bfloat162 hh0 = *(__nv_bfloat162*)&h0;
                __nv_bfloat162 hh1 = *(__nv_bfloat162*)&h1;
                *(uint32_t*)&Clo[p0] = pack_bf16(v0x - __bfloat162float(hh0.x),
                                                 v0y - __bfloat162float(hh0.y));
                *(uint32_t*)&Clo[p1] = pack_bf16(v1x - __bfloat162float(hh1.x),
                                                 v1y - __bfloat162float(hh1.y));
            }
        }
    }
}

// ---------------------------------------------------------------------------
// Fused HMMA attention v3: 512 threads, cp.async double-buffered K/V tiles.
// ---------------------------------------------------------------------------
#define QT 32
#define O_SC   0                         // 32 rows x 4096 B
#define O_QH   131072                    // 4608
#define O_QL   (O_QH + 4608)             // 135680
#define O_KB   140288                    // 2 stages x 36864 = 73728
#define KSTG   36864
#define O_PEK  214016
#define O_PEV  (O_PEK + 2304)
#define O_RB   218624
#define O_WS   (O_RB + 1536)
#define O_MSK  221696
#define ATT_SMEM 225792

__global__ __launch_bounds__(512)
void attn_mma(const __nv_bfloat16* __restrict__ qh, const __nv_bfloat16* __restrict__ ql,
              const __nv_bfloat16* __restrict__ kh, const __nv_bfloat16* __restrict__ kl,
              const __nv_bfloat16* __restrict__ vh, const __nv_bfloat16* __restrict__ vl,
              const int* __restrict__ mask, const float* __restrict__ pe_k,
              const float* __restrict__ pe_v, float* __restrict__ attn_out,
              __nv_bfloat16* __restrict__ Oh, __nv_bfloat16* __restrict__ Ol)
{
    extern __shared__ char smem[];
    const uint32_t sb = smem_u32(smem);
    float* sc = (float*)smem;
    __nv_bfloat16* QH = (__nv_bfloat16*)(smem + O_QH);
    __nv_bfloat16* QL = (__nv_bfloat16*)(smem + O_QL);
    float* pek = (float*)(smem + O_PEK);
    float* pev = (float*)(smem + O_PEV);
    float* rb  = (float*)(smem + O_RB);
    float* ws  = (float*)(smem + O_WS);
    int*   msk = (int*)(smem + O_MSK);

    const int b  = blockIdx.z;
    const int h  = blockIdx.y;
    const int qb = blockIdx.x * QT;
    const int tid = threadIdx.x;
    const int w = tid >> 5;
    const int lane = tid & 31;
    const int lr = lane >> 2;
    const int lc = lane & 3;

    // load-index precompute (each thread moves 2x16B per tile half)
    const int liR0 = tid >> 3, liD0 = tid & 7;
    const int liR1 = (tid + 512) >> 3, liD1 = tid & 7;

    // ---- K issue: tile kb -> stage st (hi at 0, lo at +18432) ----
#define ISSUE_K(KB, ST) do {                                                   \
    uint32_t sd = sb + O_KB + (ST) * KSTG;                                     \
    size_t gA = (size_t)(b * S_LEN + (KB) * 128 + liR0) * DMODEL               \
              + h * DHEAD + liD0 * 8;                                          \
    size_t gB = (size_t)(b * S_LEN + (KB) * 128 + liR1) * DMODEL               \
              + h * DHEAD + liD1 * 8;                                          \
    uint32_t dA = (uint32_t)(liR0 * 72 + liD0 * 8) * 2;                        \
    uint32_t dB = (uint32_t)(liR1 * 72 + liD1 * 8) * 2;                        \
    cp_async16(sd + dA, kh + gA);                                              \
    cp_async16(sd + dB, kh + gB);                                              \
    cp_async16(sd + 18432 + dA, kl + gA);                                      \
    cp_async16(sd + 18432 + dB, kl + gB);                                      \
} while (0)

    // ---- V issue: tile vbi -> stage st (tg = row>>6; hi, lo at +9216) ----
#define ISSUE_V(VB, ST) do {                                                   \
    uint32_t sd = sb + O_KB + (ST) * KSTG;                                     \
    size_t gA = (size_t)(b * S_LEN + (VB) * 128 + liR0) * DMODEL               \
              + h * DHEAD + liD0 * 8;                                          \
    size_t gB = (size_t)(b * S_LEN + (VB) * 128 + liR1) * DMODEL               \
              + h * DHEAD + liD1 * 8;                                          \
    uint32_t dA = (uint32_t)((liR0 >> 6) * 18432 + ((liR0 & 63) * 72 + liD0 * 8) * 2); \
    uint32_t dB = (uint32_t)((liR1 >> 6) * 18432 + ((liR1 & 63) * 72 + liD1 * 8) * 2); \
    cp_async16(sd + dA, vh + gA);                                              \
    cp_async16(sd + dB, vh + gB);                                              \
    cp_async16(sd + 9216 + dA, vl + gA);                                       \
    cp_async16(sd + 9216 + dB, vl + gB);                                       \
} while (0)

    // ---- load Q tile, pe tables, mask; prefetch K tile 0 ----
    ISSUE_K(0, 0);
    CP_COMMIT;

    if (tid < 256) {
        int row = tid >> 3, dg = tid & 7;
        size_t g = (size_t)(b * S_LEN + qb + row) * DMODEL + h * DHEAD + dg * 8;
        *(uint4*)&QH[row * 72 + dg * 8] = *(const uint4*)&qh[g];
        *(uint4*)&QL[row * 72 + dg * 8] = *(const uint4*)&ql[g];
    }
    for (int i = tid; i < 576; i += 512) { pek[i] = pe_k[i]; pev[i] = pe_v[i]; }
    for (int i = tid; i < S_LEN; i += 512) msk[i] = mask[b * S_LEN + i];
    __syncthreads();

    for (int i = tid; i < QT * 9; i += 512) {
        int qi = i / 9, j = i % 9;
        float s = 0.f;
        const __nv_bfloat16* qhr = QH + qi * 72;
        const __nv_bfloat16* qlr = QL + qi * 72;
        const float* pr = pek + j * 64;
#pragma unroll 16
        for (int d = 0; d < 64; d++)
            s += (__bfloat162float(qhr[d]) + __bfloat162float(qlr[d])) * pr[d];
        rb[qi * 12 + j] = s;
    }

    // hoist Q fragments
    uint32_t qah[4][2][4], qal[4][2][4];
#pragma unroll
    for (int ks = 0; ks < 4; ks++)
#pragma unroll
        for (int mt = 0; mt < 2; mt++) {
            int r = mt * 16 + lr;
            int kc = ks * 16 + lc * 2;
            qah[ks][mt][0] = *(const uint32_t*)&QH[r * 72 + kc];
            qah[ks][mt][1] = *(const uint32_t*)&QH[(r + 8) * 72 + kc];
            qah[ks][mt][2] = *(const uint32_t*)&QH[r * 72 + kc + 8];
            qah[ks][mt][3] = *(const uint32_t*)&QH[(r + 8) * 72 + kc + 8];
            qal[ks][mt][0] = *(const uint32_t*)&QL[r * 72 + kc];
            qal[ks][mt][1] = *(const uint32_t*)&QL[(r + 8) * 72 + kc];
            qal[ks][mt][2] = *(const uint32_t*)&QL[r * 72 + kc + 8];
            qal[ks][mt][3] = *(const uint32_t*)&QL[(r + 8) * 72 + kc + 8];
        }

    // ---- scores: 8 tiles of 128 k-cols, double-buffered ----
    const int n0 = w * 8;
    for (int kb = 0; kb < 8; kb++) {
        if (kb + 1 < 8) ISSUE_K(kb + 1, (kb + 1) & 1);
        CP_COMMIT;
        CP_WAIT1;
        __syncthreads();

        const uint32_t kt = sb + O_KB + (kb & 1) * KSTG;
        uint32_t bh2[2][4], bl2[2][4];
#pragma unroll
        for (int j = 0; j < 2; j++) {
            uint32_t addr = kt + (uint32_t)(n0 + (lane & 7)) * 144
                          + j * 64 + (lane >> 3) * 16;
            ldmx4(bh2[j], addr);
            ldmx4(bl2[j], addr + 18432);
        }

        float c[2][4] = {{0.f,0.f,0.f,0.f},{0.f,0.f,0.f,0.f}};
#pragma unroll
        for (int ks = 0; ks < 4; ks++) {
            uint32_t* bh = &bh2[ks >> 1][(ks & 1) * 2];
            uint32_t* bl = &bl2[ks >> 1][(ks & 1) * 2];
#pragma unroll
            for (int mt = 0; mt < 2; mt++) {
                mma16816(c[mt], qah[ks][mt], bh);
                mma16816(c[mt], qah[ks][mt], bl);
                mma16816(c[mt], qal[ks][mt], bh);
            }
        }
#pragma unroll
        for (int mt = 0; mt < 2; mt++) {
#pragma unroll
            for (int half = 0; half < 2; half++) {
                int qi = mt * 16 + lr + half * 8;
                int qg = qb + qi;
                int kg = kb * 128 + n0 + lc * 2;
                float v0 = c[mt][half * 2 + 0];
                float v1 = c[mt][half * 2 + 1];
                int d0 = min(MAXK, max(-MAXK, kg - qg)) + MAXK;
                int d1 = min(MAXK, max(-MAXK, kg + 1 - qg)) + MAXK;
                v0 = msk[kg] ? v0 + rb[qi * 12 + d0] : -INFINITY;
                v1 = msk[kg + 1] ? v1 + rb[qi * 12 + d1] : -INFINITY;
                *(float2*)&sc[qi * S_LEN + kg] = make_float2(v0, v1);
            }
        }
        __syncthreads();
    }

    // ---- softmax: warp w -> rows 2w, 2w+1; prefetch V tile 0 after ----
#pragma unroll
    for (int r = 0; r < 2; r++) {
        int qi = w * 2 + r;
        int qg = qb + qi;
        float* row = sc + qi * S_LEN;

        float m = -INFINITY;
        for (int k2 = lane; k2 < S_LEN; k2 += 32) m = fmaxf(m, row[k2]);
#pragma unroll
        for (int o = 16; o; o >>= 1) m = fmaxf(m, __shfl_xor_sync(0xFFFFFFFFu, m, o));

        float sum = 0.f;
        for (int k2 = lane; k2 < S_LEN; k2 += 32) {
            float e = __expf(row[k2] - m);
            row[k2] = e;
            sum += e;
        }
#pragma unroll
        for (int o = 16; o; o >>= 1) sum += __shfl_xor_sync(0xFFFFFFFFu, sum, o);
        float inv = 1.f / sum;

        float* ao = attn_out ? attn_out + ((size_t)(b * NHEAD + h) * S_LEN + qg) * S_LEN
                             : (float*)0;
        float w0 = 0.f, w8 = 0.f;
        for (int k2 = lane; k2 < S_LEN; k2 += 32) {
            float p = row[k2] * inv;
            row[k2] = p;
            if (ao) ao[k2] = p;
            if (k2 <= qg - MAXK) w0 += p;
            if (k2 >= qg + MAXK) w8 += p;
        }
#pragma unroll
        for (int o = 16; o; o >>= 1) {
            w0 += __shfl_xor_sync(0xFFFFFFFFu, w0, o);
            w8 += __shfl_xor_sync(0xFFFFFFFFu, w8, o);
        }
        __syncwarp();
        if (lane == 0) { ws[qi * 12 + 0] = w0; ws[qi * 12 + 8] = w8; }
        if (lane >= 1 && lane <= 7) {
            int k2 = qg + lane - MAXK;
            ws[qi * 12 + lane] = (k2 >= 0 && k2 < S_LEN) ? row[k2] : 0.f;
        }
        __syncwarp();

        // convert row to phi/plo in place (XOR swizzled)
        float x[32];
        const float4* src = (const float4*)(row + lane * 32);
#pragma unroll
        for (int t = 0; t < 8; t++) {
            float4 v = src[t];
            x[t * 4 + 0] = v.x; x[t * 4 + 1] = v.y;
            x[t * 4 + 2] = v.z; x[t * 4 + 3] = v.w;
        }
        __syncwarp();
        uint32_t swz = (uint32_t)((qi & 7) << 4);
        char* rowb = smem + qi * 4096;
#pragma unroll
        for (int jj = 0; jj < 16; jj++) {
            int j = lane * 16 + jj;
            float a = x[jj * 2], bb = x[jj * 2 + 1];
            uint32_t hi = pack_bf16(a, bb);
            __nv_bfloat162 h2 = *(__nv_bfloat162*)&hi;
            uint32_t lo = pack_bf16(a - __bfloat162float(h2.x),
                                    bb - __bfloat162float(h2.y));
            *(uint32_t*)(rowb + (((uint32_t)(4 * j)) ^ swz)) = hi;
            *(uint32_t*)(rowb + 2048 + (((uint32_t)(4 * j)) ^ swz)) = lo;
        }
    }

    // prefetch V tile 0 (stage 0 free: K loop ended on stage 7&1=1... both safe
    // because all threads passed the K-loop's trailing sync before last compute;
    // we still need a sync to make sure every warp finished reading stage 0)
    __syncthreads();
    ISSUE_V(0, 0);
    CP_COMMIT;

    // ---- PV: two vb-parity groups, warp (g, wn) covers d-cols wn*8..+7 ----
    const int g = w >> 3;
    const int wn = w & 7;
    float o[2][4] = {{0.f,0.f,0.f,0.f},{0.f,0.f,0.f,0.f}};

    for (int vbi = 0; vbi < 8; vbi++) {
        if (vbi + 1 < 8) ISSUE_V(vbi + 1, (vbi + 1) & 1);
        CP_COMMIT;
        CP_WAIT1;
        __syncthreads();

        const int vb = vbi * 2 + g;
        const uint32_t vtile = sb + O_KB + (vbi & 1) * KSTG + g * 18432;

        uint32_t bh2[2][4], bl2[2][4];
#pragma unroll
        for (int j = 0; j < 2; j++) {
            uint32_t addr = vtile + (uint32_t)(j * 32 + lane) * 144 + wn * 16;
            ldmx4t(bh2[j], addr);
            ldmx4t(bl2[j], addr + 9216);
        }

#pragma unroll
        for (int ks = 0; ks < 4; ks++) {
            uint32_t* bh = &bh2[ks >> 1][(ks & 1) * 2];
            uint32_t* bl = &bl2[ks >> 1][(ks & 1) * 2];
            uint32_t kby = (uint32_t)(vb * 128 + ks * 32 + (lane >> 4) * 16);
#pragma unroll
            for (int mt = 0; mt < 2; mt++) {
                int prow = mt * 16 + (lane & 7) + ((lane >> 3) & 1) * 8;
                uint32_t cby = kby ^ ((uint32_t)(prow & 7) << 4);
                uint32_t pa = sb + (uint32_t)prow * 4096 + cby;
                uint32_t ah[4], al[4];
                ldmx4(ah, pa);
                ldmx4(al, pa + 2048);
                mma16816(o[mt], ah, bh);
                mma16816(o[mt], ah, bl);
                mma16816(o[mt], al, bh);
            }
        }
        __syncthreads();
    }

    // ---- cross-group reduce + epilogue (group 0 writes) ----
    float* red = (float*)(smem + O_QH);   // Q no longer needed
    if (g == 1) {
        int widx = wn * 32 + lane;
#pragma unroll
        for (int mt = 0; mt < 2; mt++)
#pragma unroll
            for (int j = 0; j < 4; j++)
                red[widx * 8 + mt * 4 + j] = o[mt][j];
    }
    __syncthreads();
    if (g == 0) {
        int widx = wn * 32 + lane;
#pragma unroll
        for (int mt = 0; mt < 2; mt++)
#pragma unroll
            for (int j = 0; j < 4; j++)
                o[mt][j] += red[widx * 8 + mt * 4 + j];

#pragma unroll
        for (int mt = 0; mt < 2; mt++) {
#pragma unroll
            for (int half = 0; half < 2; half++) {
                int qi = mt * 16 + lr + half * 8;
                int d0 = wn * 8 + lc * 2;
                float a0 = o[mt][half * 2 + 0];
                float a1 = o[mt][half * 2 + 1];
#pragma unroll
                for (int j = 0; j < 9; j++) {
                    float wv = ws[qi * 12 + j];
                    a0 += wv * pev[j * 64 + d0];
                    a1 += wv * pev[j * 64 + d0 + 1];
                }
                size_t base = (size_t)(b * S_LEN + qb + qi) * DMODEL + h * DHEAD + d0;
                uint32_t hi = pack_bf16(a0, a1);
                __nv_bfloat162 h2 = *(__nv_bfloat162*)&hi;
                uint32_t lo = pack_bf16(a0 - __bfloat162float(h2.x),
                                        a1 - __bfloat162float(h2.y));
                *(uint32_t*)&Oh[base] = hi;
                *(uint32_t*)&Ol[base] = lo;
            }
        }
    }
}

// ---------------------------------------------------------------------------
extern "C" void kernel_launch(void* const* d_in, const int* in_sizes, int n_in,
                              void* d_out, int out_size)
{
    const float* query = (const float*)d_in[0];
    const float* key   = (const float*)d_in[1];
    const float* value = (const float*)d_in[2];
    const int*   mask  = (const int*)d_in[3];
    const float* Wq = (const float*)d_in[4];
    const float* bq = (const float*)d_in[5];
    const float* Wk = (const float*)d_in[6];
    const float* bk = (const float*)d_in[7];
    const float* Wv = (const float*)d_in[8];
    const float* bv = (const float*)d_in[9];
    const float* Wo = (const float*)d_in[10];
    const float* bo = (const float*)d_in[11];
    const float* pe_k = (const float*)d_in[12];
    const float* pe_v = (const float*)d_in[13];

    __nv_bfloat16 *ahi, *alo, *whi, *wlo, *qh, *ql, *kh, *kl, *vh, *vl, *oh, *ol;
    cudaGetSymbolAddress((void**)&ahi, g_act_hi);
    cudaGetSymbolAddress((void**)&alo, g_act_lo);
    cudaGetSymbolAddress((void**)&whi, g_w_hi);
    cudaGetSymbolAddress((void**)&wlo, g_w_lo);
    cudaGetSymbolAddress((void**)&qh, g_qh);
    cudaGetSymbolAddress((void**)&ql, g_ql);
    cudaGetSymbolAddress((void**)&kh, g_kh);
    cudaGetSymbolAddress((void**)&kl, g_kl);
    cudaGetSymbolAddress((void**)&vh, g_vh);
    cudaGetSymbolAddress((void**)&vl, g_vl);
    cudaGetSymbolAddress((void**)&oh, g_oh);
    cudaGetSymbolAddress((void**)&ol, g_ol);

    const long long OUT_ELEMS = (long long)BATCH * S_LEN * DMODEL;
    float* out_ptr  = (float*)d_out;
    float* attn_ptr = ((long long)out_size > OUT_ELEMS) ? (float*)d_out + OUT_ELEMS
                                                        : (float*)0;

    cudaFuncSetAttribute(attn_mma, cudaFuncAttributeMaxDynamicSharedMemorySize,
                         ATT_SMEM);
    cudaFuncSetAttribute(gemm_mma, cudaFuncAttributeMaxDynamicSharedMemorySize,
                         GEMM_SMEM);

    const int ACT4 = MROWS * DMODEL / 4;
    const int W4   = DMODEL * DMODEL / 4;
    dim3 gg(DMODEL / 128, MROWS / 128);

    split_bf16_kernel<<<ACT4 / 256, 256>>>(query, ahi, alo, ACT4);
    split_bf16_kernel<<<W4 / 256, 256>>>(Wq, whi, wlo, W4);
    gemm_mma<<<gg, 256, GEMM_SMEM>>>(ahi, alo, whi, wlo, bq, (float*)0, qh, ql, 0.125f);
    split_bf16_kernel<<<ACT4 / 256, 256>>>(key, ahi, alo, ACT4);
    split_bf16_kernel<<<W4 / 256, 256>>>(Wk, whi, wlo, W4);
    gemm_mma<<<gg, 256, GEMM_SMEM>>>(ahi, alo, whi, wlo, bk, (float*)0, kh, kl, 1.0f);
    split_bf16_kernel<<<ACT4 / 256, 256>>>(value, ahi, alo, ACT4);
    split_bf16_kernel<<<W4 / 256, 256>>>(Wv, whi, wlo, W4);
    gemm_mma<<<gg, 256, GEMM_SMEM>>>(ahi, alo, whi, wlo, bv, (float*)0, vh, vl, 1.0f);

    dim3 ga(S_LEN / QT, NHEAD, BATCH);
    attn_mma<<<ga, 512, ATT_SMEM>>>(qh, ql, kh, kl, vh, vl, mask, pe_k, pe_v,
                                    attn_ptr, oh, ol);

    split_bf16_kernel<<<W4 / 256, 256>>>(Wo, whi, wlo, W4);
    gemm_mma<<<gg, 256, GEMM_SMEM>>>(oh, ol, whi, wlo, bo, out_ptr,
                                     (__nv_bfloat16*)0, (__nv_bfloat16*)0, 1.0f);
}

// round 9
// speedup vs baseline: 3.1905x; 1.1072x over previous
#include <cuda_runtime.h>
#include <cuda_bf16.h>
#include <math.h>
#include <cstdint>

#define BATCH 8
#define S_LEN 1024
#define DMODEL 1024
#define NHEAD 16
#define DHEAD 64
#define MAXK 4
#define MROWS (BATCH * S_LEN)   // 8192

// Scratch (allocation-free rule -> device globals)
__device__ __nv_bfloat16 g_act_hi[(size_t)MROWS * DMODEL];
__device__ __nv_bfloat16 g_act_lo[(size_t)MROWS * DMODEL];
__device__ __nv_bfloat16 g_w_hi[(size_t)DMODEL * DMODEL];
__device__ __nv_bfloat16 g_w_lo[(size_t)DMODEL * DMODEL];
__device__ __nv_bfloat16 g_qh[(size_t)MROWS * DMODEL];
__device__ __nv_bfloat16 g_ql[(size_t)MROWS * DMODEL];
__device__ __nv_bfloat16 g_kh[(size_t)MROWS * DMODEL];
__device__ __nv_bfloat16 g_kl[(size_t)MROWS * DMODEL];
__device__ __nv_bfloat16 g_vh[(size_t)MROWS * DMODEL];
__device__ __nv_bfloat16 g_vl[(size_t)MROWS * DMODEL];
__device__ __nv_bfloat16 g_oh[(size_t)MROWS * DMODEL];
__device__ __nv_bfloat16 g_ol[(size_t)MROWS * DMODEL];

// ---------------------------------------------------------------------------
__device__ __forceinline__ void mma16816(float* c, const uint32_t* a, const uint32_t* b) {
    asm volatile(
        "mma.sync.aligned.m16n8k16.row.col.f32.bf16.bf16.f32 "
        "{%0,%1,%2,%3}, {%4,%5,%6,%7}, {%8,%9}, {%0,%1,%2,%3};"
        : "+f"(c[0]), "+f"(c[1]), "+f"(c[2]), "+f"(c[3])
        : "r"(a[0]), "r"(a[1]), "r"(a[2]), "r"(a[3]), "r"(b[0]), "r"(b[1]));
}
__device__ __forceinline__ uint32_t pack_bf16(float x, float y) {
    __nv_bfloat162 t = __halves2bfloat162(__float2bfloat16(x), __float2bfloat16(y));
    return *(uint32_t*)&t;
}
__device__ __forceinline__ uint32_t smem_u32(const void* p) {
    uint32_t a;
    asm("{ .reg .u64 t; cvta.to.shared.u64 t, %1; cvt.u32.u64 %0, t; }"
        : "=r"(a) : "l"(p));
    return a;
}
__device__ __forceinline__ void ldmx4(uint32_t* r, uint32_t addr) {
    asm volatile("ldmatrix.sync.aligned.m8n8.x4.shared.b16 {%0,%1,%2,%3}, [%4];"
        : "=r"(r[0]), "=r"(r[1]), "=r"(r[2]), "=r"(r[3]) : "r"(addr));
}
__device__ __forceinline__ void ldmx4t(uint32_t* r, uint32_t addr) {
    asm volatile("ldmatrix.sync.aligned.m8n8.x4.trans.shared.b16 {%0,%1,%2,%3}, [%4];"
        : "=r"(r[0]), "=r"(r[1]), "=r"(r[2]), "=r"(r[3]) : "r"(addr));
}
__device__ __forceinline__ void cp_async16(uint32_t d, const void* s) {
    asm volatile("cp.async.cg.shared.global [%0], [%1], 16;" :: "r"(d), "l"(s));
}
#define CP_COMMIT asm volatile("cp.async.commit_group;" ::: "memory")
#define CP_WAIT1  asm volatile("cp.async.wait_group 1;" ::: "memory")
#define CP_WAIT0  asm volatile("cp.async.wait_group 0;" ::: "memory")

// ---------------------------------------------------------------------------
// fp32 -> (bf16 hi, bf16 lo) split
// ---------------------------------------------------------------------------
__global__ void split_bf16_kernel(const float* __restrict__ x,
                                  __nv_bfloat16* __restrict__ hi,
                                  __nv_bfloat16* __restrict__ lo, int n4)
{
    int i = blockIdx.x * blockDim.x + threadIdx.x;
    if (i >= n4) return;
    float4 v = ((const float4*)x)[i];
    __nv_bfloat16 h0 = __float2bfloat16(v.x);
    __nv_bfloat16 h1 = __float2bfloat16(v.y);
    __nv_bfloat16 h2 = __float2bfloat16(v.z);
    __nv_bfloat16 h3 = __float2bfloat16(v.w);
    __nv_bfloat16 l0 = __float2bfloat16(v.x - __bfloat162float(h0));
    __nv_bfloat16 l1 = __float2bfloat16(v.y - __bfloat162float(h1));
    __nv_bfloat16 l2 = __float2bfloat16(v.z - __bfloat162float(h2));
    __nv_bfloat16 l3 = __float2bfloat16(v.w - __bfloat162float(h3));
    __nv_bfloat162* h2p = (__nv_bfloat162*)hi;
    __nv_bfloat162* l2p = (__nv_bfloat162*)lo;
    h2p[i * 2 + 0] = __halves2bfloat162(h0, h1);
    h2p[i * 2 + 1] = __halves2bfloat162(h2, h3);
    l2p[i * 2 + 0] = __halves2bfloat162(l0, l1);
    l2p[i * 2 + 1] = __halves2bfloat162(l2, l3);
}

// ---------------------------------------------------------------------------
// Pipelined HMMA GEMM (unchanged from R6, passing)
// ---------------------------------------------------------------------------
#define LDT 40
#define TILE_B (128 * LDT * 2)
#define STAGE_B (4 * TILE_B)
#define GEMM_SMEM (2 * STAGE_B)

__global__ __launch_bounds__(256, 2)
void gemm_mma(const __nv_bfloat16* __restrict__ Ahi, const __nv_bfloat16* __restrict__ Alo,
              const __nv_bfloat16* __restrict__ Whi, const __nv_bfloat16* __restrict__ Wlo,
              const float* __restrict__ bias, float* __restrict__ C,
              __nv_bfloat16* __restrict__ Chi, __nv_bfloat16* __restrict__ Clo,
              float alpha)
{
    extern __shared__ char smem[];
    const uint32_t sb = smem_u32(smem);

    const int tid = threadIdx.x;
    const int wid = tid >> 5;
    const int lane = tid & 31;
    const int wm = wid >> 2;
    const int wn = wid & 3;
    const int m0 = blockIdx.y * 128;
    const int n0 = blockIdx.x * 128;

    float acc[4][4][4];
#pragma unroll
    for (int i = 0; i < 4; i++)
#pragma unroll
        for (int j = 0; j < 4; j++)
#pragma unroll
            for (int k = 0; k < 4; k++) acc[i][j][k] = 0.f;

    const int lr = lane >> 2;
    const int lc = lane & 3;

    const int r0i = tid >> 2, c0i = tid & 3;
    const int r1i = (tid + 256) >> 2, c1i = tid & 3;

    const int aRow = wm * 64 + (lane & 15);
    const int aColB = ((lane >> 4) << 3) * 2;
    const int bRow = wn * 32 + ((lane >> 4) << 3) + (lane & 7);
    const int bColB = (((lane >> 3) & 1) << 3) * 2;

#define ISSUE(K0, ST) do {                                                     \
    uint32_t sd = sb + (ST) * STAGE_B;                                         \
    size_t g0 = (size_t)(m0 + r0i) * DMODEL + (K0) + c0i * 8;                  \
    size_t g1 = (size_t)(m0 + r1i) * DMODEL + (K0) + c1i * 8;                  \
    size_t h0 = (size_t)(n0 + r0i) * DMODEL + (K0) + c0i * 8;                  \
    size_t h1 = (size_t)(n0 + r1i) * DMODEL + (K0) + c1i * 8;                  \
    uint32_t d0 = r0i * (LDT * 2) + c0i * 16;                                  \
    uint32_t d1 = r1i * (LDT * 2) + c1i * 16;                                  \
    cp_async16(sd + 0 * TILE_B + d0, Ahi + g0);                                \
    cp_async16(sd + 0 * TILE_B + d1, Ahi + g1);                                \
    cp_async16(sd + 1 * TILE_B + d0, Alo + g0);                                \
    cp_async16(sd + 1 * TILE_B + d1, Alo + g1);                                \
    cp_async16(sd + 2 * TILE_B + d0, Whi + h0);                                \
    cp_async16(sd + 2 * TILE_B + d1, Whi + h1);                                \
    cp_async16(sd + 3 * TILE_B + d0, Wlo + h0);                                \
    cp_async16(sd + 3 * TILE_B + d1, Wlo + h1);                                \
} while (0)

    ISSUE(0, 0);
    CP_COMMIT;

    for (int it = 0; it < DMODEL / 32; it++) {
        if (it + 1 < DMODEL / 32) ISSUE((it + 1) * 32, (it + 1) & 1);
        CP_COMMIT;
        CP_WAIT1;
        __syncthreads();

        const uint32_t st = sb + (it & 1) * STAGE_B;
        const uint32_t aHiB = st + 0 * TILE_B;
        const uint32_t aLoB = st + 1 * TILE_B;
        const uint32_t wHiB = st + 2 * TILE_B;
        const uint32_t wLoB = st + 3 * TILE_B;

#pragma unroll
        for (int ks = 0; ks < 2; ks++) {
            const uint32_t acol = ks * 32 + aColB;
            const uint32_t bcol = ks * 32 + bColB;

            uint32_t bh[2][4], bl[2][4];
#pragma unroll
            for (int nip = 0; nip < 2; nip++) {
                uint32_t boff = (uint32_t)(bRow + nip * 16) * (LDT * 2) + bcol;
                ldmx4(bh[nip], wHiB + boff);
                ldmx4(bl[nip], wLoB + boff);
            }
#pragma unroll
            for (int mi = 0; mi < 4; mi++) {
                uint32_t aoff = (uint32_t)(aRow + mi * 16) * (LDT * 2) + acol;
                uint32_t a[4];
                ldmx4(a, aHiB + aoff);
#pragma unroll
                for (int nip = 0; nip < 2; nip++) {
                    mma16816(acc[mi][2 * nip + 0], a, &bh[nip][0]);
                    mma16816(acc[mi][2 * nip + 1], a, &bh[nip][2]);
                    mma16816(acc[mi][2 * nip + 0], a, &bl[nip][0]);
                    mma16816(acc[mi][2 * nip + 1], a, &bl[nip][2]);
                }
                ldmx4(a, aLoB + aoff);
#pragma unroll
                for (int nip = 0; nip < 2; nip++) {
                    mma16816(acc[mi][2 * nip + 0], a, &bh[nip][0]);
                    mma16816(acc[mi][2 * nip + 1], a, &bh[nip][2]);
                }
            }
        }
        __syncthreads();
    }
#undef ISSUE

#pragma unroll
    for (int mi = 0; mi < 4; mi++) {
        int row = m0 + wm * 64 + mi * 16 + lr;
#pragma unroll
        for (int ni = 0; ni < 4; ni++) {
            int col = n0 + wn * 32 + ni * 8 + lc * 2;
            float2 b2 = *(const float2*)&bias[col];
            float v0x = alpha * (acc[mi][ni][0] + b2.x);
            float v0y = alpha * (acc[mi][ni][1] + b2.y);
            float v1x = alpha * (acc[mi][ni][2] + b2.x);
            float v1y = alpha * (acc[mi][ni][3] + b2.y);
            size_t p0 = (size_t)row * DMODEL + col;
            size_t p1 = (size_t)(row + 8) * DMODEL + col;
            if (C) {
                *(float2*)&C[p0] = make_float2(v0x, v0y);
                *(float2*)&C[p1] = make_float2(v1x, v1y);
            }
            if (Chi) {
                uint32_t h0 = pack_bf16(v0x, v0y);
                uint32_t h1 = pack_bf16(v1x, v1y);
                *(uint32_t*)&Chi[p0] = h0;
                *(uint32_t*)&Chi[p1] = h1;
                __nv_bfloat162 hh0 = *(__nv_bfloat162*)&h0;
                __nv_bfloat162 hh1 = *(__nv_bfloat162*)&h1;
                *(uint32_t*)&Clo[p0] = pack_bf16(v0x - __bfloat162float(hh0.x),
                                                 v0y - __bfloat162float(hh0.y));
                *(uint32_t*)&Clo[p1] = pack_bf16(v1x - __bfloat162float(hh1.x),
                                                 v1y - __bfloat162float(hh1.y));
            }
        }
    }
}

// ---------------------------------------------------------------------------
// Fused HMMA attention v4: QT=16, 512 threads, single-buffered K/V tiles
// ("frags-to-regs then issue next" pipelining), 2 CTAs/SM.
// ---------------------------------------------------------------------------
#define QT 16
#define O_SC   0                          // 16 rows x 4096 B = 65536
#define O_QH   65536                      // 2304
#define O_QL   67840                      // 2304
#define O_KB   70144                      // 36864 (single K/V stage)
#define O_PEK  107008                     // 2304
#define O_PEV  109312                     // 2304
#define O_RB   111616                     // 768
#define O_WS   112384                     // 768
#define O_MSK  113152                     // 1024 (uint8 mask)
#define ATT_SMEM 114176

__global__ __launch_bounds__(512, 2)
void attn_mma(const __nv_bfloat16* __restrict__ qh, const __nv_bfloat16* __restrict__ ql,
              const __nv_bfloat16* __restrict__ kh, const __nv_bfloat16* __restrict__ kl,
              const __nv_bfloat16* __restrict__ vh, const __nv_bfloat16* __restrict__ vl,
              const int* __restrict__ mask, const float* __restrict__ pe_k,
              const float* __restrict__ pe_v, float* __restrict__ attn_out,
              __nv_bfloat16* __restrict__ Oh, __nv_bfloat16* __restrict__ Ol)
{
    extern __shared__ char smem[];
    const uint32_t sb = smem_u32(smem);
    float* sc = (float*)smem;
    __nv_bfloat16* QH = (__nv_bfloat16*)(smem + O_QH);
    __nv_bfloat16* QL = (__nv_bfloat16*)(smem + O_QL);
    float* pek = (float*)(smem + O_PEK);
    float* pev = (float*)(smem + O_PEV);
    float* rb  = (float*)(smem + O_RB);
    float* ws  = (float*)(smem + O_WS);
    unsigned char* msk = (unsigned char*)(smem + O_MSK);

    const int b  = blockIdx.z;
    const int h  = blockIdx.y;
    const int qb = blockIdx.x * QT;
    const int tid = threadIdx.x;
    const int w = tid >> 5;
    const int lane = tid & 31;
    const int lr = lane >> 2;
    const int lc = lane & 3;

    // K/V copy indices: rows via 2 positions per thread
    const int liR0 = tid >> 3, liD0 = tid & 7;          // rows 0..63
    const int liR1 = (tid + 512) >> 3, liD1 = tid & 7;  // rows 64..127

    // K tile: hi at +0, lo at +18432 (contiguous 128 rows x 144B)
#define ISSUE_K(KB) do {                                                       \
    uint32_t sd = sb + O_KB;                                                   \
    size_t gA = (size_t)(b * S_LEN + (KB) * 128 + liR0) * DMODEL               \
              + h * DHEAD + liD0 * 8;                                          \
    size_t gB = (size_t)(b * S_LEN + (KB) * 128 + liR1) * DMODEL               \
              + h * DHEAD + liD1 * 8;                                          \
    uint32_t dA = (uint32_t)(liR0 * 72 + liD0 * 8) * 2;                        \
    uint32_t dB = (uint32_t)(liR1 * 72 + liD1 * 8) * 2;                        \
    cp_async16(sd + dA, kh + gA);                                              \
    cp_async16(sd + dB, kh + gB);                                              \
    cp_async16(sd + 18432 + dA, kl + gA);                                      \
    cp_async16(sd + 18432 + dB, kl + gB);                                      \
} while (0)

    // V tile: subtile (row>>6)*18432; hi at +0, lo at +9216 within subtile
#define ISSUE_V(VB) do {                                                       \
    uint32_t sd = sb + O_KB;                                                   \
    size_t gA = (size_t)(b * S_LEN + (VB) * 128 + liR0) * DMODEL               \
              + h * DHEAD + liD0 * 8;                                          \
    size_t gB = (size_t)(b * S_LEN + (VB) * 128 + liR1) * DMODEL               \
              + h * DHEAD + liD1 * 8;                                          \
    uint32_t dA = (uint32_t)((liR0 >> 6) * 18432 + ((liR0 & 63) * 72 + liD0 * 8) * 2); \
    uint32_t dB = (uint32_t)((liR1 >> 6) * 18432 + ((liR1 & 63) * 72 + liD1 * 8) * 2); \
    cp_async16(sd + dA, vh + gA);                                              \
    cp_async16(sd + dB, vh + gB);                                              \
    cp_async16(sd + 9216 + dA, vl + gA);                                       \
    cp_async16(sd + 9216 + dB, vl + gB);                                       \
} while (0)

    // prefetch K tile 0
    ISSUE_K(0);
    CP_COMMIT;

    // load Q tile (16 rows x 8 chunks), pe tables, mask
    if (tid < 128) {
        int row = tid >> 3, dg = tid & 7;
        size_t g = (size_t)(b * S_LEN + qb + row) * DMODEL + h * DHEAD + dg * 8;
        *(uint4*)&QH[row * 72 + dg * 8] = *(const uint4*)&qh[g];
        *(uint4*)&QL[row * 72 + dg * 8] = *(const uint4*)&ql[g];
    }
    for (int i = tid; i < 576; i += 512) { pek[i] = pe_k[i]; pev[i] = pe_v[i]; }
    for (int i = tid; i < S_LEN; i += 512)
        msk[i] = (unsigned char)(mask[b * S_LEN + i] != 0);
    __syncthreads();

    for (int i = tid; i < QT * 9; i += 512) {
        int qi = i / 9, j = i % 9;
        float s = 0.f;
        const __nv_bfloat16* qhr = QH + qi * 72;
        const __nv_bfloat16* qlr = QL + qi * 72;
        const float* pr = pek + j * 64;
#pragma unroll 16
        for (int d = 0; d < 64; d++)
            s += (__bfloat162float(qhr[d]) + __bfloat162float(qlr[d])) * pr[d];
        rb[qi * 12 + j] = s;
    }

    // hoist Q fragments (16 rows: single m16 tile)
    uint32_t qah[4][4], qal[4][4];
#pragma unroll
    for (int ks = 0; ks < 4; ks++) {
        int kc = ks * 16 + lc * 2;
        qah[ks][0] = *(const uint32_t*)&QH[lr * 72 + kc];
        qah[ks][1] = *(const uint32_t*)&QH[(lr + 8) * 72 + kc];
        qah[ks][2] = *(const uint32_t*)&QH[lr * 72 + kc + 8];
        qah[ks][3] = *(const uint32_t*)&QH[(lr + 8) * 72 + kc + 8];
        qal[ks][0] = *(const uint32_t*)&QL[lr * 72 + kc];
        qal[ks][1] = *(const uint32_t*)&QL[(lr + 8) * 72 + kc];
        qal[ks][2] = *(const uint32_t*)&QL[lr * 72 + kc + 8];
        qal[ks][3] = *(const uint32_t*)&QL[(lr + 8) * 72 + kc + 8];
    }

    // ---- scores: 8 tiles of 128 k-cols; single buffer, frags-to-regs ----
    const int n0 = w * 8;
    for (int kb = 0; kb < 8; kb++) {
        CP_WAIT0;
        __syncthreads();

        const uint32_t kt = sb + O_KB;
        uint32_t bh2[2][4], bl2[2][4];
#pragma unroll
        for (int j = 0; j < 2; j++) {
            uint32_t addr = kt + (uint32_t)(n0 + (lane & 7)) * 144
                          + j * 64 + (lane >> 3) * 16;
            ldmx4(bh2[j], addr);
            ldmx4(bl2[j], addr + 18432);
        }
        __syncthreads();
        if (kb + 1 < 8) { ISSUE_K(kb + 1); } else { ISSUE_V(0); }
        CP_COMMIT;

        float c[4] = {0.f, 0.f, 0.f, 0.f};
#pragma unroll
        for (int ks = 0; ks < 4; ks++) {
            uint32_t* bh = &bh2[ks >> 1][(ks & 1) * 2];
            uint32_t* bl = &bl2[ks >> 1][(ks & 1) * 2];
            mma16816(c, qah[ks], bh);
            mma16816(c, qah[ks], bl);
            mma16816(c, qal[ks], bh);
        }
#pragma unroll
        for (int half = 0; half < 2; half++) {
            int qi = lr + half * 8;
            int qg = qb + qi;
            int kg = kb * 128 + n0 + lc * 2;
            float v0 = c[half * 2 + 0];
            float v1 = c[half * 2 + 1];
            int d0 = min(MAXK, max(-MAXK, kg - qg)) + MAXK;
            int d1 = min(MAXK, max(-MAXK, kg + 1 - qg)) + MAXK;
            v0 = msk[kg] ? v0 + rb[qi * 12 + d0] : -INFINITY;
            v1 = msk[kg + 1] ? v1 + rb[qi * 12 + d1] : -INFINITY;
            *(float2*)&sc[qi * S_LEN + kg] = make_float2(v0, v1);
        }
    }
    __syncthreads();

    // ---- softmax: warp w -> row w (V tile 0 loading in background) ----
    {
        int qi = w;
        int qg = qb + qi;
        float* row = sc + qi * S_LEN;

        float m = -INFINITY;
        for (int k2 = lane; k2 < S_LEN; k2 += 32) m = fmaxf(m, row[k2]);
#pragma unroll
        for (int o = 16; o; o >>= 1) m = fmaxf(m, __shfl_xor_sync(0xFFFFFFFFu, m, o));

        float sum = 0.f;
        for (int k2 = lane; k2 < S_LEN; k2 += 32) {
            float e = __expf(row[k2] - m);
            row[k2] = e;
            sum += e;
        }
#pragma unroll
        for (int o = 16; o; o >>= 1) sum += __shfl_xor_sync(0xFFFFFFFFu, sum, o);
        float inv = 1.f / sum;

        float* ao = attn_out ? attn_out + ((size_t)(b * NHEAD + h) * S_LEN + qg) * S_LEN
                             : (float*)0;
        float w0 = 0.f, w8 = 0.f;
        for (int k2 = lane; k2 < S_LEN; k2 += 32) {
            float p = row[k2] * inv;
            row[k2] = p;
            if (ao) ao[k2] = p;
            if (k2 <= qg - MAXK) w0 += p;
            if (k2 >= qg + MAXK) w8 += p;
        }
#pragma unroll
        for (int o = 16; o; o >>= 1) {
            w0 += __shfl_xor_sync(0xFFFFFFFFu, w0, o);
            w8 += __shfl_xor_sync(0xFFFFFFFFu, w8, o);
        }
        __syncwarp();
        if (lane == 0) { ws[qi * 12 + 0] = w0; ws[qi * 12 + 8] = w8; }
        if (lane >= 1 && lane <= 7) {
            int k2 = qg + lane - MAXK;
            ws[qi * 12 + lane] = (k2 >= 0 && k2 < S_LEN) ? row[k2] : 0.f;
        }
        __syncwarp();

        // conflict-free in-place convert: j = lane + 32*t, float2 reads,
        // uint32 writes at 4j^swz (hi) / +2048 (lo)
        float x[32];
#pragma unroll
        for (int t = 0; t < 16; t++) {
            float2 v = *(const float2*)(row + 2 * (lane + 32 * t));
            x[2 * t] = v.x;
            x[2 * t + 1] = v.y;
        }
        __syncwarp();
        uint32_t swz = (uint32_t)((qi & 7) << 4);
        char* rowb = smem + qi * 4096;
#pragma unroll
        for (int t = 0; t < 16; t++) {
            int j = lane + 32 * t;
            float a = x[2 * t], bb = x[2 * t + 1];
            uint32_t hi = pack_bf16(a, bb);
            __nv_bfloat162 h2 = *(__nv_bfloat162*)&hi;
            uint32_t lo = pack_bf16(a - __bfloat162float(h2.x),
                                    bb - __bfloat162float(h2.y));
            *(uint32_t*)(rowb + (((uint32_t)(4 * j)) ^ swz)) = hi;
            *(uint32_t*)(rowb + 2048 + (((uint32_t)(4 * j)) ^ swz)) = lo;
        }
    }

    // ---- PV: two vb-parity groups, warp (g, wn) covers d-cols wn*8..+7 ----
    const int g = w >> 3;
    const int wn = w & 7;
    float o[4] = {0.f, 0.f, 0.f, 0.f};

    for (int vbi = 0; vbi < 8; vbi++) {
        CP_WAIT0;
        __syncthreads();

        const int vb = vbi * 2 + g;
        const uint32_t vtile = sb + O_KB + g * 18432;

        uint32_t bh2[2][4], bl2[2][4];
#pragma unroll
        for (int j = 0; j < 2; j++) {
            uint32_t addr = vtile + (uint32_t)(j * 32 + lane) * 144 + wn * 16;
            ldmx4t(bh2[j], addr);
            ldmx4t(bl2[j], addr + 9216);
        }
        __syncthreads();
        if (vbi + 1 < 8) { ISSUE_V(vbi + 1); CP_COMMIT; }

#pragma unroll
        for (int ks = 0; ks < 4; ks++) {
            uint32_t* bh = &bh2[ks >> 1][(ks & 1) * 2];
            uint32_t* bl = &bl2[ks >> 1][(ks & 1) * 2];
            uint32_t kby = (uint32_t)(vb * 128 + ks * 32 + (lane >> 4) * 16);
            int prow = (lane & 7) + ((lane >> 3) & 1) * 8;
            uint32_t cby = kby ^ ((uint32_t)(prow & 7) << 4);
            uint32_t pa = sb + (uint32_t)prow * 4096 + cby;
            uint32_t ah[4], al[4];
            ldmx4(ah, pa);
            ldmx4(al, pa + 2048);
            mma16816(o, ah, bh);
            mma16816(o, ah, bl);
            mma16816(o, al, bh);
        }
    }

    // ---- cross-group reduce + epilogue (group 0 writes) ----
    __syncthreads();
    float* red = (float*)(smem + O_QH);   // Q no longer needed (4 KB fits)
    if (g == 1) {
        int widx = wn * 32 + lane;
#pragma unroll
        for (int j = 0; j < 4; j++) red[widx * 4 + j] = o[j];
    }
    __syncthreads();
    if (g == 0) {
        int widx = wn * 32 + lane;
#pragma unroll
        for (int j = 0; j < 4; j++) o[j] += red[widx * 4 + j];

#pragma unroll
        for (int half = 0; half < 2; half++) {
            int qi = lr + half * 8;
            int d0 = wn * 8 + lc * 2;
            float a0 = o[half * 2 + 0];
            float a1 = o[half * 2 + 1];
#pragma unroll
            for (int j = 0; j < 9; j++) {
                float wv = ws[qi * 12 + j];
                a0 += wv * pev[j * 64 + d0];
                a1 += wv * pev[j * 64 + d0 + 1];
            }
            size_t base = (size_t)(b * S_LEN + qb + qi) * DMODEL + h * DHEAD + d0;
            uint32_t hi = pack_bf16(a0, a1);
            __nv_bfloat162 h2 = *(__nv_bfloat162*)&hi;
            uint32_t lo = pack_bf16(a0 - __bfloat162float(h2.x),
                                    a1 - __bfloat162float(h2.y));
            *(uint32_t*)&Oh[base] = hi;
            *(uint32_t*)&Ol[base] = lo;
        }
    }
}

// ---------------------------------------------------------------------------
extern "C" void kernel_launch(void* const* d_in, const int* in_sizes, int n_in,
                              void* d_out, int out_size)
{
    const float* query = (const float*)d_in[0];
    const float* key   = (const float*)d_in[1];
    const float* value = (const float*)d_in[2];
    const int*   mask  = (const int*)d_in[3];
    const float* Wq = (const float*)d_in[4];
    const float* bq = (const float*)d_in[5];
    const float* Wk = (const float*)d_in[6];
    const float* bk = (const float*)d_in[7];
    const float* Wv = (const float*)d_in[8];
    const float* bv = (const float*)d_in[9];
    const float* Wo = (const float*)d_in[10];
    const float* bo = (const float*)d_in[11];
    const float* pe_k = (const float*)d_in[12];
    const float* pe_v = (const float*)d_in[13];

    __nv_bfloat16 *ahi, *alo, *whi, *wlo, *qh, *ql, *kh, *kl, *vh, *vl, *oh, *ol;
    cudaGetSymbolAddress((void**)&ahi, g_act_hi);
    cudaGetSymbolAddress((void**)&alo, g_act_lo);
    cudaGetSymbolAddress((void**)&whi, g_w_hi);
    cudaGetSymbolAddress((void**)&wlo, g_w_lo);
    cudaGetSymbolAddress((void**)&qh, g_qh);
    cudaGetSymbolAddress((void**)&ql, g_ql);
    cudaGetSymbolAddress((void**)&kh, g_kh);
    cudaGetSymbolAddress((void**)&kl, g_kl);
    cudaGetSymbolAddress((void**)&vh, g_vh);
    cudaGetSymbolAddress((void**)&vl, g_vl);
    cudaGetSymbolAddress((void**)&oh, g_oh);
    cudaGetSymbolAddress((void**)&ol, g_ol);

    const long long OUT_ELEMS = (long long)BATCH * S_LEN * DMODEL;
    float* out_ptr  = (float*)d_out;
    float* attn_ptr = ((long long)out_size > OUT_ELEMS) ? (float*)d_out + OUT_ELEMS
                                                        : (float*)0;

    cudaFuncSetAttribute(attn_mma, cudaFuncAttributeMaxDynamicSharedMemorySize,
                         ATT_SMEM);
    cudaFuncSetAttribute(gemm_mma, cudaFuncAttributeMaxDynamicSharedMemorySize,
                         GEMM_SMEM);

    const int ACT4 = MROWS * DMODEL / 4;
    const int W4   = DMODEL * DMODEL / 4;
    dim3 gg(DMODEL / 128, MROWS / 128);

    split_bf16_kernel<<<ACT4 / 256, 256>>>(query, ahi, alo, ACT4);
    split_bf16_kernel<<<W4 / 256, 256>>>(Wq, whi, wlo, W4);
    gemm_mma<<<gg, 256, GEMM_SMEM>>>(ahi, alo, whi, wlo, bq, (float*)0, qh, ql, 0.125f);
    split_bf16_kernel<<<ACT4 / 256, 256>>>(key, ahi, alo, ACT4);
    split_bf16_kernel<<<W4 / 256, 256>>>(Wk, whi, wlo, W4);
    gemm_mma<<<gg, 256, GEMM_SMEM>>>(ahi, alo, whi, wlo, bk, (float*)0, kh, kl, 1.0f);
    split_bf16_kernel<<<ACT4 / 256, 256>>>(value, ahi, alo, ACT4);
    split_bf16_kernel<<<W4 / 256, 256>>>(Wv, whi, wlo, W4);
    gemm_mma<<<gg, 256, GEMM_SMEM>>>(ahi, alo, whi, wlo, bv, (float*)0, vh, vl, 1.0f);

    dim3 ga(S_LEN / QT, NHEAD, BATCH);   // (64, 16, 8)
    attn_mma<<<ga, 512, ATT_SMEM>>>(qh, ql, kh, kl, vh, vl, mask, pe_k, pe_v,
                                    attn_ptr, oh, ol);

    split_bf16_kernel<<<W4 / 256, 256>>>(Wo, whi, wlo, W4);
    gemm_mma<<<gg, 256, GEMM_SMEM>>>(oh, ol, whi, wlo, bo, out_ptr,
                                     (__nv_bfloat16*)0, (__nv_bfloat16*)0, 1.0f);
}

// round 10
// speedup vs baseline: 4.1109x; 1.2885x over previous
#include <cuda_runtime.h>
#include <cuda_fp16.h>
#include <math.h>
#include <cstdint>

#define BATCH 8
#define S_LEN 1024
#define DMODEL 1024
#define NHEAD 16
#define DHEAD 64
#define MAXK 4
#define MROWS (BATCH * S_LEN)   // 8192

// Scratch (allocation-free rule -> device globals)
__device__ __half g_act[(size_t)MROWS * DMODEL];
__device__ __half g_w_hi[(size_t)DMODEL * DMODEL];
__device__ __half g_w_lo[(size_t)DMODEL * DMODEL];
__device__ __half g_qh[(size_t)MROWS * DMODEL];
__device__ __half g_kh[(size_t)MROWS * DMODEL];
__device__ __half g_kl[(size_t)MROWS * DMODEL];
__device__ __half g_vh[(size_t)MROWS * DMODEL];
__device__ __half g_vl[(size_t)MROWS * DMODEL];
__device__ __half g_oh[(size_t)MROWS * DMODEL];

// ---------------------------------------------------------------------------
__device__ __forceinline__ void mma16816(float* c, const uint32_t* a, const uint32_t* b) {
    asm volatile(
        "mma.sync.aligned.m16n8k16.row.col.f32.f16.f16.f32 "
        "{%0,%1,%2,%3}, {%4,%5,%6,%7}, {%8,%9}, {%0,%1,%2,%3};"
        : "+f"(c[0]), "+f"(c[1]), "+f"(c[2]), "+f"(c[3])
        : "r"(a[0]), "r"(a[1]), "r"(a[2]), "r"(a[3]), "r"(b[0]), "r"(b[1]));
}
__device__ __forceinline__ uint32_t pack_h(float x, float y) {
    __half2 t = __floats2half2_rn(x, y);
    return *(uint32_t*)&t;
}
__device__ __forceinline__ uint32_t smem_u32(const void* p) {
    uint32_t a;
    asm("{ .reg .u64 t; cvta.to.shared.u64 t, %1; cvt.u32.u64 %0, t; }"
        : "=r"(a) : "l"(p));
    return a;
}
__device__ __forceinline__ void ldmx4(uint32_t* r, uint32_t addr) {
    asm volatile("ldmatrix.sync.aligned.m8n8.x4.shared.b16 {%0,%1,%2,%3}, [%4];"
        : "=r"(r[0]), "=r"(r[1]), "=r"(r[2]), "=r"(r[3]) : "r"(addr));
}
__device__ __forceinline__ void ldmx4t(uint32_t* r, uint32_t addr) {
    asm volatile("ldmatrix.sync.aligned.m8n8.x4.trans.shared.b16 {%0,%1,%2,%3}, [%4];"
        : "=r"(r[0]), "=r"(r[1]), "=r"(r[2]), "=r"(r[3]) : "r"(addr));
}
__device__ __forceinline__ void cp_async16(uint32_t d, const void* s) {
    asm volatile("cp.async.cg.shared.global [%0], [%1], 16;" :: "r"(d), "l"(s));
}
#define CP_COMMIT asm volatile("cp.async.commit_group;" ::: "memory")
#define CP_WAIT1  asm volatile("cp.async.wait_group 1;" ::: "memory")
#define CP_WAIT0  asm volatile("cp.async.wait_group 0;" ::: "memory")

// ---------------------------------------------------------------------------
// fp32 -> (fp16 hi, fp16 lo) split (weights / B-side operands)
// ---------------------------------------------------------------------------
__global__ void split_h_kernel(const float* __restrict__ x,
                               __half* __restrict__ hi,
                               __half* __restrict__ lo, int n4)
{
    int i = blockIdx.x * blockDim.x + threadIdx.x;
    if (i >= n4) return;
    float4 v = ((const float4*)x)[i];
    __half h0 = __float2half_rn(v.x);
    __half h1 = __float2half_rn(v.y);
    __half h2 = __float2half_rn(v.z);
    __half h3 = __float2half_rn(v.w);
    __half l0 = __float2half_rn(v.x - __half2float(h0));
    __half l1 = __float2half_rn(v.y - __half2float(h1));
    __half l2 = __float2half_rn(v.z - __half2float(h2));
    __half l3 = __float2half_rn(v.w - __half2float(h3));
    __half2* h2p = (__half2*)hi;
    __half2* l2p = (__half2*)lo;
    h2p[i * 2 + 0] = __halves2half2(h0, h1);
    h2p[i * 2 + 1] = __halves2half2(h2, h3);
    l2p[i * 2 + 0] = __halves2half2(l0, l1);
    l2p[i * 2 + 1] = __halves2half2(l2, l3);
}

// fp32 -> fp16 (A-side activations: hi only)
__global__ void conv_h_kernel(const float* __restrict__ x,
                              __half* __restrict__ hi, int n4)
{
    int i = blockIdx.x * blockDim.x + threadIdx.x;
    if (i >= n4) return;
    float4 v = ((const float4*)x)[i];
    __half2* h2p = (__half2*)hi;
    h2p[i * 2 + 0] = __floats2half2_rn(v.x, v.y);
    h2p[i * 2 + 1] = __floats2half2_rn(v.z, v.w);
}

// ---------------------------------------------------------------------------
// Pipelined HMMA GEMM (fp16, asymmetric 2-pass): C = alpha*(A @ W^T + bias)
// A fp16 (hi only), W split hi/lo. D = A*Whi + A*Wlo.
// Tile 128x128, BK=32, 8 warps (2M x 4N), cp.async 2-stage, ldmatrix frags.
// ---------------------------------------------------------------------------
#define LDT 40
#define TILE_B (128 * LDT * 2)      // 10240
#define STAGE_B (3 * TILE_B)        // 30720 (A, Whi, Wlo)
#define GEMM_SMEM (2 * STAGE_B)     // 61440

__global__ __launch_bounds__(256, 2)
void gemm_mma(const __half* __restrict__ A,
              const __half* __restrict__ Whi, const __half* __restrict__ Wlo,
              const float* __restrict__ bias, float* __restrict__ C,
              __half* __restrict__ Chi, __half* __restrict__ Clo,
              float alpha)
{
    extern __shared__ char smem[];
    const uint32_t sb = smem_u32(smem);

    const int tid = threadIdx.x;
    const int wid = tid >> 5;
    const int lane = tid & 31;
    const int wm = wid >> 2;
    const int wn = wid & 3;
    const int m0 = blockIdx.y * 128;
    const int n0 = blockIdx.x * 128;

    float acc[4][4][4];
#pragma unroll
    for (int i = 0; i < 4; i++)
#pragma unroll
        for (int j = 0; j < 4; j++)
#pragma unroll
            for (int k = 0; k < 4; k++) acc[i][j][k] = 0.f;

    const int lr = lane >> 2;
    const int lc = lane & 3;

    const int r0i = tid >> 2, c0i = tid & 3;
    const int r1i = (tid + 256) >> 2, c1i = tid & 3;

    const int aRow = wm * 64 + (lane & 15);
    const int aColB = ((lane >> 4) << 3) * 2;
    const int bRow = wn * 32 + ((lane >> 4) << 3) + (lane & 7);
    const int bColB = (((lane >> 3) & 1) << 3) * 2;

#define ISSUE(K0, ST) do {                                                     \
    uint32_t sd = sb + (ST) * STAGE_B;                                         \
    size_t g0 = (size_t)(m0 + r0i) * DMODEL + (K0) + c0i * 8;                  \
    size_t g1 = (size_t)(m0 + r1i) * DMODEL + (K0) + c1i * 8;                  \
    size_t h0 = (size_t)(n0 + r0i) * DMODEL + (K0) + c0i * 8;                  \
    size_t h1 = (size_t)(n0 + r1i) * DMODEL + (K0) + c1i * 8;                  \
    uint32_t d0 = r0i * (LDT * 2) + c0i * 16;                                  \
    uint32_t d1 = r1i * (LDT * 2) + c1i * 16;                                  \
    cp_async16(sd + 0 * TILE_B + d0, A + g0);                                  \
    cp_async16(sd + 0 * TILE_B + d1, A + g1);                                  \
    cp_async16(sd + 1 * TILE_B + d0, Whi + h0);                                \
    cp_async16(sd + 1 * TILE_B + d1, Whi + h1);                                \
    cp_async16(sd + 2 * TILE_B + d0, Wlo + h0);                                \
    cp_async16(sd + 2 * TILE_B + d1, Wlo + h1);                                \
} while (0)

    ISSUE(0, 0);
    CP_COMMIT;

    for (int it = 0; it < DMODEL / 32; it++) {
        if (it + 1 < DMODEL / 32) ISSUE((it + 1) * 32, (it + 1) & 1);
        CP_COMMIT;
        CP_WAIT1;
        __syncthreads();

        const uint32_t st = sb + (it & 1) * STAGE_B;
        const uint32_t aB   = st + 0 * TILE_B;
        const uint32_t wHiB = st + 1 * TILE_B;
        const uint32_t wLoB = st + 2 * TILE_B;

#pragma unroll
        for (int ks = 0; ks < 2; ks++) {
            const uint32_t acol = ks * 32 + aColB;
            const uint32_t bcol = ks * 32 + bColB;

            uint32_t bh[2][4], bl[2][4];
#pragma unroll
            for (int nip = 0; nip < 2; nip++) {
                uint32_t boff = (uint32_t)(bRow + nip * 16) * (LDT * 2) + bcol;
                ldmx4(bh[nip], wHiB + boff);
                ldmx4(bl[nip], wLoB + boff);
            }
#pragma unroll
            for (int mi = 0; mi < 4; mi++) {
                uint32_t aoff = (uint32_t)(aRow + mi * 16) * (LDT * 2) + acol;
                uint32_t a[4];
                ldmx4(a, aB + aoff);
#pragma unroll
                for (int nip = 0; nip < 2; nip++) {
                    mma16816(acc[mi][2 * nip + 0], a, &bh[nip][0]);
                    mma16816(acc[mi][2 * nip + 1], a, &bh[nip][2]);
                    mma16816(acc[mi][2 * nip + 0], a, &bl[nip][0]);
                    mma16816(acc[mi][2 * nip + 1], a, &bl[nip][2]);
                }
            }
        }
        __syncthreads();
    }
#undef ISSUE

#pragma unroll
    for (int mi = 0; mi < 4; mi++) {
        int row = m0 + wm * 64 + mi * 16 + lr;
#pragma unroll
        for (int ni = 0; ni < 4; ni++) {
            int col = n0 + wn * 32 + ni * 8 + lc * 2;
            float2 b2 = *(const float2*)&bias[col];
            float v0x = alpha * (acc[mi][ni][0] + b2.x);
            float v0y = alpha * (acc[mi][ni][1] + b2.y);
            float v1x = alpha * (acc[mi][ni][2] + b2.x);
            float v1y = alpha * (acc[mi][ni][3] + b2.y);
            size_t p0 = (size_t)row * DMODEL + col;
            size_t p1 = (size_t)(row + 8) * DMODEL + col;
            if (C) {
                *(float2*)&C[p0] = make_float2(v0x, v0y);
                *(float2*)&C[p1] = make_float2(v1x, v1y);
            }
            if (Chi) {
                uint32_t h0 = pack_h(v0x, v0y);
                uint32_t h1 = pack_h(v1x, v1y);
                *(uint32_t*)&Chi[p0] = h0;
                *(uint32_t*)&Chi[p1] = h1;
                if (Clo) {
                    __half2 hh0 = *(__half2*)&h0;
                    __half2 hh1 = *(__half2*)&h1;
                    *(uint32_t*)&Clo[p0] =
                        pack_h(v0x - __half2float(__low2half(hh0)),
                               v0y - __half2float(__high2half(hh0)));
                    *(uint32_t*)&Clo[p1] =
                        pack_h(v1x - __half2float(__low2half(hh1)),
                               v1y - __half2float(__high2half(hh1)));
                }
            }
        }
    }
}

// ---------------------------------------------------------------------------
// Fused HMMA attention (fp16 2-pass): QT=16, 512 threads, 2 CTAs/SM.
// Q fp16 hi only; K,V split hi/lo; P fp16 hi only.
// ---------------------------------------------------------------------------
#define QT 16
#define O_SC   0                          // 16 rows x 4096 B = 65536
#define O_QH   65536                      // 2304
#define O_KB   70144                      // 36864 (single K/V stage)
#define O_PEK  107008                     // 2304
#define O_PEV  109312                     // 2304
#define O_RB   111616                     // 768
#define O_WS   112384                     // 768
#define O_MSK  113152                     // 1024 (uint8 mask)
#define ATT_SMEM 114176

__global__ __launch_bounds__(512, 2)
void attn_mma(const __half* __restrict__ qh,
              const __half* __restrict__ kh, const __half* __restrict__ kl,
              const __half* __restrict__ vh, const __half* __restrict__ vl,
              const int* __restrict__ mask, const float* __restrict__ pe_k,
              const float* __restrict__ pe_v, float* __restrict__ attn_out,
              __half* __restrict__ Oh)
{
    extern __shared__ char smem[];
    const uint32_t sb = smem_u32(smem);
    float* sc = (float*)smem;
    __half* QH = (__half*)(smem + O_QH);
    float* pek = (float*)(smem + O_PEK);
    float* pev = (float*)(smem + O_PEV);
    float* rb  = (float*)(smem + O_RB);
    float* ws  = (float*)(smem + O_WS);
    unsigned char* msk = (unsigned char*)(smem + O_MSK);

    const int b  = blockIdx.z;
    const int h  = blockIdx.y;
    const int qb = blockIdx.x * QT;
    const int tid = threadIdx.x;
    const int w = tid >> 5;
    const int lane = tid & 31;
    const int lr = lane >> 2;
    const int lc = lane & 3;

    const int liR0 = tid >> 3, liD0 = tid & 7;          // rows 0..63
    const int liR1 = (tid + 512) >> 3, liD1 = tid & 7;  // rows 64..127

#define ISSUE_K(KB) do {                                                       \
    uint32_t sd = sb + O_KB;                                                   \
    size_t gA = (size_t)(b * S_LEN + (KB) * 128 + liR0) * DMODEL               \
              + h * DHEAD + liD0 * 8;                                          \
    size_t gB = (size_t)(b * S_LEN + (KB) * 128 + liR1) * DMODEL               \
              + h * DHEAD + liD1 * 8;                                          \
    uint32_t dA = (uint32_t)(liR0 * 72 + liD0 * 8) * 2;                        \
    uint32_t dB = (uint32_t)(liR1 * 72 + liD1 * 8) * 2;                        \
    cp_async16(sd + dA, kh + gA);                                              \
    cp_async16(sd + dB, kh + gB);                                              \
    cp_async16(sd + 18432 + dA, kl + gA);                                      \
    cp_async16(sd + 18432 + dB, kl + gB);                                      \
} while (0)

#define ISSUE_V(VB) do {                                                       \
    uint32_t sd = sb + O_KB;                                                   \
    size_t gA = (size_t)(b * S_LEN + (VB) * 128 + liR0) * DMODEL               \
              + h * DHEAD + liD0 * 8;                                          \
    size_t gB = (size_t)(b * S_LEN + (VB) * 128 + liR1) * DMODEL               \
              + h * DHEAD + liD1 * 8;                                          \
    uint32_t dA = (uint32_t)((liR0 >> 6) * 18432 + ((liR0 & 63) * 72 + liD0 * 8) * 2); \
    uint32_t dB = (uint32_t)((liR1 >> 6) * 18432 + ((liR1 & 63) * 72 + liD1 * 8) * 2); \
    cp_async16(sd + dA, vh + gA);                                              \
    cp_async16(sd + dB, vh + gB);                                              \
    cp_async16(sd + 9216 + dA, vl + gA);                                       \
    cp_async16(sd + 9216 + dB, vl + gB);                                       \
} while (0)

    ISSUE_K(0);
    CP_COMMIT;

    if (tid < 128) {
        int row = tid >> 3, dg = tid & 7;
        size_t g = (size_t)(b * S_LEN + qb + row) * DMODEL + h * DHEAD + dg * 8;
        *(uint4*)&QH[row * 72 + dg * 8] = *(const uint4*)&qh[g];
    }
    for (int i = tid; i < 576; i += 512) { pek[i] = pe_k[i]; pev[i] = pe_v[i]; }
    for (int i = tid; i < S_LEN; i += 512)
        msk[i] = (unsigned char)(mask[b * S_LEN + i] != 0);
    __syncthreads();

    for (int i = tid; i < QT * 9; i += 512) {
        int qi = i / 9, j = i % 9;
        float s = 0.f;
        const __half* qhr = QH + qi * 72;
        const float* pr = pek + j * 64;
#pragma unroll 16
        for (int d = 0; d < 64; d++)
            s += __half2float(qhr[d]) * pr[d];
        rb[qi * 12 + j] = s;
    }

    // hoist Q fragments (hi only)
    uint32_t qah[4][4];
#pragma unroll
    for (int ks = 0; ks < 4; ks++) {
        int kc = ks * 16 + lc * 2;
        qah[ks][0] = *(const uint32_t*)&QH[lr * 72 + kc];
        qah[ks][1] = *(const uint32_t*)&QH[(lr + 8) * 72 + kc];
        qah[ks][2] = *(const uint32_t*)&QH[lr * 72 + kc + 8];
        qah[ks][3] = *(const uint32_t*)&QH[(lr + 8) * 72 + kc + 8];
    }

    // ---- scores: 8 tiles of 128 k-cols; single buffer, frags-to-regs ----
    const int n0 = w * 8;
    for (int kb = 0; kb < 8; kb++) {
        CP_WAIT0;
        __syncthreads();

        const uint32_t kt = sb + O_KB;
        uint32_t bh2[2][4], bl2[2][4];
#pragma unroll
        for (int j = 0; j < 2; j++) {
            uint32_t addr = kt + (uint32_t)(n0 + (lane & 7)) * 144
                          + j * 64 + (lane >> 3) * 16;
            ldmx4(bh2[j], addr);
            ldmx4(bl2[j], addr + 18432);
        }
        __syncthreads();
        if (kb + 1 < 8) { ISSUE_K(kb + 1); } else { ISSUE_V(0); }
        CP_COMMIT;

        float c[4] = {0.f, 0.f, 0.f, 0.f};
#pragma unroll
        for (int ks = 0; ks < 4; ks++) {
            uint32_t* bh = &bh2[ks >> 1][(ks & 1) * 2];
            uint32_t* bl = &bl2[ks >> 1][(ks & 1) * 2];
            mma16816(c, qah[ks], bh);
            mma16816(c, qah[ks], bl);
        }
#pragma unroll
        for (int half = 0; half < 2; half++) {
            int qi = lr + half * 8;
            int qg = qb + qi;
            int kg = kb * 128 + n0 + lc * 2;
            float v0 = c[half * 2 + 0];
            float v1 = c[half * 2 + 1];
            int d0 = min(MAXK, max(-MAXK, kg - qg)) + MAXK;
            int d1 = min(MAXK, max(-MAXK, kg + 1 - qg)) + MAXK;
            v0 = msk[kg] ? v0 + rb[qi * 12 + d0] : -INFINITY;
            v1 = msk[kg + 1] ? v1 + rb[qi * 12 + d1] : -INFINITY;
            *(float2*)&sc[qi * S_LEN + kg] = make_float2(v0, v1);
        }
    }
    __syncthreads();

    // ---- softmax: warp w -> row w (V tile 0 loading in background) ----
    {
        int qi = w;
        int qg = qb + qi;
        float* row = sc + qi * S_LEN;

        float m = -INFINITY;
        for (int k2 = lane; k2 < S_LEN; k2 += 32) m = fmaxf(m, row[k2]);
#pragma unroll
        for (int o = 16; o; o >>= 1) m = fmaxf(m, __shfl_xor_sync(0xFFFFFFFFu, m, o));

        float sum = 0.f;
        for (int k2 = lane; k2 < S_LEN; k2 += 32) {
            float e = __expf(row[k2] - m);
            row[k2] = e;
            sum += e;
        }
#pragma unroll
        for (int o = 16; o; o >>= 1) sum += __shfl_xor_sync(0xFFFFFFFFu, sum, o);
        float inv = 1.f / sum;

        float* ao = attn_out ? attn_out + ((size_t)(b * NHEAD + h) * S_LEN + qg) * S_LEN
                             : (float*)0;
        float w0 = 0.f, w8 = 0.f;
        for (int k2 = lane; k2 < S_LEN; k2 += 32) {
            float p = row[k2] * inv;
            row[k2] = p;
            if (ao) ao[k2] = p;
            if (k2 <= qg - MAXK) w0 += p;
            if (k2 >= qg + MAXK) w8 += p;
        }
#pragma unroll
        for (int o = 16; o; o >>= 1) {
            w0 += __shfl_xor_sync(0xFFFFFFFFu, w0, o);
            w8 += __shfl_xor_sync(0xFFFFFFFFu, w8, o);
        }
        __syncwarp();
        if (lane == 0) { ws[qi * 12 + 0] = w0; ws[qi * 12 + 8] = w8; }
        if (lane >= 1 && lane <= 7) {
            int k2 = qg + lane - MAXK;
            ws[qi * 12 + lane] = (k2 >= 0 && k2 < S_LEN) ? row[k2] : 0.f;
        }
        __syncwarp();

        // conflict-free in-place convert to fp16 hi (swizzled)
        float x[32];
#pragma unroll
        for (int t = 0; t < 16; t++) {
            float2 v = *(const float2*)(row + 2 * (lane + 32 * t));
            x[2 * t] = v.x;
            x[2 * t + 1] = v.y;
        }
        __syncwarp();
        uint32_t swz = (uint32_t)((qi & 7) << 4);
        char* rowb = smem + qi * 4096;
#pragma unroll
        for (int t = 0; t < 16; t++) {
            int j = lane + 32 * t;
            *(uint32_t*)(rowb + (((uint32_t)(4 * j)) ^ swz)) =
                pack_h(x[2 * t], x[2 * t + 1]);
        }
    }

    // ---- PV: two vb-parity groups, warp (g, wn) covers d-cols wn*8..+7 ----
    const int g = w >> 3;
    const int wn = w & 7;
    float o[4] = {0.f, 0.f, 0.f, 0.f};

    for (int vbi = 0; vbi < 8; vbi++) {
        CP_WAIT0;
        __syncthreads();

        const int vb = vbi * 2 + g;
        const uint32_t vtile = sb + O_KB + g * 18432;

        uint32_t bh2[2][4], bl2[2][4];
#pragma unroll
        for (int j = 0; j < 2; j++) {
            uint32_t addr = vtile + (uint32_t)(j * 32 + lane) * 144 + wn * 16;
            ldmx4t(bh2[j], addr);
            ldmx4t(bl2[j], addr + 9216);
        }
        __syncthreads();
        if (vbi + 1 < 8) { ISSUE_V(vbi + 1); CP_COMMIT; }

#pragma unroll
        for (int ks = 0; ks < 4; ks++) {
            uint32_t* bh = &bh2[ks >> 1][(ks & 1) * 2];
            uint32_t* bl = &bl2[ks >> 1][(ks & 1) * 2];
            uint32_t kby = (uint32_t)(vb * 128 + ks * 32 + (lane >> 4) * 16);
            int prow = (lane & 7) + ((lane >> 3) & 1) * 8;
            uint32_t cby = kby ^ ((uint32_t)(prow & 7) << 4);
            uint32_t pa = sb + (uint32_t)prow * 4096 + cby;
            uint32_t ah[4];
            ldmx4(ah, pa);
            mma16816(o, ah, bh);
            mma16816(o, ah, bl);
        }
    }

    // ---- cross-group reduce + epilogue (group 0 writes) ----
    __syncthreads();
    float* red = (float*)(smem + O_QH);
    if (g == 1) {
        int widx = wn * 32 + lane;
#pragma unroll
        for (int j = 0; j < 4; j++) red[widx * 4 + j] = o[j];
    }
    __syncthreads();
    if (g == 0) {
        int widx = wn * 32 + lane;
#pragma unroll
        for (int j = 0; j < 4; j++) o[j] += red[widx * 4 + j];

#pragma unroll
        for (int half = 0; half < 2; half++) {
            int qi = lr + half * 8;
            int d0 = wn * 8 + lc * 2;
            float a0 = o[half * 2 + 0];
            float a1 = o[half * 2 + 1];
#pragma unroll
            for (int j = 0; j < 9; j++) {
                float wv = ws[qi * 12 + j];
                a0 += wv * pev[j * 64 + d0];
                a1 += wv * pev[j * 64 + d0 + 1];
            }
            size_t base = (size_t)(b * S_LEN + qb + qi) * DMODEL + h * DHEAD + d0;
            *(uint32_t*)&Oh[base] = pack_h(a0, a1);
        }
    }
}

// ---------------------------------------------------------------------------
extern "C" void kernel_launch(void* const* d_in, const int* in_sizes, int n_in,
                              void* d_out, int out_size)
{
    const float* query = (const float*)d_in[0];
    const float* key   = (const float*)d_in[1];
    const float* value = (const float*)d_in[2];
    const int*   mask  = (const int*)d_in[3];
    const float* Wq = (const float*)d_in[4];
    const float* bq = (const float*)d_in[5];
    const float* Wk = (const float*)d_in[6];
    const float* bk = (const float*)d_in[7];
    const float* Wv = (const float*)d_in[8];
    const float* bv = (const float*)d_in[9];
    const float* Wo = (const float*)d_in[10];
    const float* bo = (const float*)d_in[11];
    const float* pe_k = (const float*)d_in[12];
    const float* pe_v = (const float*)d_in[13];

    __half *act, *whi, *wlo, *qh, *kh, *kl, *vh, *vl, *oh;
    cudaGetSymbolAddress((void**)&act, g_act);
    cudaGetSymbolAddress((void**)&whi, g_w_hi);
    cudaGetSymbolAddress((void**)&wlo, g_w_lo);
    cudaGetSymbolAddress((void**)&qh, g_qh);
    cudaGetSymbolAddress((void**)&kh, g_kh);
    cudaGetSymbolAddress((void**)&kl, g_kl);
    cudaGetSymbolAddress((void**)&vh, g_vh);
    cudaGetSymbolAddress((void**)&vl, g_vl);
    cudaGetSymbolAddress((void**)&oh, g_oh);

    const long long OUT_ELEMS = (long long)BATCH * S_LEN * DMODEL;
    float* out_ptr  = (float*)d_out;
    float* attn_ptr = ((long long)out_size > OUT_ELEMS) ? (float*)d_out + OUT_ELEMS
                                                        : (float*)0;

    cudaFuncSetAttribute(attn_mma, cudaFuncAttributeMaxDynamicSharedMemorySize,
                         ATT_SMEM);
    cudaFuncSetAttribute(gemm_mma, cudaFuncAttributeMaxDynamicSharedMemorySize,
                         GEMM_SMEM);

    const int ACT4 = MROWS * DMODEL / 4;
    const int W4   = DMODEL * DMODEL / 4;
    dim3 gg(DMODEL / 128, MROWS / 128);

    // Q projection (fold 1/SCALE = 0.125); Q stored hi-only
    conv_h_kernel<<<ACT4 / 256, 256>>>(query, act, ACT4);
    split_h_kernel<<<W4 / 256, 256>>>(Wq, whi, wlo, W4);
    gemm_mma<<<gg, 256, GEMM_SMEM>>>(act, whi, wlo, bq, (float*)0, qh, (__half*)0, 0.125f);
    // K projection (hi+lo)
    conv_h_kernel<<<ACT4 / 256, 256>>>(key, act, ACT4);
    split_h_kernel<<<W4 / 256, 256>>>(Wk, whi, wlo, W4);
    gemm_mma<<<gg, 256, GEMM_SMEM>>>(act, whi, wlo, bk, (float*)0, kh, kl, 1.0f);
    // V projection (hi+lo)
    conv_h_kernel<<<ACT4 / 256, 256>>>(value, act, ACT4);
    split_h_kernel<<<W4 / 256, 256>>>(Wv, whi, wlo, W4);
    gemm_mma<<<gg, 256, GEMM_SMEM>>>(act, whi, wlo, bv, (float*)0, vh, vl, 1.0f);

    // fused attention (writes O hi-only)
    dim3 ga(S_LEN / QT, NHEAD, BATCH);   // (64, 16, 8)
    attn_mma<<<ga, 512, ATT_SMEM>>>(qh, kh, kl, vh, vl, mask, pe_k, pe_v,
                                    attn_ptr, oh);

    // output projection (fp32 out)
    split_h_kernel<<<W4 / 256, 256>>>(Wo, whi, wlo, W4);
    gemm_mma<<<gg, 256, GEMM_SMEM>>>(oh, whi, wlo, bo, out_ptr,
                                     (__half*)0, (__half*)0, 1.0f);
}

// round 11
// speedup vs baseline: 4.9073x; 1.1937x over previous
#include <cuda_runtime.h>
#include <cuda_fp16.h>
#include <math.h>
#include <cstdint>

#define BATCH 8
#define S_LEN 1024
#define DMODEL 1024
#define NHEAD 16
#define DHEAD 64
#define MAXK 4
#define MROWS (BATCH * S_LEN)   // 8192

// Scratch (allocation-free rule -> device globals)
__device__ __half g_act[(size_t)MROWS * DMODEL];
__device__ __half g_w_hi[(size_t)DMODEL * DMODEL];
__device__ __half g_w_lo[(size_t)DMODEL * DMODEL];
__device__ __half g_qh[(size_t)MROWS * DMODEL];
__device__ __half g_kh[(size_t)MROWS * DMODEL];
__device__ __half g_vh[(size_t)MROWS * DMODEL];
__device__ __half g_oh[(size_t)MROWS * DMODEL];

// ---------------------------------------------------------------------------
__device__ __forceinline__ void mma16816(float* c, const uint32_t* a, const uint32_t* b) {
    asm volatile(
        "mma.sync.aligned.m16n8k16.row.col.f32.f16.f16.f32 "
        "{%0,%1,%2,%3}, {%4,%5,%6,%7}, {%8,%9}, {%0,%1,%2,%3};"
        : "+f"(c[0]), "+f"(c[1]), "+f"(c[2]), "+f"(c[3])
        : "r"(a[0]), "r"(a[1]), "r"(a[2]), "r"(a[3]), "r"(b[0]), "r"(b[1]));
}
__device__ __forceinline__ uint32_t pack_h(float x, float y) {
    __half2 t = __floats2half2_rn(x, y);
    return *(uint32_t*)&t;
}
__device__ __forceinline__ uint32_t smem_u32(const void* p) {
    uint32_t a;
    asm("{ .reg .u64 t; cvta.to.shared.u64 t, %1; cvt.u32.u64 %0, t; }"
        : "=r"(a) : "l"(p));
    return a;
}
__device__ __forceinline__ void ldmx4(uint32_t* r, uint32_t addr) {
    asm volatile("ldmatrix.sync.aligned.m8n8.x4.shared.b16 {%0,%1,%2,%3}, [%4];"
        : "=r"(r[0]), "=r"(r[1]), "=r"(r[2]), "=r"(r[3]) : "r"(addr));
}
__device__ __forceinline__ void ldmx4t(uint32_t* r, uint32_t addr) {
    asm volatile("ldmatrix.sync.aligned.m8n8.x4.trans.shared.b16 {%0,%1,%2,%3}, [%4];"
        : "=r"(r[0]), "=r"(r[1]), "=r"(r[2]), "=r"(r[3]) : "r"(addr));
}
__device__ __forceinline__ void cp_async16(uint32_t d, const void* s) {
    asm volatile("cp.async.cg.shared.global [%0], [%1], 16;" :: "r"(d), "l"(s));
}
#define CP_COMMIT asm volatile("cp.async.commit_group;" ::: "memory")
#define CP_WAIT1  asm volatile("cp.async.wait_group 1;" ::: "memory")

// ---------------------------------------------------------------------------
// fp32 -> (fp16 hi, fp16 lo) split (weights)
// ---------------------------------------------------------------------------
__global__ void split_h_kernel(const float* __restrict__ x,
                               __half* __restrict__ hi,
                               __half* __restrict__ lo, int n4)
{
    int i = blockIdx.x * blockDim.x + threadIdx.x;
    if (i >= n4) return;
    float4 v = ((const float4*)x)[i];
    __half h0 = __float2half_rn(v.x);
    __half h1 = __float2half_rn(v.y);
    __half h2 = __float2half_rn(v.z);
    __half h3 = __float2half_rn(v.w);
    __half l0 = __float2half_rn(v.x - __half2float(h0));
    __half l1 = __float2half_rn(v.y - __half2float(h1));
    __half l2 = __float2half_rn(v.z - __half2float(h2));
    __half l3 = __float2half_rn(v.w - __half2float(h3));
    __half2* h2p = (__half2*)hi;
    __half2* l2p = (__half2*)lo;
    h2p[i * 2 + 0] = __halves2half2(h0, h1);
    h2p[i * 2 + 1] = __halves2half2(h2, h3);
    l2p[i * 2 + 0] = __halves2half2(l0, l1);
    l2p[i * 2 + 1] = __halves2half2(l2, l3);
}

// fp32 -> fp16 (A-side activations)
__global__ void conv_h_kernel(const float* __restrict__ x,
                              __half* __restrict__ hi, int n4)
{
    int i = blockIdx.x * blockDim.x + threadIdx.x;
    if (i >= n4) return;
    float4 v = ((const float4*)x)[i];
    __half2* h2p = (__half2*)hi;
    h2p[i * 2 + 0] = __floats2half2_rn(v.x, v.y);
    h2p[i * 2 + 1] = __floats2half2_rn(v.z, v.w);
}

// ---------------------------------------------------------------------------
// Pipelined HMMA GEMM (fp16, asymmetric 2-pass): C = alpha*(A @ W^T + bias)
// ---------------------------------------------------------------------------
#define LDT 40
#define TILE_B (128 * LDT * 2)      // 10240
#define STAGE_B (3 * TILE_B)        // 30720 (A, Whi, Wlo)
#define GEMM_SMEM (2 * STAGE_B)     // 61440

__global__ __launch_bounds__(256, 2)
void gemm_mma(const __half* __restrict__ A,
              const __half* __restrict__ Whi, const __half* __restrict__ Wlo,
              const float* __restrict__ bias, float* __restrict__ C,
              __half* __restrict__ Chi, float alpha)
{
    extern __shared__ char smem[];
    const uint32_t sb = smem_u32(smem);

    const int tid = threadIdx.x;
    const int wid = tid >> 5;
    const int lane = tid & 31;
    const int wm = wid >> 2;
    const int wn = wid & 3;
    const int m0 = blockIdx.y * 128;
    const int n0 = blockIdx.x * 128;

    float acc[4][4][4];
#pragma unroll
    for (int i = 0; i < 4; i++)
#pragma unroll
        for (int j = 0; j < 4; j++)
#pragma unroll
            for (int k = 0; k < 4; k++) acc[i][j][k] = 0.f;

    const int lr = lane >> 2;
    const int lc = lane & 3;

    const int r0i = tid >> 2, c0i = tid & 3;
    const int r1i = (tid + 256) >> 2, c1i = tid & 3;

    const int aRow = wm * 64 + (lane & 15);
    const int aColB = ((lane >> 4) << 3) * 2;
    const int bRow = wn * 32 + ((lane >> 4) << 3) + (lane & 7);
    const int bColB = (((lane >> 3) & 1) << 3) * 2;

#define ISSUE(K0, ST) do {                                                     \
    uint32_t sd = sb + (ST) * STAGE_B;                                         \
    size_t g0 = (size_t)(m0 + r0i) * DMODEL + (K0) + c0i * 8;                  \
    size_t g1 = (size_t)(m0 + r1i) * DMODEL + (K0) + c1i * 8;                  \
    size_t h0 = (size_t)(n0 + r0i) * DMODEL + (K0) + c0i * 8;                  \
    size_t h1 = (size_t)(n0 + r1i) * DMODEL + (K0) + c1i * 8;                  \
    uint32_t d0 = r0i * (LDT * 2) + c0i * 16;                                  \
    uint32_t d1 = r1i * (LDT * 2) + c1i * 16;                                  \
    cp_async16(sd + 0 * TILE_B + d0, A + g0);                                  \
    cp_async16(sd + 0 * TILE_B + d1, A + g1);                                  \
    cp_async16(sd + 1 * TILE_B + d0, Whi + h0);                                \
    cp_async16(sd + 1 * TILE_B + d1, Whi + h1);                                \
    cp_async16(sd + 2 * TILE_B + d0, Wlo + h0);                                \
    cp_async16(sd + 2 * TILE_B + d1, Wlo + h1);                                \
} while (0)

    ISSUE(0, 0);
    CP_COMMIT;

    for (int it = 0; it < DMODEL / 32; it++) {
        if (it + 1 < DMODEL / 32) ISSUE((it + 1) * 32, (it + 1) & 1);
        CP_COMMIT;
        CP_WAIT1;
        __syncthreads();

        const uint32_t st = sb + (it & 1) * STAGE_B;
        const uint32_t aB   = st + 0 * TILE_B;
        const uint32_t wHiB = st + 1 * TILE_B;
        const uint32_t wLoB = st + 2 * TILE_B;

#pragma unroll
        for (int ks = 0; ks < 2; ks++) {
            const uint32_t acol = ks * 32 + aColB;
            const uint32_t bcol = ks * 32 + bColB;

            uint32_t bh[2][4], bl[2][4];
#pragma unroll
            for (int nip = 0; nip < 2; nip++) {
                uint32_t boff = (uint32_t)(bRow + nip * 16) * (LDT * 2) + bcol;
                ldmx4(bh[nip], wHiB + boff);
                ldmx4(bl[nip], wLoB + boff);
            }
#pragma unroll
            for (int mi = 0; mi < 4; mi++) {
                uint32_t aoff = (uint32_t)(aRow + mi * 16) * (LDT * 2) + acol;
                uint32_t a[4];
                ldmx4(a, aB + aoff);
#pragma unroll
                for (int nip = 0; nip < 2; nip++) {
                    mma16816(acc[mi][2 * nip + 0], a, &bh[nip][0]);
                    mma16816(acc[mi][2 * nip + 1], a, &bh[nip][2]);
                    mma16816(acc[mi][2 * nip + 0], a, &bl[nip][0]);
                    mma16816(acc[mi][2 * nip + 1], a, &bl[nip][2]);
                }
            }
        }
        __syncthreads();
    }
#undef ISSUE

#pragma unroll
    for (int mi = 0; mi < 4; mi++) {
        int row = m0 + wm * 64 + mi * 16 + lr;
#pragma unroll
        for (int ni = 0; ni < 4; ni++) {
            int col = n0 + wn * 32 + ni * 8 + lc * 2;
            float2 b2 = *(const float2*)&bias[col];
            float v0x = alpha * (acc[mi][ni][0] + b2.x);
            float v0y = alpha * (acc[mi][ni][1] + b2.y);
            float v1x = alpha * (acc[mi][ni][2] + b2.x);
            float v1y = alpha * (acc[mi][ni][3] + b2.y);
            size_t p0 = (size_t)row * DMODEL + col;
            size_t p1 = (size_t)(row + 8) * DMODEL + col;
            if (C) {
                *(float2*)&C[p0] = make_float2(v0x, v0y);
                *(float2*)&C[p1] = make_float2(v1x, v1y);
            }
            if (Chi) {
                *(uint32_t*)&Chi[p0] = pack_h(v0x, v0y);
                *(uint32_t*)&Chi[p1] = pack_h(v1x, v1y);
            }
        }
    }
}

// ---------------------------------------------------------------------------
// Fused HMMA attention (fp16, K/V hi-only, 1 MMA pass): QT=16, 512 threads,
// 2 CTAs/SM, double-buffered K/V stages.
// ---------------------------------------------------------------------------
#define QT 16
#define O_SC   0                          // 16 rows x 4096 B = 65536
#define O_QH   65536                      // 2304
#define O_KB   70144                      // 2 stages x 18432 = 36864
#define KSTG   18432
#define O_PEK  107008                     // 2304
#define O_PEV  109312                     // 2304
#define O_RB   111616                     // 768
#define O_WS   112384                     // 768
#define O_MSK  113152                     // 1024
#define ATT_SMEM 114176

__global__ __launch_bounds__(512, 2)
void attn_mma(const __half* __restrict__ qh,
              const __half* __restrict__ kh, const __half* __restrict__ vh,
              const int* __restrict__ mask, const float* __restrict__ pe_k,
              const float* __restrict__ pe_v, float* __restrict__ attn_out,
              __half* __restrict__ Oh)
{
    extern __shared__ char smem[];
    const uint32_t sb = smem_u32(smem);
    float* sc = (float*)smem;
    __half* QH = (__half*)(smem + O_QH);
    float* pek = (float*)(smem + O_PEK);
    float* pev = (float*)(smem + O_PEV);
    float* rb  = (float*)(smem + O_RB);
    float* ws  = (float*)(smem + O_WS);
    unsigned char* msk = (unsigned char*)(smem + O_MSK);

    const int b  = blockIdx.z;
    const int h  = blockIdx.y;
    const int qb = blockIdx.x * QT;
    const int tid = threadIdx.x;
    const int w = tid >> 5;
    const int lane = tid & 31;
    const int lr = lane >> 2;
    const int lc = lane & 3;

    const int liR0 = tid >> 3, liD0 = tid & 7;          // rows 0..63
    const int liR1 = (tid + 512) >> 3, liD1 = tid & 7;  // rows 64..127

    // K/V tile (hi only): 128 rows x 144 B; each thread copies 2 x 16 B
#define ISSUE_T(SRC, TB, ST) do {                                              \
    uint32_t sd = sb + O_KB + (ST) * KSTG;                                     \
    size_t gA = (size_t)(b * S_LEN + (TB) * 128 + liR0) * DMODEL               \
              + h * DHEAD + liD0 * 8;                                          \
    size_t gB = (size_t)(b * S_LEN + (TB) * 128 + liR1) * DMODEL               \
              + h * DHEAD + liD1 * 8;                                          \
    cp_async16(sd + (uint32_t)(liR0 * 72 + liD0 * 8) * 2, (SRC) + gA);         \
    cp_async16(sd + (uint32_t)(liR1 * 72 + liD1 * 8) * 2, (SRC) + gB);         \
} while (0)

    ISSUE_T(kh, 0, 0);
    CP_COMMIT;

    if (tid < 128) {
        int row = tid >> 3, dg = tid & 7;
        size_t g = (size_t)(b * S_LEN + qb + row) * DMODEL + h * DHEAD + dg * 8;
        *(uint4*)&QH[row * 72 + dg * 8] = *(const uint4*)&qh[g];
    }
    for (int i = tid; i < 576; i += 512) { pek[i] = pe_k[i]; pev[i] = pe_v[i]; }
    for (int i = tid; i < S_LEN; i += 512)
        msk[i] = (unsigned char)(mask[b * S_LEN + i] != 0);
    __syncthreads();

    for (int i = tid; i < QT * 9; i += 512) {
        int qi = i / 9, j = i % 9;
        float s = 0.f;
        const __half* qhr = QH + qi * 72;
        const float* pr = pek + j * 64;
#pragma unroll 16
        for (int d = 0; d < 64; d++)
            s += __half2float(qhr[d]) * pr[d];
        rb[qi * 12 + j] = s;
    }

    // hoist Q fragments
    uint32_t qah[4][4];
#pragma unroll
    for (int ks = 0; ks < 4; ks++) {
        int kc = ks * 16 + lc * 2;
        qah[ks][0] = *(const uint32_t*)&QH[lr * 72 + kc];
        qah[ks][1] = *(const uint32_t*)&QH[(lr + 8) * 72 + kc];
        qah[ks][2] = *(const uint32_t*)&QH[lr * 72 + kc + 8];
        qah[ks][3] = *(const uint32_t*)&QH[(lr + 8) * 72 + kc + 8];
    }

    // ---- scores: 8 tiles of 128 k-cols, double-buffered ----
    const int n0 = w * 8;
    for (int kb = 0; kb < 8; kb++) {
        if (kb + 1 < 8) { ISSUE_T(kh, kb + 1, (kb + 1) & 1); }
        else { ISSUE_T(vh, 0, 0); }
        CP_COMMIT;
        CP_WAIT1;
        __syncthreads();

        const uint32_t kt = sb + O_KB + (kb & 1) * KSTG;
        uint32_t bh2[2][4];
#pragma unroll
        for (int j = 0; j < 2; j++) {
            uint32_t addr = kt + (uint32_t)(n0 + (lane & 7)) * 144
                          + j * 64 + (lane >> 3) * 16;
            ldmx4(bh2[j], addr);
        }

        float c[4] = {0.f, 0.f, 0.f, 0.f};
#pragma unroll
        for (int ks = 0; ks < 4; ks++)
            mma16816(c, qah[ks], &bh2[ks >> 1][(ks & 1) * 2]);

#pragma unroll
        for (int half = 0; half < 2; half++) {
            int qi = lr + half * 8;
            int qg = qb + qi;
            int kg = kb * 128 + n0 + lc * 2;
            float v0 = c[half * 2 + 0];
            float v1 = c[half * 2 + 1];
            int d0 = min(MAXK, max(-MAXK, kg - qg)) + MAXK;
            int d1 = min(MAXK, max(-MAXK, kg + 1 - qg)) + MAXK;
            v0 = msk[kg] ? v0 + rb[qi * 12 + d0] : -INFINITY;
            v1 = msk[kg + 1] ? v1 + rb[qi * 12 + d1] : -INFINITY;
            *(float2*)&sc[qi * S_LEN + kg] = make_float2(v0, v1);
        }
        __syncthreads();
    }

    // ---- softmax: warp w -> row w (V tile 0 landing in background) ----
    {
        int qi = w;
        int qg = qb + qi;
        float* row = sc + qi * S_LEN;

        float m = -INFINITY;
        for (int k2 = lane; k2 < S_LEN; k2 += 32) m = fmaxf(m, row[k2]);
#pragma unroll
        for (int o = 16; o; o >>= 1) m = fmaxf(m, __shfl_xor_sync(0xFFFFFFFFu, m, o));

        float sum = 0.f;
        for (int k2 = lane; k2 < S_LEN; k2 += 32) {
            float e = __expf(row[k2] - m);
            row[k2] = e;
            sum += e;
        }
#pragma unroll
        for (int o = 16; o; o >>= 1) sum += __shfl_xor_sync(0xFFFFFFFFu, sum, o);
        float inv = 1.f / sum;

        float* ao = attn_out ? attn_out + ((size_t)(b * NHEAD + h) * S_LEN + qg) * S_LEN
                             : (float*)0;
        float w0 = 0.f, w8 = 0.f;
        for (int k2 = lane; k2 < S_LEN; k2 += 32) {
            float p = row[k2] * inv;
            row[k2] = p;
            if (ao) ao[k2] = p;
            if (k2 <= qg - MAXK) w0 += p;
            if (k2 >= qg + MAXK) w8 += p;
        }
#pragma unroll
        for (int o = 16; o; o >>= 1) {
            w0 += __shfl_xor_sync(0xFFFFFFFFu, w0, o);
            w8 += __shfl_xor_sync(0xFFFFFFFFu, w8, o);
        }
        __syncwarp();
        if (lane == 0) { ws[qi * 12 + 0] = w0; ws[qi * 12 + 8] = w8; }
        if (lane >= 1 && lane <= 7) {
            int k2 = qg + lane - MAXK;
            ws[qi * 12 + lane] = (k2 >= 0 && k2 < S_LEN) ? row[k2] : 0.f;
        }
        __syncwarp();

        // conflict-free in-place convert to fp16 (swizzled)
        float x[32];
#pragma unroll
        for (int t = 0; t < 16; t++) {
            float2 v = *(const float2*)(row + 2 * (lane + 32 * t));
            x[2 * t] = v.x;
            x[2 * t + 1] = v.y;
        }
        __syncwarp();
        uint32_t swz = (uint32_t)((qi & 7) << 4);
        char* rowb = smem + qi * 4096;
#pragma unroll
        for (int t = 0; t < 16; t++) {
            int j = lane + 32 * t;
            *(uint32_t*)(rowb + (((uint32_t)(4 * j)) ^ swz)) =
                pack_h(x[2 * t], x[2 * t + 1]);
        }
    }
    __syncthreads();

    // ---- PV: two vb-parity groups, warp (g, wn) covers d-cols wn*8..+7 ----
    const int g = w >> 3;
    const int wn = w & 7;
    float o[4] = {0.f, 0.f, 0.f, 0.f};

    for (int vbi = 0; vbi < 8; vbi++) {
        if (vbi + 1 < 8) { ISSUE_T(vh, vbi + 1, (vbi + 1) & 1); }
        CP_COMMIT;
        CP_WAIT1;
        __syncthreads();

        const int vb = vbi * 2 + g;
        const uint32_t vtile = sb + O_KB + (vbi & 1) * KSTG + g * 9216;

        uint32_t bh2[2][4];
#pragma unroll
        for (int j = 0; j < 2; j++) {
            uint32_t addr = vtile + (uint32_t)(j * 32 + lane) * 144 + wn * 16;
            ldmx4t(bh2[j], addr);
        }

#pragma unroll
        for (int ks = 0; ks < 4; ks++) {
            uint32_t* bh = &bh2[ks >> 1][(ks & 1) * 2];
            uint32_t kby = (uint32_t)(vb * 128 + ks * 32 + (lane >> 4) * 16);
            int prow = (lane & 7) + ((lane >> 3) & 1) * 8;
            uint32_t cby = kby ^ ((uint32_t)(prow & 7) << 4);
            uint32_t ah[4];
            ldmx4(ah, sb + (uint32_t)prow * 4096 + cby);
            mma16816(o, ah, bh);
        }
        __syncthreads();
    }

    // ---- cross-group reduce + epilogue (group 0 writes) ----
    float* red = (float*)(smem + O_QH);
    if (g == 1) {
        int widx = wn * 32 + lane;
#pragma unroll
        for (int j = 0; j < 4; j++) red[widx * 4 + j] = o[j];
    }
    __syncthreads();
    if (g == 0) {
        int widx = wn * 32 + lane;
#pragma unroll
        for (int j = 0; j < 4; j++) o[j] += red[widx * 4 + j];

#pragma unroll
        for (int half = 0; half < 2; half++) {
            int qi = lr + half * 8;
            int d0 = wn * 8 + lc * 2;
            float a0 = o[half * 2 + 0];
            float a1 = o[half * 2 + 1];
#pragma unroll
            for (int j = 0; j < 9; j++) {
                float wv = ws[qi * 12 + j];
                a0 += wv * pev[j * 64 + d0];
                a1 += wv * pev[j * 64 + d0 + 1];
            }
            size_t base = (size_t)(b * S_LEN + qb + qi) * DMODEL + h * DHEAD + d0;
            *(uint32_t*)&Oh[base] = pack_h(a0, a1);
        }
    }
}

// ---------------------------------------------------------------------------
extern "C" void kernel_launch(void* const* d_in, const int* in_sizes, int n_in,
                              void* d_out, int out_size)
{
    const float* query = (const float*)d_in[0];
    const float* key   = (const float*)d_in[1];
    const float* value = (const float*)d_in[2];
    const int*   mask  = (const int*)d_in[3];
    const float* Wq = (const float*)d_in[4];
    const float* bq = (const float*)d_in[5];
    const float* Wk = (const float*)d_in[6];
    const float* bk = (const float*)d_in[7];
    const float* Wv = (const float*)d_in[8];
    const float* bv = (const float*)d_in[9];
    const float* Wo = (const float*)d_in[10];
    const float* bo = (const float*)d_in[11];
    const float* pe_k = (const float*)d_in[12];
    const float* pe_v = (const float*)d_in[13];

    __half *act, *whi, *wlo, *qh, *kh, *vh, *oh;
    cudaGetSymbolAddress((void**)&act, g_act);
    cudaGetSymbolAddress((void**)&whi, g_w_hi);
    cudaGetSymbolAddress((void**)&wlo, g_w_lo);
    cudaGetSymbolAddress((void**)&qh, g_qh);
    cudaGetSymbolAddress((void**)&kh, g_kh);
    cudaGetSymbolAddress((void**)&vh, g_vh);
    cudaGetSymbolAddress((void**)&oh, g_oh);

    const long long OUT_ELEMS = (long long)BATCH * S_LEN * DMODEL;
    float* out_ptr  = (float*)d_out;
    float* attn_ptr = ((long long)out_size > OUT_ELEMS) ? (float*)d_out + OUT_ELEMS
                                                        : (float*)0;

    cudaFuncSetAttribute(attn_mma, cudaFuncAttributeMaxDynamicSharedMemorySize,
                         ATT_SMEM);
    cudaFuncSetAttribute(gemm_mma, cudaFuncAttributeMaxDynamicSharedMemorySize,
                         GEMM_SMEM);

    const int ACT4 = MROWS * DMODEL / 4;
    const int W4   = DMODEL * DMODEL / 4;
    dim3 gg(DMODEL / 128, MROWS / 128);

    // Q projection (fold 1/SCALE = 0.125)
    conv_h_kernel<<<ACT4 / 256, 256>>>(query, act, ACT4);
    split_h_kernel<<<W4 / 256, 256>>>(Wq, whi, wlo, W4);
    gemm_mma<<<gg, 256, GEMM_SMEM>>>(act, whi, wlo, bq, (float*)0, qh, 0.125f);
    // K projection (hi only)
    conv_h_kernel<<<ACT4 / 256, 256>>>(key, act, ACT4);
    split_h_kernel<<<W4 / 256, 256>>>(Wk, whi, wlo, W4);
    gemm_mma<<<gg, 256, GEMM_SMEM>>>(act, whi, wlo, bk, (float*)0, kh, 1.0f);
    // V projection (hi only)
    conv_h_kernel<<<ACT4 / 256, 256>>>(value, act, ACT4);
    split_h_kernel<<<W4 / 256, 256>>>(Wv, whi, wlo, W4);
    gemm_mma<<<gg, 256, GEMM_SMEM>>>(act, whi, wlo, bv, (float*)0, vh, 1.0f);

    // fused attention
    dim3 ga(S_LEN / QT, NHEAD, BATCH);   // (64, 16, 8)
    attn_mma<<<ga, 512, ATT_SMEM>>>(qh, kh, vh, mask, pe_k, pe_v,
                                    attn_ptr, oh);

    // output projection (fp32 out)
    split_h_kernel<<<W4 / 256, 256>>>(Wo, whi, wlo, W4);
    gemm_mma<<<gg, 256, GEMM_SMEM>>>(oh, whi, wlo, bo, out_ptr,
                                     (__half*)0, 1.0f);
}

// round 12
// speedup vs baseline: 5.7914x; 1.1802x over previous
#include <cuda_runtime.h>
#include <cuda_fp16.h>
#include <math.h>
#include <cstdint>

#define BATCH 8
#define S_LEN 1024
#define DMODEL 1024
#define NHEAD 16
#define DHEAD 64
#define MAXK 4
#define MROWS (BATCH * S_LEN)   // 8192

// Scratch (allocation-free rule -> device globals)
__device__ __half g_act[(size_t)MROWS * DMODEL];
__device__ __half g_w[(size_t)DMODEL * DMODEL];
__device__ __half g_qh[(size_t)MROWS * DMODEL];
__device__ __half g_kh[(size_t)MROWS * DMODEL];
__device__ __half g_vh[(size_t)MROWS * DMODEL];
__device__ __half g_oh[(size_t)MROWS * DMODEL];

// ---------------------------------------------------------------------------
__device__ __forceinline__ void mma16816(float* c, const uint32_t* a, const uint32_t* b) {
    asm volatile(
        "mma.sync.aligned.m16n8k16.row.col.f32.f16.f16.f32 "
        "{%0,%1,%2,%3}, {%4,%5,%6,%7}, {%8,%9}, {%0,%1,%2,%3};"
        : "+f"(c[0]), "+f"(c[1]), "+f"(c[2]), "+f"(c[3])
        : "r"(a[0]), "r"(a[1]), "r"(a[2]), "r"(a[3]), "r"(b[0]), "r"(b[1]));
}
__device__ __forceinline__ uint32_t pack_h(float x, float y) {
    __half2 t = __floats2half2_rn(x, y);
    return *(uint32_t*)&t;
}
__device__ __forceinline__ uint32_t smem_u32(const void* p) {
    uint32_t a;
    asm("{ .reg .u64 t; cvta.to.shared.u64 t, %1; cvt.u32.u64 %0, t; }"
        : "=r"(a) : "l"(p));
    return a;
}
__device__ __forceinline__ void ldmx4(uint32_t* r, uint32_t addr) {
    asm volatile("ldmatrix.sync.aligned.m8n8.x4.shared.b16 {%0,%1,%2,%3}, [%4];"
        : "=r"(r[0]), "=r"(r[1]), "=r"(r[2]), "=r"(r[3]) : "r"(addr));
}
__device__ __forceinline__ void ldmx4t(uint32_t* r, uint32_t addr) {
    asm volatile("ldmatrix.sync.aligned.m8n8.x4.trans.shared.b16 {%0,%1,%2,%3}, [%4];"
        : "=r"(r[0]), "=r"(r[1]), "=r"(r[2]), "=r"(r[3]) : "r"(addr));
}
__device__ __forceinline__ void cp_async16(uint32_t d, const void* s) {
    asm volatile("cp.async.cg.shared.global [%0], [%1], 16;" :: "r"(d), "l"(s));
}
#define CP_COMMIT asm volatile("cp.async.commit_group;" ::: "memory")
#define CP_WAIT1  asm volatile("cp.async.wait_group 1;" ::: "memory")

// ---------------------------------------------------------------------------
// fp32 -> fp16 convert
// ---------------------------------------------------------------------------
__global__ void conv_h_kernel(const float* __restrict__ x,
                              __half* __restrict__ hi, int n4)
{
    int i = blockIdx.x * blockDim.x + threadIdx.x;
    if (i >= n4) return;
    float4 v = ((const float4*)x)[i];
    __half2* h2p = (__half2*)hi;
    h2p[i * 2 + 0] = __floats2half2_rn(v.x, v.y);
    h2p[i * 2 + 1] = __floats2half2_rn(v.z, v.w);
}

// ---------------------------------------------------------------------------
// Pipelined HMMA GEMM (fp16 single pass): C = alpha*(A @ W^T + bias)
// Tile 128x128, BK=32, 8 warps (2M x 4N), cp.async 2-stage, ldmatrix frags.
// ---------------------------------------------------------------------------
#define LDT 40
#define TILE_B (128 * LDT * 2)      // 10240
#define STAGE_B (2 * TILE_B)        // 20480 (A, W)
#define GEMM_SMEM (2 * STAGE_B)     // 40960

__global__ __launch_bounds__(256, 2)
void gemm_mma(const __half* __restrict__ A, const __half* __restrict__ W,
              const float* __restrict__ bias, float* __restrict__ C,
              __half* __restrict__ Chi, float alpha)
{
    extern __shared__ char smem[];
    const uint32_t sb = smem_u32(smem);

    const int tid = threadIdx.x;
    const int wid = tid >> 5;
    const int lane = tid & 31;
    const int wm = wid >> 2;
    const int wn = wid & 3;
    const int m0 = blockIdx.y * 128;
    const int n0 = blockIdx.x * 128;

    float acc[4][4][4];
#pragma unroll
    for (int i = 0; i < 4; i++)
#pragma unroll
        for (int j = 0; j < 4; j++)
#pragma unroll
            for (int k = 0; k < 4; k++) acc[i][j][k] = 0.f;

    const int lr = lane >> 2;
    const int lc = lane & 3;

    const int r0i = tid >> 2, c0i = tid & 3;
    const int r1i = (tid + 256) >> 2, c1i = tid & 3;

    const int aRow = wm * 64 + (lane & 15);
    const int aColB = ((lane >> 4) << 3) * 2;
    const int bRow = wn * 32 + ((lane >> 4) << 3) + (lane & 7);
    const int bColB = (((lane >> 3) & 1) << 3) * 2;

#define ISSUE(K0, ST) do {                                                     \
    uint32_t sd = sb + (ST) * STAGE_B;                                         \
    size_t g0 = (size_t)(m0 + r0i) * DMODEL + (K0) + c0i * 8;                  \
    size_t g1 = (size_t)(m0 + r1i) * DMODEL + (K0) + c1i * 8;                  \
    size_t h0 = (size_t)(n0 + r0i) * DMODEL + (K0) + c0i * 8;                  \
    size_t h1 = (size_t)(n0 + r1i) * DMODEL + (K0) + c1i * 8;                  \
    uint32_t d0 = r0i * (LDT * 2) + c0i * 16;                                  \
    uint32_t d1 = r1i * (LDT * 2) + c1i * 16;                                  \
    cp_async16(sd + 0 * TILE_B + d0, A + g0);                                  \
    cp_async16(sd + 0 * TILE_B + d1, A + g1);                                  \
    cp_async16(sd + 1 * TILE_B + d0, W + h0);                                  \
    cp_async16(sd + 1 * TILE_B + d1, W + h1);                                  \
} while (0)

    ISSUE(0, 0);
    CP_COMMIT;

    for (int it = 0; it < DMODEL / 32; it++) {
        if (it + 1 < DMODEL / 32) ISSUE((it + 1) * 32, (it + 1) & 1);
        CP_COMMIT;
        CP_WAIT1;
        __syncthreads();

        const uint32_t st = sb + (it & 1) * STAGE_B;
        const uint32_t aB = st + 0 * TILE_B;
        const uint32_t wB = st + 1 * TILE_B;

#pragma unroll
        for (int ks = 0; ks < 2; ks++) {
            const uint32_t acol = ks * 32 + aColB;
            const uint32_t bcol = ks * 32 + bColB;

            uint32_t bh[2][4];
#pragma unroll
            for (int nip = 0; nip < 2; nip++) {
                uint32_t boff = (uint32_t)(bRow + nip * 16) * (LDT * 2) + bcol;
                ldmx4(bh[nip], wB + boff);
            }
#pragma unroll
            for (int mi = 0; mi < 4; mi++) {
                uint32_t aoff = (uint32_t)(aRow + mi * 16) * (LDT * 2) + acol;
                uint32_t a[4];
                ldmx4(a, aB + aoff);
#pragma unroll
                for (int nip = 0; nip < 2; nip++) {
                    mma16816(acc[mi][2 * nip + 0], a, &bh[nip][0]);
                    mma16816(acc[mi][2 * nip + 1], a, &bh[nip][2]);
                }
            }
        }
        __syncthreads();
    }
#undef ISSUE

#pragma unroll
    for (int mi = 0; mi < 4; mi++) {
        int row = m0 + wm * 64 + mi * 16 + lr;
#pragma unroll
        for (int ni = 0; ni < 4; ni++) {
            int col = n0 + wn * 32 + ni * 8 + lc * 2;
            float2 b2 = *(const float2*)&bias[col];
            float v0x = alpha * (acc[mi][ni][0] + b2.x);
            float v0y = alpha * (acc[mi][ni][1] + b2.y);
            float v1x = alpha * (acc[mi][ni][2] + b2.x);
            float v1y = alpha * (acc[mi][ni][3] + b2.y);
            size_t p0 = (size_t)row * DMODEL + col;
            size_t p1 = (size_t)(row + 8) * DMODEL + col;
            if (C) {
                *(float2*)&C[p0] = make_float2(v0x, v0y);
                *(float2*)&C[p1] = make_float2(v1x, v1y);
            }
            if (Chi) {
                *(uint32_t*)&Chi[p0] = pack_h(v0x, v0y);
                *(uint32_t*)&Chi[p1] = pack_h(v1x, v1y);
            }
        }
    }
}

// ---------------------------------------------------------------------------
// Fused HMMA attention (fp16, 1 MMA pass): QT=16, 512 threads, 2 CTAs/SM,
// double-buffered K/V stages. (Unchanged from R11, passing.)
// ---------------------------------------------------------------------------
#define QT 16
#define O_SC   0                          // 16 rows x 4096 B = 65536
#define O_QH   65536                      // 2304
#define O_KB   70144                      // 2 stages x 18432 = 36864
#define KSTG   18432
#define O_PEK  107008                     // 2304
#define O_PEV  109312                     // 2304
#define O_RB   111616                     // 768
#define O_WS   112384                     // 768
#define O_MSK  113152                     // 1024
#define ATT_SMEM 114176

__global__ __launch_bounds__(512, 2)
void attn_mma(const __half* __restrict__ qh,
              const __half* __restrict__ kh, const __half* __restrict__ vh,
              const int* __restrict__ mask, const float* __restrict__ pe_k,
              const float* __restrict__ pe_v, float* __restrict__ attn_out,
              __half* __restrict__ Oh)
{
    extern __shared__ char smem[];
    const uint32_t sb = smem_u32(smem);
    float* sc = (float*)smem;
    __half* QH = (__half*)(smem + O_QH);
    float* pek = (float*)(smem + O_PEK);
    float* pev = (float*)(smem + O_PEV);
    float* rb  = (float*)(smem + O_RB);
    float* ws  = (float*)(smem + O_WS);
    unsigned char* msk = (unsigned char*)(smem + O_MSK);

    const int b  = blockIdx.z;
    const int h  = blockIdx.y;
    const int qb = blockIdx.x * QT;
    const int tid = threadIdx.x;
    const int w = tid >> 5;
    const int lane = tid & 31;
    const int lr = lane >> 2;
    const int lc = lane & 3;

    const int liR0 = tid >> 3, liD0 = tid & 7;
    const int liR1 = (tid + 512) >> 3, liD1 = tid & 7;

#define ISSUE_T(SRC, TB, ST) do {                                              \
    uint32_t sd = sb + O_KB + (ST) * KSTG;                                     \
    size_t gA = (size_t)(b * S_LEN + (TB) * 128 + liR0) * DMODEL               \
              + h * DHEAD + liD0 * 8;                                          \
    size_t gB = (size_t)(b * S_LEN + (TB) * 128 + liR1) * DMODEL               \
              + h * DHEAD + liD1 * 8;                                          \
    cp_async16(sd + (uint32_t)(liR0 * 72 + liD0 * 8) * 2, (SRC) + gA);         \
    cp_async16(sd + (uint32_t)(liR1 * 72 + liD1 * 8) * 2, (SRC) + gB);         \
} while (0)

    ISSUE_T(kh, 0, 0);
    CP_COMMIT;

    if (tid < 128) {
        int row = tid >> 3, dg = tid & 7;
        size_t g = (size_t)(b * S_LEN + qb + row) * DMODEL + h * DHEAD + dg * 8;
        *(uint4*)&QH[row * 72 + dg * 8] = *(const uint4*)&qh[g];
    }
    for (int i = tid; i < 576; i += 512) { pek[i] = pe_k[i]; pev[i] = pe_v[i]; }
    for (int i = tid; i < S_LEN; i += 512)
        msk[i] = (unsigned char)(mask[b * S_LEN + i] != 0);
    __syncthreads();

    for (int i = tid; i < QT * 9; i += 512) {
        int qi = i / 9, j = i % 9;
        float s = 0.f;
        const __half* qhr = QH + qi * 72;
        const float* pr = pek + j * 64;
#pragma unroll 16
        for (int d = 0; d < 64; d++)
            s += __half2float(qhr[d]) * pr[d];
        rb[qi * 12 + j] = s;
    }

    uint32_t qah[4][4];
#pragma unroll
    for (int ks = 0; ks < 4; ks++) {
        int kc = ks * 16 + lc * 2;
        qah[ks][0] = *(const uint32_t*)&QH[lr * 72 + kc];
        qah[ks][1] = *(const uint32_t*)&QH[(lr + 8) * 72 + kc];
        qah[ks][2] = *(const uint32_t*)&QH[lr * 72 + kc + 8];
        qah[ks][3] = *(const uint32_t*)&QH[(lr + 8) * 72 + kc + 8];
    }

    // ---- scores: 8 tiles of 128 k-cols, double-buffered ----
    const int n0 = w * 8;
    for (int kb = 0; kb < 8; kb++) {
        if (kb + 1 < 8) { ISSUE_T(kh, kb + 1, (kb + 1) & 1); }
        else { ISSUE_T(vh, 0, 0); }
        CP_COMMIT;
        CP_WAIT1;
        __syncthreads();

        const uint32_t kt = sb + O_KB + (kb & 1) * KSTG;
        uint32_t bh2[2][4];
#pragma unroll
        for (int j = 0; j < 2; j++) {
            uint32_t addr = kt + (uint32_t)(n0 + (lane & 7)) * 144
                          + j * 64 + (lane >> 3) * 16;
            ldmx4(bh2[j], addr);
        }

        float c[4] = {0.f, 0.f, 0.f, 0.f};
#pragma unroll
        for (int ks = 0; ks < 4; ks++)
            mma16816(c, qah[ks], &bh2[ks >> 1][(ks & 1) * 2]);

#pragma unroll
        for (int half = 0; half < 2; half++) {
            int qi = lr + half * 8;
            int qg = qb + qi;
            int kg = kb * 128 + n0 + lc * 2;
            float v0 = c[half * 2 + 0];
            float v1 = c[half * 2 + 1];
            int d0 = min(MAXK, max(-MAXK, kg - qg)) + MAXK;
            int d1 = min(MAXK, max(-MAXK, kg + 1 - qg)) + MAXK;
            v0 = msk[kg] ? v0 + rb[qi * 12 + d0] : -INFINITY;
            v1 = msk[kg + 1] ? v1 + rb[qi * 12 + d1] : -INFINITY;
            *(float2*)&sc[qi * S_LEN + kg] = make_float2(v0, v1);
        }
        __syncthreads();
    }

    // ---- softmax: warp w -> row w ----
    {
        int qi = w;
        int qg = qb + qi;
        float* row = sc + qi * S_LEN;

        float m = -INFINITY;
        for (int k2 = lane; k2 < S_LEN; k2 += 32) m = fmaxf(m, row[k2]);
#pragma unroll
        for (int o = 16; o; o >>= 1) m = fmaxf(m, __shfl_xor_sync(0xFFFFFFFFu, m, o));

        float sum = 0.f;
        for (int k2 = lane; k2 < S_LEN; k2 += 32) {
            float e = __expf(row[k2] - m);
            row[k2] = e;
            sum += e;
        }
#pragma unroll
        for (int o = 16; o; o >>= 1) sum += __shfl_xor_sync(0xFFFFFFFFu, sum, o);
        float inv = 1.f / sum;

        float* ao = attn_out ? attn_out + ((size_t)(b * NHEAD + h) * S_LEN + qg) * S_LEN
                             : (float*)0;
        float w0 = 0.f, w8 = 0.f;
        for (int k2 = lane; k2 < S_LEN; k2 += 32) {
            float p = row[k2] * inv;
            row[k2] = p;
            if (ao) ao[k2] = p;
            if (k2 <= qg - MAXK) w0 += p;
            if (k2 >= qg + MAXK) w8 += p;
        }
#pragma unroll
        for (int o = 16; o; o >>= 1) {
            w0 += __shfl_xor_sync(0xFFFFFFFFu, w0, o);
            w8 += __shfl_xor_sync(0xFFFFFFFFu, w8, o);
        }
        __syncwarp();
        if (lane == 0) { ws[qi * 12 + 0] = w0; ws[qi * 12 + 8] = w8; }
        if (lane >= 1 && lane <= 7) {
            int k2 = qg + lane - MAXK;
            ws[qi * 12 + lane] = (k2 >= 0 && k2 < S_LEN) ? row[k2] : 0.f;
        }
        __syncwarp();

        float x[32];
#pragma unroll
        for (int t = 0; t < 16; t++) {
            float2 v = *(const float2*)(row + 2 * (lane + 32 * t));
            x[2 * t] = v.x;
            x[2 * t + 1] = v.y;
        }
        __syncwarp();
        uint32_t swz = (uint32_t)((qi & 7) << 4);
        char* rowb = smem + qi * 4096;
#pragma unroll
        for (int t = 0; t < 16; t++) {
            int j = lane + 32 * t;
            *(uint32_t*)(rowb + (((uint32_t)(4 * j)) ^ swz)) =
                pack_h(x[2 * t], x[2 * t + 1]);
        }
    }
    __syncthreads();

    // ---- PV: two vb-parity groups, warp (g, wn) covers d-cols wn*8..+7 ----
    const int g = w >> 3;
    const int wn = w & 7;
    float o[4] = {0.f, 0.f, 0.f, 0.f};

    for (int vbi = 0; vbi < 8; vbi++) {
        if (vbi + 1 < 8) { ISSUE_T(vh, vbi + 1, (vbi + 1) & 1); }
        CP_COMMIT;
        CP_WAIT1;
        __syncthreads();

        const int vb = vbi * 2 + g;
        const uint32_t vtile = sb + O_KB + (vbi & 1) * KSTG + g * 9216;

        uint32_t bh2[2][4];
#pragma unroll
        for (int j = 0; j < 2; j++) {
            uint32_t addr = vtile + (uint32_t)(j * 32 + lane) * 144 + wn * 16;
            ldmx4t(bh2[j], addr);
        }

#pragma unroll
        for (int ks = 0; ks < 4; ks++) {
            uint32_t* bh = &bh2[ks >> 1][(ks & 1) * 2];
            uint32_t kby = (uint32_t)(vb * 128 + ks * 32 + (lane >> 4) * 16);
            int prow = (lane & 7) + ((lane >> 3) & 1) * 8;
            uint32_t cby = kby ^ ((uint32_t)(prow & 7) << 4);
            uint32_t ah[4];
            ldmx4(ah, sb + (uint32_t)prow * 4096 + cby);
            mma16816(o, ah, bh);
        }
        __syncthreads();
    }

    // ---- cross-group reduce + epilogue (group 0 writes) ----
    float* red = (float*)(smem + O_QH);
    if (g == 1) {
        int widx = wn * 32 + lane;
#pragma unroll
        for (int j = 0; j < 4; j++) red[widx * 4 + j] = o[j];
    }
    __syncthreads();
    if (g == 0) {
        int widx = wn * 32 + lane;
#pragma unroll
        for (int j = 0; j < 4; j++) o[j] += red[widx * 4 + j];

#pragma unroll
        for (int half = 0; half < 2; half++) {
            int qi = lr + half * 8;
            int d0 = wn * 8 + lc * 2;
            float a0 = o[half * 2 + 0];
            float a1 = o[half * 2 + 1];
#pragma unroll
            for (int j = 0; j < 9; j++) {
                float wv = ws[qi * 12 + j];
                a0 += wv * pev[j * 64 + d0];
                a1 += wv * pev[j * 64 + d0 + 1];
            }
            size_t base = (size_t)(b * S_LEN + qb + qi) * DMODEL + h * DHEAD + d0;
            *(uint32_t*)&Oh[base] = pack_h(a0, a1);
        }
    }
}

// ---------------------------------------------------------------------------
extern "C" void kernel_launch(void* const* d_in, const int* in_sizes, int n_in,
                              void* d_out, int out_size)
{
    const float* query = (const float*)d_in[0];
    const float* key   = (const float*)d_in[1];
    const float* value = (const float*)d_in[2];
    const int*   mask  = (const int*)d_in[3];
    const float* Wq = (const float*)d_in[4];
    const float* bq = (const float*)d_in[5];
    const float* Wk = (const float*)d_in[6];
    const float* bk = (const float*)d_in[7];
    const float* Wv = (const float*)d_in[8];
    const float* bv = (const float*)d_in[9];
    const float* Wo = (const float*)d_in[10];
    const float* bo = (const float*)d_in[11];
    const float* pe_k = (const float*)d_in[12];
    const float* pe_v = (const float*)d_in[13];

    __half *act, *wbuf, *qh, *kh, *vh, *oh;
    cudaGetSymbolAddress((void**)&act, g_act);
    cudaGetSymbolAddress((void**)&wbuf, g_w);
    cudaGetSymbolAddress((void**)&qh, g_qh);
    cudaGetSymbolAddress((void**)&kh, g_kh);
    cudaGetSymbolAddress((void**)&vh, g_vh);
    cudaGetSymbolAddress((void**)&oh, g_oh);

    const long long OUT_ELEMS = (long long)BATCH * S_LEN * DMODEL;
    float* out_ptr  = (float*)d_out;
    float* attn_ptr = ((long long)out_size > OUT_ELEMS) ? (float*)d_out + OUT_ELEMS
                                                        : (float*)0;

    cudaFuncSetAttribute(attn_mma, cudaFuncAttributeMaxDynamicSharedMemorySize,
                         ATT_SMEM);
    cudaFuncSetAttribute(gemm_mma, cudaFuncAttributeMaxDynamicSharedMemorySize,
                         GEMM_SMEM);

    const int ACT4 = MROWS * DMODEL / 4;
    const int W4   = DMODEL * DMODEL / 4;
    dim3 gg(DMODEL / 128, MROWS / 128);

    // Q projection (fold 1/SCALE = 0.125)
    conv_h_kernel<<<ACT4 / 256, 256>>>(query, act, ACT4);
    conv_h_kernel<<<W4 / 256, 256>>>(Wq, wbuf, W4);
    gemm_mma<<<gg, 256, GEMM_SMEM>>>(act, wbuf, bq, (float*)0, qh, 0.125f);
    // K projection
    conv_h_kernel<<<ACT4 / 256, 256>>>(key, act, ACT4);
    conv_h_kernel<<<W4 / 256, 256>>>(Wk, wbuf, W4);
    gemm_mma<<<gg, 256, GEMM_SMEM>>>(act, wbuf, bk, (float*)0, kh, 1.0f);
    // V projection
    conv_h_kernel<<<ACT4 / 256, 256>>>(value, act, ACT4);
    conv_h_kernel<<<W4 / 256, 256>>>(Wv, wbuf, W4);
    gemm_mma<<<gg, 256, GEMM_SMEM>>>(act, wbuf, bv, (float*)0, vh, 1.0f);

    // fused attention
    dim3 ga(S_LEN / QT, NHEAD, BATCH);   // (64, 16, 8)
    attn_mma<<<ga, 512, ATT_SMEM>>>(qh, kh, vh, mask, pe_k, pe_v,
                                    attn_ptr, oh);

    // output projection (fp32 out)
    conv_h_kernel<<<W4 / 256, 256>>>(Wo, wbuf, W4);
    gemm_mma<<<gg, 256, GEMM_SMEM>>>(oh, wbuf, bo, out_ptr,
                                     (__half*)0, 1.0f);
}

// round 13
// speedup vs baseline: 6.0682x; 1.0478x over previous
#include <cuda_runtime.h>
#include <cuda_fp16.h>
#include <math.h>
#include <cstdint>

#define BATCH 8
#define S_LEN 1024
#define DMODEL 1024
#define NHEAD 16
#define DHEAD 64
#define MAXK 4
#define MROWS (BATCH * S_LEN)   // 8192

// Scratch (allocation-free rule -> device globals)
__device__ __half g_act3[(size_t)3 * MROWS * DMODEL];
__device__ __half g_w4[(size_t)4 * DMODEL * DMODEL];
__device__ __half g_qh[(size_t)MROWS * DMODEL];
__device__ __half g_kh[(size_t)MROWS * DMODEL];
__device__ __half g_vh[(size_t)MROWS * DMODEL];
__device__ __half g_oh[(size_t)MROWS * DMODEL];

// ---------------------------------------------------------------------------
__device__ __forceinline__ void mma16816(float* c, const uint32_t* a, const uint32_t* b) {
    asm volatile(
        "mma.sync.aligned.m16n8k16.row.col.f32.f16.f16.f32 "
        "{%0,%1,%2,%3}, {%4,%5,%6,%7}, {%8,%9}, {%0,%1,%2,%3};"
        : "+f"(c[0]), "+f"(c[1]), "+f"(c[2]), "+f"(c[3])
        : "r"(a[0]), "r"(a[1]), "r"(a[2]), "r"(a[3]), "r"(b[0]), "r"(b[1]));
}
__device__ __forceinline__ uint32_t pack_h(float x, float y) {
    __half2 t = __floats2half2_rn(x, y);
    return *(uint32_t*)&t;
}
__device__ __forceinline__ uint32_t smem_u32(const void* p) {
    uint32_t a;
    asm("{ .reg .u64 t; cvta.to.shared.u64 t, %1; cvt.u32.u64 %0, t; }"
        : "=r"(a) : "l"(p));
    return a;
}
__device__ __forceinline__ void ldmx4(uint32_t* r, uint32_t addr) {
    asm volatile("ldmatrix.sync.aligned.m8n8.x4.shared.b16 {%0,%1,%2,%3}, [%4];"
        : "=r"(r[0]), "=r"(r[1]), "=r"(r[2]), "=r"(r[3]) : "r"(addr));
}
__device__ __forceinline__ void ldmx4t(uint32_t* r, uint32_t addr) {
    asm volatile("ldmatrix.sync.aligned.m8n8.x4.trans.shared.b16 {%0,%1,%2,%3}, [%4];"
        : "=r"(r[0]), "=r"(r[1]), "=r"(r[2]), "=r"(r[3]) : "r"(addr));
}
__device__ __forceinline__ void cp_async16(uint32_t d, const void* s) {
    asm volatile("cp.async.cg.shared.global [%0], [%1], 16;" :: "r"(d), "l"(s));
}
#define CP_COMMIT asm volatile("cp.async.commit_group;" ::: "memory")
#define CP_WAIT1  asm volatile("cp.async.wait_group 1;" ::: "memory")
#define CP_WAIT2  asm volatile("cp.async.wait_group 2;" ::: "memory")

// ---------------------------------------------------------------------------
// Batched fp32 -> fp16 converts (2 float4 per thread)
// ---------------------------------------------------------------------------
__global__ void conv_acts_kernel(const float* __restrict__ q, const float* __restrict__ k,
                                 const float* __restrict__ v, __half* __restrict__ out,
                                 int n4)
{
    const float* src = (blockIdx.y == 0) ? q : (blockIdx.y == 1) ? k : v;
    __half2* dst = (__half2*)(out + (size_t)blockIdx.y * MROWS * DMODEL);
    int i = blockIdx.x * 512 + threadIdx.x;
#pragma unroll
    for (int t = 0; t < 2; t++, i += 256) {
        if (i < n4) {
            float4 x = ((const float4*)src)[i];
            dst[i * 2 + 0] = __floats2half2_rn(x.x, x.y);
            dst[i * 2 + 1] = __floats2half2_rn(x.z, x.w);
        }
    }
}
__global__ void conv_ws_kernel(const float* __restrict__ w0, const float* __restrict__ w1,
                               const float* __restrict__ w2, const float* __restrict__ w3,
                               __half* __restrict__ out, int n4)
{
    const float* src = (blockIdx.y == 0) ? w0 : (blockIdx.y == 1) ? w1
                     : (blockIdx.y == 2) ? w2 : w3;
    __half2* dst = (__half2*)(out + (size_t)blockIdx.y * DMODEL * DMODEL);
    int i = blockIdx.x * 512 + threadIdx.x;
#pragma unroll
    for (int t = 0; t < 2; t++, i += 256) {
        if (i < n4) {
            float4 x = ((const float4*)src)[i];
            dst[i * 2 + 0] = __floats2half2_rn(x.x, x.y);
            dst[i * 2 + 1] = __floats2half2_rn(x.z, x.w);
        }
    }
}

// ---------------------------------------------------------------------------
// Pipelined HMMA GEMM (fp16 single pass, unchanged from R12)
// ---------------------------------------------------------------------------
#define LDT 40
#define TILE_B (128 * LDT * 2)
#define STAGE_B (2 * TILE_B)
#define GEMM_SMEM (2 * STAGE_B)

__global__ __launch_bounds__(256, 2)
void gemm_mma(const __half* __restrict__ A, const __half* __restrict__ W,
              const float* __restrict__ bias, float* __restrict__ C,
              __half* __restrict__ Chi, float alpha)
{
    extern __shared__ char smem[];
    const uint32_t sb = smem_u32(smem);

    const int tid = threadIdx.x;
    const int wid = tid >> 5;
    const int lane = tid & 31;
    const int wm = wid >> 2;
    const int wn = wid & 3;
    const int m0 = blockIdx.y * 128;
    const int n0 = blockIdx.x * 128;

    float acc[4][4][4];
#pragma unroll
    for (int i = 0; i < 4; i++)
#pragma unroll
        for (int j = 0; j < 4; j++)
#pragma unroll
            for (int k = 0; k < 4; k++) acc[i][j][k] = 0.f;

    const int lr = lane >> 2;
    const int lc = lane & 3;

    const int r0i = tid >> 2, c0i = tid & 3;
    const int r1i = (tid + 256) >> 2, c1i = tid & 3;

    const int aRow = wm * 64 + (lane & 15);
    const int aColB = ((lane >> 4) << 3) * 2;
    const int bRow = wn * 32 + ((lane >> 4) << 3) + (lane & 7);
    const int bColB = (((lane >> 3) & 1) << 3) * 2;

#define ISSUE(K0, ST) do {                                                     \
    uint32_t sd = sb + (ST) * STAGE_B;                                         \
    size_t g0 = (size_t)(m0 + r0i) * DMODEL + (K0) + c0i * 8;                  \
    size_t g1 = (size_t)(m0 + r1i) * DMODEL + (K0) + c1i * 8;                  \
    size_t h0 = (size_t)(n0 + r0i) * DMODEL + (K0) + c0i * 8;                  \
    size_t h1 = (size_t)(n0 + r1i) * DMODEL + (K0) + c1i * 8;                  \
    uint32_t d0 = r0i * (LDT * 2) + c0i * 16;                                  \
    uint32_t d1 = r1i * (LDT * 2) + c1i * 16;                                  \
    cp_async16(sd + 0 * TILE_B + d0, A + g0);                                  \
    cp_async16(sd + 0 * TILE_B + d1, A + g1);                                  \
    cp_async16(sd + 1 * TILE_B + d0, W + h0);                                  \
    cp_async16(sd + 1 * TILE_B + d1, W + h1);                                  \
} while (0)

    ISSUE(0, 0);
    CP_COMMIT;

    for (int it = 0; it < DMODEL / 32; it++) {
        if (it + 1 < DMODEL / 32) ISSUE((it + 1) * 32, (it + 1) & 1);
        CP_COMMIT;
        CP_WAIT1;
        __syncthreads();

        const uint32_t st = sb + (it & 1) * STAGE_B;
        const uint32_t aB = st + 0 * TILE_B;
        const uint32_t wB = st + 1 * TILE_B;

#pragma unroll
        for (int ks = 0; ks < 2; ks++) {
            const uint32_t acol = ks * 32 + aColB;
            const uint32_t bcol = ks * 32 + bColB;

            uint32_t bh[2][4];
#pragma unroll
            for (int nip = 0; nip < 2; nip++) {
                uint32_t boff = (uint32_t)(bRow + nip * 16) * (LDT * 2) + bcol;
                ldmx4(bh[nip], wB + boff);
            }
#pragma unroll
            for (int mi = 0; mi < 4; mi++) {
                uint32_t aoff = (uint32_t)(aRow + mi * 16) * (LDT * 2) + acol;
                uint32_t a[4];
                ldmx4(a, aB + aoff);
#pragma unroll
                for (int nip = 0; nip < 2; nip++) {
                    mma16816(acc[mi][2 * nip + 0], a, &bh[nip][0]);
                    mma16816(acc[mi][2 * nip + 1], a, &bh[nip][2]);
                }
            }
        }
        __syncthreads();
    }
#undef ISSUE

#pragma unroll
    for (int mi = 0; mi < 4; mi++) {
        int row = m0 + wm * 64 + mi * 16 + lr;
#pragma unroll
        for (int ni = 0; ni < 4; ni++) {
            int col = n0 + wn * 32 + ni * 8 + lc * 2;
            float2 b2 = *(const float2*)&bias[col];
            float v0x = alpha * (acc[mi][ni][0] + b2.x);
            float v0y = alpha * (acc[mi][ni][1] + b2.y);
            float v1x = alpha * (acc[mi][ni][2] + b2.x);
            float v1y = alpha * (acc[mi][ni][3] + b2.y);
            size_t p0 = (size_t)row * DMODEL + col;
            size_t p1 = (size_t)(row + 8) * DMODEL + col;
            if (C) {
                *(float2*)&C[p0] = make_float2(v0x, v0y);
                *(float2*)&C[p1] = make_float2(v1x, v1y);
            }
            if (Chi) {
                *(uint32_t*)&Chi[p0] = pack_h(v0x, v0y);
                *(uint32_t*)&Chi[p1] = pack_h(v1x, v1y);
            }
        }
    }
}

// ---------------------------------------------------------------------------
// Fused HMMA attention v6: QT=32, 512 threads, 1 CTA/SM, 4-stage cp.async
// ring (3-deep prefetch, one __syncthreads per tile), PV with no reduction.
// ---------------------------------------------------------------------------
#define QT 32
#define O_SC   0                          // 32 rows x 4096 B = 131072
#define O_QH   131072                     // 32*72*2 = 4608
#define O_KB   135680                     // 4 stages x 18432 = 73728
#define KSTG   18432
#define O_PEK  209408                     // 2304
#define O_PEV  211712                     // 2304
#define O_RB   214016                     // 1536
#define O_WS   215552                     // 1536
#define O_MSK  217088                     // 1024
#define ATT_SMEM 218112

__global__ __launch_bounds__(512, 1)
void attn_mma(const __half* __restrict__ qh,
              const __half* __restrict__ kh, const __half* __restrict__ vh,
              const int* __restrict__ mask, const float* __restrict__ pe_k,
              const float* __restrict__ pe_v, float* __restrict__ attn_out,
              __half* __restrict__ Oh)
{
    extern __shared__ char smem[];
    const uint32_t sb = smem_u32(smem);
    float* sc = (float*)smem;
    __half* QH = (__half*)(smem + O_QH);
    float* pek = (float*)(smem + O_PEK);
    float* pev = (float*)(smem + O_PEV);
    float* rb  = (float*)(smem + O_RB);
    float* ws  = (float*)(smem + O_WS);
    unsigned char* msk = (unsigned char*)(smem + O_MSK);

    const int b  = blockIdx.z;
    const int h  = blockIdx.y;
    const int qb = blockIdx.x * QT;
    const int tid = threadIdx.x;
    const int w = tid >> 5;
    const int lane = tid & 31;
    const int lr = lane >> 2;
    const int lc = lane & 3;

    const int liR0 = tid >> 3, liD0 = tid & 7;          // rows 0..63
    const int liR1 = (tid + 512) >> 3, liD1 = tid & 7;  // rows 64..127

    // K/V tile: 128 rows x 144 B (64 d + pad); each thread copies 2 x 16 B
#define ISSUE_T(SRC, TB, ST) do {                                              \
    uint32_t sd = sb + O_KB + (ST) * KSTG;                                     \
    size_t gA = (size_t)(b * S_LEN + (TB) * 128 + liR0) * DMODEL               \
              + h * DHEAD + liD0 * 8;                                          \
    size_t gB = (size_t)(b * S_LEN + (TB) * 128 + liR1) * DMODEL               \
              + h * DHEAD + liD1 * 8;                                          \
    cp_async16(sd + (uint32_t)(liR0 * 72 + liD0 * 8) * 2, (SRC) + gA);         \
    cp_async16(sd + (uint32_t)(liR1 * 72 + liD1 * 8) * 2, (SRC) + gB);         \
} while (0)

    // prologue: K0, K1, K2 into stages 0,1,2 (one group each)
    ISSUE_T(kh, 0, 0); CP_COMMIT;
    ISSUE_T(kh, 1, 1); CP_COMMIT;
    ISSUE_T(kh, 2, 2); CP_COMMIT;

    // load Q tile (32 rows x 8 chunks), pe tables, mask
    if (tid < 256) {
        int row = tid >> 3, dg = tid & 7;
        size_t g = (size_t)(b * S_LEN + qb + row) * DMODEL + h * DHEAD + dg * 8;
        *(uint4*)&QH[row * 72 + dg * 8] = *(const uint4*)&qh[g];
    }
    for (int i = tid; i < 576; i += 512) { pek[i] = pe_k[i]; pev[i] = pe_v[i]; }
    for (int i = tid; i < S_LEN; i += 512)
        msk[i] = (unsigned char)(mask[b * S_LEN + i] != 0);
    __syncthreads();

    for (int i = tid; i < QT * 9; i += 512) {
        int qi = i / 9, j = i % 9;
        float s = 0.f;
        const __half* qhr = QH + qi * 72;
        const float* pr = pek + j * 64;
#pragma unroll 16
        for (int d = 0; d < 64; d++)
            s += __half2float(qhr[d]) * pr[d];
        rb[qi * 12 + j] = s;
    }

    // hoist Q fragments (2 m-tiles)
    uint32_t qah[4][2][4];
#pragma unroll
    for (int ks = 0; ks < 4; ks++)
#pragma unroll
        for (int mt = 0; mt < 2; mt++) {
            int r = mt * 16 + lr;
            int kc = ks * 16 + lc * 2;
            qah[ks][mt][0] = *(const uint32_t*)&QH[r * 72 + kc];
            qah[ks][mt][1] = *(const uint32_t*)&QH[(r + 8) * 72 + kc];
            qah[ks][mt][2] = *(const uint32_t*)&QH[r * 72 + kc + 8];
            qah[ks][mt][3] = *(const uint32_t*)&QH[(r + 8) * 72 + kc + 8];
        }

    // ---- scores: 8 tiles of 128 k-cols; ring order: wait2,sync,ldmx,issue ----
    const int n0 = w * 8;
    for (int kb = 0; kb < 8; kb++) {
        CP_WAIT2;
        __syncthreads();

        const uint32_t kt = sb + O_KB + (kb & 3) * KSTG;
        uint32_t bh2[2][4];
#pragma unroll
        for (int j = 0; j < 2; j++) {
            uint32_t addr = kt + (uint32_t)(n0 + (lane & 7)) * 144
                          + j * 64 + (lane >> 3) * 16;
            ldmx4(bh2[j], addr);
        }

        {   // issue tile kb+3 (K, or V for tail) into stage (kb+3)&3
            int t = kb + 3;
            if (t < 8) { ISSUE_T(kh, t, t & 3); }
            else       { ISSUE_T(vh, t - 8, t & 3); }
            CP_COMMIT;
        }

        float c[2][4] = {{0.f,0.f,0.f,0.f},{0.f,0.f,0.f,0.f}};
#pragma unroll
        for (int ks = 0; ks < 4; ks++) {
            uint32_t* bh = &bh2[ks >> 1][(ks & 1) * 2];
#pragma unroll
            for (int mt = 0; mt < 2; mt++)
                mma16816(c[mt], qah[ks][mt], bh);
        }
#pragma unroll
        for (int mt = 0; mt < 2; mt++) {
#pragma unroll
            for (int half = 0; half < 2; half++) {
                int qi = mt * 16 + lr + half * 8;
                int qg = qb + qi;
                int kg = kb * 128 + n0 + lc * 2;
                float v0 = c[mt][half * 2 + 0];
                float v1 = c[mt][half * 2 + 1];
                int d0 = min(MAXK, max(-MAXK, kg - qg)) + MAXK;
                int d1 = min(MAXK, max(-MAXK, kg + 1 - qg)) + MAXK;
                v0 = msk[kg] ? v0 + rb[qi * 12 + d0] : -INFINITY;
                v1 = msk[kg + 1] ? v1 + rb[qi * 12 + d1] : -INFINITY;
                *(float2*)&sc[qi * S_LEN + kg] = make_float2(v0, v1);
            }
        }
    }
    __syncthreads();

    // ---- softmax: warp w -> rows 2w, 2w+1 (V0..V2 landing in background) ----
#pragma unroll
    for (int r = 0; r < 2; r++) {
        int qi = w * 2 + r;
        int qg = qb + qi;
        float* row = sc + qi * S_LEN;

        float m = -INFINITY;
        for (int k2 = lane; k2 < S_LEN; k2 += 32) m = fmaxf(m, row[k2]);
#pragma unroll
        for (int o = 16; o; o >>= 1) m = fmaxf(m, __shfl_xor_sync(0xFFFFFFFFu, m, o));

        float sum = 0.f;
        for (int k2 = lane; k2 < S_LEN; k2 += 32) {
            float e = __expf(row[k2] - m);
            row[k2] = e;
            sum += e;
        }
#pragma unroll
        for (int o = 16; o; o >>= 1) sum += __shfl_xor_sync(0xFFFFFFFFu, sum, o);
        float inv = 1.f / sum;

        float* ao = attn_out ? attn_out + ((size_t)(b * NHEAD + h) * S_LEN + qg) * S_LEN
                             : (float*)0;
        float w0 = 0.f, w8 = 0.f;
        for (int k2 = lane; k2 < S_LEN; k2 += 32) {
            float p = row[k2] * inv;
            row[k2] = p;
            if (ao) ao[k2] = p;
            if (k2 <= qg - MAXK) w0 += p;
            if (k2 >= qg + MAXK) w8 += p;
        }
#pragma unroll
        for (int o = 16; o; o >>= 1) {
            w0 += __shfl_xor_sync(0xFFFFFFFFu, w0, o);
            w8 += __shfl_xor_sync(0xFFFFFFFFu, w8, o);
        }
        __syncwarp();
        if (lane == 0) { ws[qi * 12 + 0] = w0; ws[qi * 12 + 8] = w8; }
        if (lane >= 1 && lane <= 7) {
            int k2 = qg + lane - MAXK;
            ws[qi * 12 + lane] = (k2 >= 0 && k2 < S_LEN) ? row[k2] : 0.f;
        }
        __syncwarp();

        // conflict-free in-place convert to fp16 (swizzled)
        float x[32];
#pragma unroll
        for (int t = 0; t < 16; t++) {
            float2 v = *(const float2*)(row + 2 * (lane + 32 * t));
            x[2 * t] = v.x;
            x[2 * t + 1] = v.y;
        }
        __syncwarp();
        uint32_t swz = (uint32_t)((qi & 7) << 4);
        char* rowb = smem + qi * 4096;
#pragma unroll
        for (int t = 0; t < 16; t++) {
            int j = lane + 32 * t;
            *(uint32_t*)(rowb + (((uint32_t)(4 * j)) ^ swz)) =
                pack_h(x[2 * t], x[2 * t + 1]);
        }
    }

    // ---- PV: warp (mw = w>>3, wn = w&7) owns m-tile mw, d-cols wn*8..+7 ----
    const int mw = w >> 3;
    const int wn = w & 7;
    float o[4] = {0.f, 0.f, 0.f, 0.f};
    const int prow = mw * 16 + (lane & 7) + ((lane >> 3) & 1) * 8;
    const uint32_t pswz = (uint32_t)((prow & 7) << 4);

    for (int vb = 0; vb < 8; vb++) {
        CP_WAIT2;
        __syncthreads();

        const uint32_t vtile = sb + O_KB + (vb & 3) * KSTG;
        uint32_t vbh[4][4];
#pragma unroll
        for (int j = 0; j < 4; j++) {
            uint32_t addr = vtile + (uint32_t)(j * 32 + lane) * 144 + wn * 16;
            ldmx4t(vbh[j], addr);
        }

        if (vb + 3 < 8) { ISSUE_T(vh, vb + 3, (vb + 3) & 3); }
        CP_COMMIT;   // empty group on tail keeps the count uniform

#pragma unroll
        for (int ks = 0; ks < 8; ks++) {
            uint32_t cby = (uint32_t)(vb * 256 + ks * 32 + (lane >> 4) * 16) ^ pswz;
            uint32_t a[4];
            ldmx4(a, sb + (uint32_t)prow * 4096 + cby);
            mma16816(o, a, &vbh[ks >> 1][(ks & 1) * 2]);
        }
    }

    // ---- epilogue: rel_v + write O (each warp owns its output) ----
#pragma unroll
    for (int half = 0; half < 2; half++) {
        int qi = mw * 16 + lr + half * 8;
        int d0 = wn * 8 + lc * 2;
        float a0 = o[half * 2 + 0];
        float a1 = o[half * 2 + 1];
#pragma unroll
        for (int j = 0; j < 9; j++) {
            float wv = ws[qi * 12 + j];
            a0 += wv * pev[j * 64 + d0];
            a1 += wv * pev[j * 64 + d0 + 1];
        }
        size_t base = (size_t)(b * S_LEN + qb + qi) * DMODEL + h * DHEAD + d0;
        *(uint32_t*)&Oh[base] = pack_h(a0, a1);
    }
}

// ---------------------------------------------------------------------------
extern "C" void kernel_launch(void* const* d_in, const int* in_sizes, int n_in,
                              void* d_out, int out_size)
{
    const float* query = (const float*)d_in[0];
    const float* key   = (const float*)d_in[1];
    const float* value = (const float*)d_in[2];
    const int*   mask  = (const int*)d_in[3];
    const float* Wq = (const float*)d_in[4];
    const float* bq = (const float*)d_in[5];
    const float* Wk = (const float*)d_in[6];
    const float* bk = (const float*)d_in[7];
    const float* Wv = (const float*)d_in[8];
    const float* bv = (const float*)d_in[9];
    const float* Wo = (const float*)d_in[10];
    const float* bo = (const float*)d_in[11];
    const float* pe_k = (const float*)d_in[12];
    const float* pe_v = (const float*)d_in[13];

    __half *act3, *w4, *qh, *kh, *vh, *oh;
    cudaGetSymbolAddress((void**)&act3, g_act3);
    cudaGetSymbolAddress((void**)&w4, g_w4);
    cudaGetSymbolAddress((void**)&qh, g_qh);
    cudaGetSymbolAddress((void**)&kh, g_kh);
    cudaGetSymbolAddress((void**)&vh, g_vh);
    cudaGetSymbolAddress((void**)&oh, g_oh);

    const long long OUT_ELEMS = (long long)BATCH * S_LEN * DMODEL;
    float* out_ptr  = (float*)d_out;
    float* attn_ptr = ((long long)out_size > OUT_ELEMS) ? (float*)d_out + OUT_ELEMS
                                                        : (float*)0;

    cudaFuncSetAttribute(attn_mma, cudaFuncAttributeMaxDynamicSharedMemorySize,
                         ATT_SMEM);
    cudaFuncSetAttribute(gemm_mma, cudaFuncAttributeMaxDynamicSharedMemorySize,
                         GEMM_SMEM);

    const int ACT4 = MROWS * DMODEL / 4;   // 2M float4 per tensor
    const int W4E  = DMODEL * DMODEL / 4;  // 256K float4 per weight
    const size_t WSTRIDE = (size_t)DMODEL * DMODEL;
    dim3 gg(DMODEL / 128, MROWS / 128);

    // batched converts: 3 activations, 4 weights
    conv_acts_kernel<<<dim3(ACT4 / 512, 3), 256>>>(query, key, value, act3, ACT4);
    conv_ws_kernel<<<dim3(W4E / 512, 4), 256>>>(Wq, Wk, Wv, Wo, w4, W4E);

    // projections (fold 1/SCALE into Q)
    gemm_mma<<<gg, 256, GEMM_SMEM>>>(act3 + 0 * (size_t)MROWS * DMODEL,
                                     w4 + 0 * WSTRIDE, bq, (float*)0, qh, 0.125f);
    gemm_mma<<<gg, 256, GEMM_SMEM>>>(act3 + 1 * (size_t)MROWS * DMODEL,
                                     w4 + 1 * WSTRIDE, bk, (float*)0, kh, 1.0f);
    gemm_mma<<<gg, 256, GEMM_SMEM>>>(act3 + 2 * (size_t)MROWS * DMODEL,
                                     w4 + 2 * WSTRIDE, bv, (float*)0, vh, 1.0f);

    // fused attention
    dim3 ga(S_LEN / QT, NHEAD, BATCH);   // (32, 16, 8)
    attn_mma<<<ga, 512, ATT_SMEM>>>(qh, kh, vh, mask, pe_k, pe_v, attn_ptr, oh);

    // output projection (fp32 out)
    gemm_mma<<<gg, 256, GEMM_SMEM>>>(oh, w4 + 3 * WSTRIDE, bo, out_ptr,
                                     (__half*)0, 1.0f);
}